// round 8
// baseline (speedup 1.0000x reference)
#include <cuda_runtime.h>
#include <cstdint>
#include <math.h>

#define T_SEQ 2048
#define DMODEL 2048
#define NH 32
#define NKV 8
#define HD 64

// ---------------- Scratch (device globals; allocation-free) ----------------
__device__ uint32_t g_qt [(size_t)2 * NH * T_SEQ * HD];   // tf32 Q*0.125 (b,h,t,d)
__device__ uint32_t g_ctx[(size_t)2 * T_SEQ * NH * HD];   // tf32 ctx (b,t,h,d)
__device__ uint32_t g_xt [(size_t)4096 * 2048];           // tf32 x
__device__ uint32_t g_wq [(size_t)2048 * 2048];
__device__ uint32_t g_wk [(size_t)512 * 2048];
__device__ uint32_t g_wv [(size_t)512 * 2048];
__device__ uint32_t g_wo [(size_t)2048 * 2048];
__device__ uint32_t g_kc [(size_t)2 * NKV * T_SEQ * HD];  // tf32 K (b,kv,t,d)
__device__ uint32_t g_vt [(size_t)2 * NKV * HD * T_SEQ];  // tf32 V^T (b,kv,d,t)

__device__ __forceinline__ uint32_t f2tf32(float f) {
    uint32_t u;
    asm("cvt.rna.tf32.f32 %0, %1;" : "=r"(u) : "f"(f));
    return u;
}

__device__ __forceinline__ void mma_tf32(float* c, uint32_t a0, uint32_t a1,
                                         uint32_t a2, uint32_t a3,
                                         uint32_t b0, uint32_t b1) {
    asm volatile(
        "mma.sync.aligned.m16n8k8.row.col.f32.tf32.tf32.f32 "
        "{%0,%1,%2,%3}, {%4,%5,%6,%7}, {%8,%9}, {%0,%1,%2,%3};"
        : "+f"(c[0]), "+f"(c[1]), "+f"(c[2]), "+f"(c[3])
        : "r"(a0), "r"(a1), "r"(a2), "r"(a3), "r"(b0), "r"(b1));
}

__device__ __forceinline__ uint32_t smem_u32(const void* p) {
    uint32_t a;
    asm("{ .reg .u64 t; cvta.to.shared.u64 t, %1; cvt.u32.u64 %0, t; }"
        : "=r"(a) : "l"(p));
    return a;
}
#define CP_ASYNC16(dst, src) \
    asm volatile("cp.async.ca.shared.global [%0], [%1], 16;" :: "r"(dst), "l"(src))
#define CP_COMMIT() asm volatile("cp.async.commit_group;" ::: "memory")
#define CP_WAIT0()  asm volatile("cp.async.wait_group 0;" ::: "memory")

// ============================================================================
// Prep: all fp32 -> tf32 conversions in ONE kernel (5 regions).
// ============================================================================
__global__ void cvt_all(const float* __restrict__ x,
                        const float* __restrict__ wq,
                        const float* __restrict__ wk,
                        const float* __restrict__ wv,
                        const float* __restrict__ wo,
                        uint32_t* __restrict__ xt,
                        uint32_t* __restrict__ wqt,
                        uint32_t* __restrict__ wkt,
                        uint32_t* __restrict__ wvt,
                        uint32_t* __restrict__ wot)
{
    int i = blockIdx.x * blockDim.x + threadIdx.x;
    const float* in;
    uint32_t* out;
    if (i < 2097152)        { in = x;  out = xt; }
    else if (i < 3145728)   { in = wq; out = wqt; i -= 2097152; }
    else if (i < 3407872)   { in = wk; out = wkt; i -= 3145728; }
    else if (i < 3670016)   { in = wv; out = wvt; i -= 3407872; }
    else                    { in = wo; out = wot; i -= 3670016; }
    float4 v = ((const float4*)in)[i];
    uint4 o;
    o.x = f2tf32(v.x); o.y = f2tf32(v.y); o.z = f2tf32(v.z); o.w = f2tf32(v.w);
    ((uint4*)out)[i] = o;
}

// ============================================================================
// Prep: V (b,kv,t,d) fp32 -> V^T (b,kv,d,t) tf32.
// ============================================================================
__global__ void vtrans(const float* __restrict__ vin, uint32_t* __restrict__ vt)
{
    __shared__ uint32_t ts[64 * 65];
    const int tid = threadIdx.x;
    const int jt = blockIdx.x;
    const int bkv = blockIdx.y;

    const float* in = vin + ((size_t)bkv * T_SEQ + jt * 64) * HD;
#pragma unroll
    for (int p = 0; p < 4; p++) {
        const int lin = p * 256 + tid;
        const int t = lin >> 4;
        const int dq = (lin & 15) * 4;
        float4 v = *(const float4*)&in[t * HD + dq];
        ts[(dq + 0) * 65 + t] = f2tf32(v.x);
        ts[(dq + 1) * 65 + t] = f2tf32(v.y);
        ts[(dq + 2) * 65 + t] = f2tf32(v.z);
        ts[(dq + 3) * 65 + t] = f2tf32(v.w);
    }
    __syncthreads();
    uint32_t* out = vt + (size_t)bkv * HD * T_SEQ + jt * 64;
#pragma unroll
    for (int p = 0; p < 4; p++) {
        const int lin = p * 256 + tid;
        const int d = lin >> 4;
        const int cq = (lin & 15) * 4;
        uint4 w;
        w.x = ts[d * 65 + cq + 0];
        w.y = ts[d * 65 + cq + 1];
        w.z = ts[d * 65 + cq + 2];
        w.w = ts[d * 65 + cq + 3];
        *(uint4*)&out[(size_t)d * T_SEQ + cq] = w;
    }
}

// ============================================================================
// cp.async double-buffered tf32 GEMM. 128x128 CTA tile, BK=32.
// 128 threads = 4 warps in 2x2; warp tile 64x64 (4x8 m16n8 frags).
// KIND 0: fused QKV. bx<16: Q+RoPE -> g_qt (tf32, *0.125); 16..19: K+RoPE ->
//         kout fp32 + g_kc tf32; 20..23: V -> vout fp32.
// KIND 1: O projection: A=g_ctx(tf32), C=out fp32.
// ============================================================================
#define SPAD 40
#define TILE_W (128 * SPAD)

template <int KIND>
__global__ __launch_bounds__(128, 2) void db_gemm(
    const uint32_t* __restrict__ xA,
    const float* __restrict__ bq, const float* __restrict__ bk,
    const float* __restrict__ bv,
    float* __restrict__ kout, float* __restrict__ vout,
    float* __restrict__ outC,
    const float* __restrict__ cosT, const float* __restrict__ sinT)
{
    extern __shared__ __align__(16) uint32_t sm[];
    const uint32_t sm_addr = smem_u32(sm);

    const int tid = threadIdx.x;
    const int wid = tid >> 5;
    const int lane = tid & 31;
    const int gr = lane >> 2;
    const int tig = lane & 3;
    const int wm = wid >> 1;   // 0..1
    const int wn = wid & 1;    // 0..1

    constexpr int K = DMODEL;
    const int m0 = blockIdx.y * 128;

    int mode, n0;
    const uint32_t* A;
    const uint32_t* W;
    const float* bias;
    if (KIND == 1) {
        mode = 0; n0 = blockIdx.x * 128; A = g_ctx; W = g_wo; bias = bq;
    } else {
        const int bx = blockIdx.x;
        A = xA;
        if (bx < 16)      { mode = 1; n0 = bx * 128;        W = g_wq; bias = bq; }
        else if (bx < 20) { mode = 2; n0 = (bx - 16) * 128; W = g_wk; bias = bk; }
        else              { mode = 3; n0 = (bx - 20) * 128; W = g_wv; bias = bv; }
    }

    // loaders: 8 chunks per tile per thread (128 rows x 8 chunk-cols)
    const int row8 = tid >> 3;   // 0..15
    const int cc = tid & 7;      // chunk col
    const uint32_t dstb = (uint32_t)((row8 * SPAD + cc * 4) * 4);
    const uint32_t* Ag = A + (size_t)(m0 + row8) * K + cc * 4;
    const uint32_t* Wg = W + (size_t)(n0 + row8) * K + cc * 4;

    float acc[4][8][4];
#pragma unroll
    for (int mi = 0; mi < 4; mi++)
#pragma unroll
        for (int ni = 0; ni < 8; ni++)
#pragma unroll
            for (int r = 0; r < 4; r++) acc[mi][ni][r] = 0.f;

    const int NST = K / 32;
#pragma unroll
    for (int i = 0; i < 8; i++) {
        CP_ASYNC16(sm_addr + i * 16 * SPAD * 4 + dstb, Ag + (size_t)i * 16 * K);
        CP_ASYNC16(sm_addr + TILE_W * 4 + i * 16 * SPAD * 4 + dstb, Wg + (size_t)i * 16 * K);
    }
    CP_COMMIT();

    for (int s = 0; s < NST; s++) {
        CP_WAIT0();
        __syncthreads();
        if (s + 1 < NST) {
            const uint32_t boff = (uint32_t)((s + 1) & 1) * (2 * TILE_W * 4);
            const int ko = (s + 1) * 32;
#pragma unroll
            for (int i = 0; i < 8; i++) {
                CP_ASYNC16(sm_addr + boff + i * 16 * SPAD * 4 + dstb,
                           Ag + (size_t)i * 16 * K + ko);
                CP_ASYNC16(sm_addr + boff + TILE_W * 4 + i * 16 * SPAD * 4 + dstb,
                           Wg + (size_t)i * 16 * K + ko);
            }
            CP_COMMIT();
        }

        const uint32_t* Abase = sm + (s & 1) * 2 * TILE_W + (wm * 64) * SPAD;
        const uint32_t* Bbase = sm + (s & 1) * 2 * TILE_W + TILE_W + (wn * 64) * SPAD;
#pragma unroll
        for (int kk = 0; kk < 4; kk++) {
            const int kc = kk * 8 + 2 * tig;
            uint32_t bf[8][2];
#pragma unroll
            for (int ni = 0; ni < 8; ni++) {
                uint64_t bv = *(const uint64_t*)&Bbase[(ni * 8 + gr) * SPAD + kc];
                bf[ni][0] = (uint32_t)bv;
                bf[ni][1] = (uint32_t)(bv >> 32);
            }
#pragma unroll
            for (int mi = 0; mi < 4; mi++) {
                uint64_t a02 = *(const uint64_t*)&Abase[(mi * 16 + gr) * SPAD + kc];
                uint64_t a13 = *(const uint64_t*)&Abase[(mi * 16 + gr + 8) * SPAD + kc];
                uint32_t a0 = (uint32_t)a02, a2 = (uint32_t)(a02 >> 32);
                uint32_t a1 = (uint32_t)a13, a3 = (uint32_t)(a13 >> 32);
#pragma unroll
                for (int ni = 0; ni < 8; ni++)
                    mma_tf32(acc[mi][ni], a0, a1, a2, a3, bf[ni][0], bf[ni][1]);
            }
        }
    }

    // ---------------- Register epilogue ----------------
#pragma unroll
    for (int mi = 0; mi < 4; mi++) {
#pragma unroll
        for (int half = 0; half < 2; half++) {
            const int m = m0 + wm * 64 + mi * 16 + gr + half * 8;
            const int bb = m >> 11;
            const int t = m & (T_SEQ - 1);
#pragma unroll
            for (int ni = 0; ni < 8; ni++) {
                const int n = n0 + wn * 64 + ni * 8 + tig * 2;
                float v0 = acc[mi][ni][half * 2 + 0] + bias[n];
                float v1 = acc[mi][ni][half * 2 + 1] + bias[n + 1];
                if (mode == 1 || mode == 2) {
                    const int hh = (n & 63) >> 1;
                    const float c = cosT[t * (HD / 2) + hh];
                    const float ss = sinT[t * (HD / 2) + hh];
                    const float e = v0 * c - v1 * ss;
                    const float o = v0 * ss + v1 * c;
                    v0 = e;
                    v1 = o;
                }
                if (mode == 0) {
                    *(float2*)&outC[(size_t)m * DMODEL + n] = make_float2(v0, v1);
                } else if (mode == 1) {
                    // tf32 Q, pre-scaled by 1/sqrt(64) (exact power-of-2 scale)
                    uint2 qv;
                    qv.x = f2tf32(v0 * 0.125f);
                    qv.y = f2tf32(v1 * 0.125f);
                    *(uint2*)&g_qt[(((size_t)(bb * NH + (n >> 6))) * T_SEQ + t) * HD + (n & 63)] = qv;
                } else {
                    const size_t idx =
                        (((size_t)(bb * NKV + (n >> 6))) * T_SEQ + t) * HD + (n & 63);
                    if (mode == 2) {
                        *(float2*)&kout[idx] = make_float2(v0, v1);
                        uint2 kq;
                        kq.x = f2tf32(v0);
                        kq.y = f2tf32(v1);
                        *(uint2*)&g_kc[idx] = kq;
                    } else {
                        *(float2*)&vout[idx] = make_float2(v0, v1);
                    }
                }
            }
        }
    }
}

// ============================================================================
// Flash attention, tf32 mma.sync. 128 threads = 4 warps; warp tile 32x64
// (2 m16 tiles per warp). Q tile (128x64, pre-scaled tf32) staged in smem
// once per CTA; K/V cp.async double-buffered. Heavy-first scheduling.
// smem words: Q 128*72 | K 2x64*72 | V 2x64*72 = 27648 (110592 B).
// ============================================================================
#define ATP 72
#define QW (128 * ATP)        // 9216
#define KVW (64 * ATP)        // 4608

__global__ __launch_bounds__(128, 2) void attn_mma()
{
    extern __shared__ __align__(16) uint32_t sm[];
    const uint32_t sm_addr = smem_u32(sm);

    const int tid = threadIdx.x;
    const int wid = tid >> 5;  // 0..3, owns q rows [32w, 32w+32)
    const int lane = tid & 31;
    const int gr = lane >> 2;
    const int tig = lane & 3;

    const int qt = (gridDim.x - 1) - blockIdx.x;  // heavy-first
    const int bh = blockIdx.y;
    const int b = bh >> 5;
    const int h = bh & 31;
    const int bkv = (b * NKV) + (h >> 2);

    const uint32_t* Qg = g_qt + (((size_t)(b * NH + h)) * T_SEQ + qt * 128) * HD;
    const uint32_t* Kbase = g_kc + (size_t)bkv * T_SEQ * HD;
    const uint32_t* Vbase = g_vt + (size_t)bkv * HD * T_SEQ;

    float ctx[2][8][4];
#pragma unroll
    for (int mi = 0; mi < 2; mi++)
#pragma unroll
        for (int ni = 0; ni < 8; ni++)
#pragma unroll
            for (int r = 0; r < 4; r++) ctx[mi][ni][r] = 0.f;
    float mrun[2][2] = {{-INFINITY, -INFINITY}, {-INFINITY, -INFINITY}};
    float lrun[2][2] = {{0.f, 0.f}, {0.f, 0.f}};

    // loaders
    const int kvrow = tid >> 1;          // 0..63
    const int kvhalf = tid & 1;          // which 32-word half of the row
    const int njt = 2 * qt + 2;

    // prologue: Q tile (16 chunks/thread) + K/V tile 0 (8+8 chunks/thread)
#pragma unroll
    for (int c = 0; c < 16; c++) {
        CP_ASYNC16(sm_addr + (tid * ATP + c * 4) * 4, Qg + (size_t)tid * HD + c * 4);
    }
#pragma unroll
    for (int c = 0; c < 8; c++) {
        const int colw = (kvhalf * 8 + c) * 4;
        CP_ASYNC16(sm_addr + (QW + kvrow * ATP + colw) * 4,
                   Kbase + (size_t)kvrow * HD + colw);
        CP_ASYNC16(sm_addr + (QW + 2 * KVW + kvrow * ATP + colw) * 4,
                   Vbase + (size_t)kvrow * T_SEQ + colw);
    }
    CP_COMMIT();

    const int rowb = qt * 128 + wid * 32 + gr;  // row of (mi=0, half=0)

    for (int jt = 0; jt < njt; jt++) {
        CP_WAIT0();
        __syncthreads();
        if (jt + 1 < njt) {
            const uint32_t boff = (uint32_t)((jt + 1) & 1) * KVW;
            const int kt = (jt + 1) * 64;
#pragma unroll
            for (int c = 0; c < 8; c++) {
                const int colw = (kvhalf * 8 + c) * 4;
                CP_ASYNC16(sm_addr + (QW + boff + kvrow * ATP + colw) * 4,
                           Kbase + (size_t)(kt + kvrow) * HD + colw);
                CP_ASYNC16(sm_addr + (QW + 2 * KVW + boff + kvrow * ATP + colw) * 4,
                           Vbase + (size_t)kvrow * T_SEQ + kt + colw);
            }
            CP_COMMIT();
        }

        // fully-masked warp x tile -> skip compute
        if (jt * 64 > qt * 128 + wid * 32 + 31) continue;

        const uint32_t* Ks = sm + QW + (jt & 1) * KVW;
        const uint32_t* Vs = sm + QW + 2 * KVW + (jt & 1) * KVW;
        const uint32_t* Qs = sm + (wid * 32) * ATP;

        // ---- S = Q K^T (warp tile 32 x 64) ----
        float s[2][8][4];
#pragma unroll
        for (int mi = 0; mi < 2; mi++)
#pragma unroll
            for (int ni = 0; ni < 8; ni++)
#pragma unroll
                for (int r = 0; r < 4; r++) s[mi][ni][r] = 0.f;
#pragma unroll
        for (int ks = 0; ks < 8; ks++) {
            const int kc = ks * 8 + 2 * tig;
            uint32_t qa[2][4];
#pragma unroll
            for (int mi = 0; mi < 2; mi++) {
                uint64_t a02 = *(const uint64_t*)&Qs[(mi * 16 + gr) * ATP + kc];
                uint64_t a13 = *(const uint64_t*)&Qs[(mi * 16 + gr + 8) * ATP + kc];
                qa[mi][0] = (uint32_t)a02;
                qa[mi][2] = (uint32_t)(a02 >> 32);
                qa[mi][1] = (uint32_t)a13;
                qa[mi][3] = (uint32_t)(a13 >> 32);
            }
#pragma unroll
            for (int ni = 0; ni < 8; ni++) {
                uint64_t bv = *(const uint64_t*)&Ks[(ni * 8 + gr) * ATP + kc];
                const uint32_t b0 = (uint32_t)bv, b1 = (uint32_t)(bv >> 32);
                mma_tf32(s[0][ni], qa[0][0], qa[0][1], qa[0][2], qa[0][3], b0, b1);
                mma_tf32(s[1][ni], qa[1][0], qa[1][1], qa[1][2], qa[1][3], b0, b1);
            }
        }

        // ---- causal mask (only near-diagonal warp x tile combos) ----
        if (jt * 64 + 63 > qt * 128 + wid * 32) {
            const int colb = jt * 64 + 2 * tig;
#pragma unroll
            for (int mi = 0; mi < 2; mi++) {
                const int r0 = rowb + mi * 16;
                const int r1 = r0 + 8;
#pragma unroll
                for (int ni = 0; ni < 8; ni++) {
                    const int c0 = colb + 8 * ni;
                    if (c0 > r0) s[mi][ni][0] = -INFINITY;
                    if (c0 + 1 > r0) s[mi][ni][1] = -INFINITY;
                    if (c0 > r1) s[mi][ni][2] = -INFINITY;
                    if (c0 + 1 > r1) s[mi][ni][3] = -INFINITY;
                }
            }
        }

        // ---- online softmax (per mi, rows gr / gr+8) ----
#pragma unroll
        for (int mi = 0; mi < 2; mi++) {
            float m0 = -INFINITY, m1 = -INFINITY;
#pragma unroll
            for (int ni = 0; ni < 8; ni++) {
                m0 = fmaxf(m0, fmaxf(s[mi][ni][0], s[mi][ni][1]));
                m1 = fmaxf(m1, fmaxf(s[mi][ni][2], s[mi][ni][3]));
            }
            m0 = fmaxf(m0, __shfl_xor_sync(0xffffffffu, m0, 1, 4));
            m0 = fmaxf(m0, __shfl_xor_sync(0xffffffffu, m0, 2, 4));
            m1 = fmaxf(m1, __shfl_xor_sync(0xffffffffu, m1, 1, 4));
            m1 = fmaxf(m1, __shfl_xor_sync(0xffffffffu, m1, 2, 4));
            const float mn0 = fmaxf(mrun[mi][0], m0);
            const float mn1 = fmaxf(mrun[mi][1], m1);
            const float al0 = __expf(mrun[mi][0] - mn0);
            const float al1 = __expf(mrun[mi][1] - mn1);
            float ls0 = 0.f, ls1 = 0.f;
#pragma unroll
            for (int ni = 0; ni < 8; ni++) {
                float p0 = __expf(s[mi][ni][0] - mn0);
                float p1 = __expf(s[mi][ni][1] - mn0);
                float p2 = __expf(s[mi][ni][2] - mn1);
                float p3 = __expf(s[mi][ni][3] - mn1);
                ls0 += p0 + p1;
                ls1 += p2 + p3;
                // overwrite s with tf32 P bits (A-fragment under k-relabeling)
                s[mi][ni][0] = __uint_as_float(f2tf32(p0));
                s[mi][ni][1] = __uint_as_float(f2tf32(p1));
                s[mi][ni][2] = __uint_as_float(f2tf32(p2));
                s[mi][ni][3] = __uint_as_float(f2tf32(p3));
                ctx[mi][ni][0] *= al0;
                ctx[mi][ni][1] *= al0;
                ctx[mi][ni][2] *= al1;
                ctx[mi][ni][3] *= al1;
            }
            ls0 += __shfl_xor_sync(0xffffffffu, ls0, 1, 4);
            ls0 += __shfl_xor_sync(0xffffffffu, ls0, 2, 4);
            ls1 += __shfl_xor_sync(0xffffffffu, ls1, 1, 4);
            ls1 += __shfl_xor_sync(0xffffffffu, ls1, 2, 4);
            mrun[mi][0] = mn0;
            mrun[mi][1] = mn1;
            lrun[mi][0] = lrun[mi][0] * al0 + ls0;
            lrun[mi][1] = lrun[mi][1] * al1 + ls1;
        }

        // ---- ctx += P V ----
#pragma unroll
        for (int ks = 0; ks < 8; ks++) {
#pragma unroll
            for (int ni = 0; ni < 8; ni++) {
                uint64_t bv = *(const uint64_t*)&Vs[(ni * 8 + gr) * ATP + ks * 8 + 2 * tig];
                const uint32_t b0 = (uint32_t)bv, b1 = (uint32_t)(bv >> 32);
                mma_tf32(ctx[0][ni],
                         __float_as_uint(s[0][ks][0]), __float_as_uint(s[0][ks][2]),
                         __float_as_uint(s[0][ks][1]), __float_as_uint(s[0][ks][3]),
                         b0, b1);
                mma_tf32(ctx[1][ni],
                         __float_as_uint(s[1][ks][0]), __float_as_uint(s[1][ks][2]),
                         __float_as_uint(s[1][ks][1]), __float_as_uint(s[1][ks][3]),
                         b0, b1);
            }
        }
    }

    // ---- finalize: g_ctx tf32 (b,t,h,d) ----
#pragma unroll
    for (int mi = 0; mi < 2; mi++) {
        const float inv0 = 1.0f / lrun[mi][0];
        const float inv1 = 1.0f / lrun[mi][1];
        const int r0 = rowb + mi * 16;
        uint32_t* o0 = g_ctx + (((size_t)(b * T_SEQ + r0)) * NH + h) * HD;
        uint32_t* o1 = g_ctx + (((size_t)(b * T_SEQ + r0 + 8)) * NH + h) * HD;
#pragma unroll
        for (int ni = 0; ni < 8; ni++) {
            const int d = ni * 8 + 2 * tig;
            uint2 w0, w1;
            w0.x = f2tf32(ctx[mi][ni][0] * inv0);
            w0.y = f2tf32(ctx[mi][ni][1] * inv0);
            w1.x = f2tf32(ctx[mi][ni][2] * inv1);
            w1.y = f2tf32(ctx[mi][ni][3] * inv1);
            *(uint2*)&o0[d] = w0;
            *(uint2*)&o1[d] = w1;
        }
    }
}

// ---------------------------------------------------------------------------
extern "C" void kernel_launch(void* const* d_in, const int* in_sizes, int n_in,
                              void* d_out, int out_size)
{
    const float* x    = (const float*)d_in[0];
    const float* cosT = (const float*)d_in[1];
    const float* sinT = (const float*)d_in[2];
    const float* wq   = (const float*)d_in[3];
    const float* bq   = (const float*)d_in[4];
    const float* wk   = (const float*)d_in[5];
    const float* bk   = (const float*)d_in[6];
    const float* wv   = (const float*)d_in[7];
    const float* bv   = (const float*)d_in[8];
    const float* wo   = (const float*)d_in[9];
    const float* bo   = (const float*)d_in[10];

    float* out  = (float*)d_out;            // (B, T, D)
    float* kout = out + (size_t)8388608;    // (B, KV, T, HD)
    float* vout = out + (size_t)10485760;   // (B, KV, T, HD)

    const int GEMM_SMEM = 4 * TILE_W * 4;                 // 81920 B
    const int ATTN_SMEM = (QW + 4 * KVW) * 4;             // 110592 B
    static bool attr_set = false;
    if (!attr_set) {
        cudaFuncSetAttribute(db_gemm<0>, cudaFuncAttributeMaxDynamicSharedMemorySize, GEMM_SMEM);
        cudaFuncSetAttribute(db_gemm<1>, cudaFuncAttributeMaxDynamicSharedMemorySize, GEMM_SMEM);
        cudaFuncSetAttribute(attn_mma, cudaFuncAttributeMaxDynamicSharedMemorySize, ATTN_SMEM);
        attr_set = true;
    }

    uint32_t* p_xt;  cudaGetSymbolAddress((void**)&p_xt, g_xt);
    uint32_t* p_wq;  cudaGetSymbolAddress((void**)&p_wq, g_wq);
    uint32_t* p_wk;  cudaGetSymbolAddress((void**)&p_wk, g_wk);
    uint32_t* p_wv;  cudaGetSymbolAddress((void**)&p_wv, g_wv);
    uint32_t* p_wo;  cudaGetSymbolAddress((void**)&p_wo, g_wo);
    uint32_t* p_vt;  cudaGetSymbolAddress((void**)&p_vt, g_vt);

    // Prep: fp32 -> tf32
    cvt_all<<<18432, 256>>>(x, wq, wk, wv, wo, p_xt, p_wq, p_wk, p_wv, p_wo);

    // Fused QKV projections (+RoPE for Q,K; Q -> tf32 scaled; K -> fp32 + tf32)
    db_gemm<0><<<dim3(24, 32), 128, GEMM_SMEM>>>(
        p_xt, bq, bk, bv, kout, vout, nullptr, cosT, sinT);

    // V -> transposed tf32
    vtrans<<<dim3(32, 16), 256>>>(vout, p_vt);

    // Attention -> g_ctx (tf32)
    attn_mma<<<dim3(T_SEQ / 128, 2 * NH), 128, ATTN_SMEM>>>();

    // Output projection -> out
    db_gemm<1><<<dim3(16, 32), 128, GEMM_SMEM>>>(
        nullptr, bo, nullptr, nullptr, nullptr, nullptr, out, nullptr, nullptr);
}

// round 9
// speedup vs baseline: 1.0858x; 1.0858x over previous
#include <cuda_runtime.h>
#include <cstdint>
#include <math.h>

#define T_SEQ 2048
#define DMODEL 2048
#define NH 32
#define NKV 8
#define HD 64

// ---------------- Scratch (device globals; allocation-free) ----------------
// k16 permutation: within each 16-word k-block, logical k = b*8 + 2*tig + lo
// (b in {0,1}, tig in 0..3, lo in {0,1}) is stored at slot tig*4 + b*2 + lo.
// Applied identically to both MMA operands' k dimension -> results bit-exact.
__device__ float    g_q  [(size_t)2 * NH * T_SEQ * HD];   // fp32 Q (b,h,t,d) natural
__device__ uint32_t g_ctx[(size_t)2 * T_SEQ * NH * HD];   // tf32 ctx (b,t,h,d) PERM
__device__ uint32_t g_xt [(size_t)4096 * 2048];           // tf32 x PERM
__device__ uint32_t g_wq [(size_t)2048 * 2048];           // PERM
__device__ uint32_t g_wk [(size_t)512 * 2048];            // PERM
__device__ uint32_t g_wv [(size_t)512 * 2048];            // PERM
__device__ uint32_t g_wo [(size_t)2048 * 2048];           // PERM
__device__ uint32_t g_kc [(size_t)2 * NKV * T_SEQ * HD];  // tf32 K (b,kv,t,d) PERM(d)
__device__ uint32_t g_vt [(size_t)2 * NKV * HD * T_SEQ];  // tf32 V^T (b,kv,d,t) PERM(t)

__device__ __forceinline__ uint32_t f2tf32(float f) {
    uint32_t u;
    asm("cvt.rna.tf32.f32 %0, %1;" : "=r"(u) : "f"(f));
    return u;
}

__device__ __forceinline__ void mma_tf32(float* c, uint32_t a0, uint32_t a1,
                                         uint32_t a2, uint32_t a3,
                                         uint32_t b0, uint32_t b1) {
    asm volatile(
        "mma.sync.aligned.m16n8k8.row.col.f32.tf32.tf32.f32 "
        "{%0,%1,%2,%3}, {%4,%5,%6,%7}, {%8,%9}, {%0,%1,%2,%3};"
        : "+f"(c[0]), "+f"(c[1]), "+f"(c[2]), "+f"(c[3])
        : "r"(a0), "r"(a1), "r"(a2), "r"(a3), "r"(b0), "r"(b1));
}

__device__ __forceinline__ uint32_t smem_u32(const void* p) {
    uint32_t a;
    asm("{ .reg .u64 t; cvta.to.shared.u64 t, %1; cvt.u32.u64 %0, t; }"
        : "=r"(a) : "l"(p));
    return a;
}
#define CP_ASYNC16(dst, src) \
    asm volatile("cp.async.ca.shared.global [%0], [%1], 16;" :: "r"(dst), "l"(src))
#define CP_COMMIT() asm volatile("cp.async.commit_group;" ::: "memory")
#define CP_WAIT0()  asm volatile("cp.async.wait_group 0;" ::: "memory")

// ============================================================================
// Prep: all fp32 -> tf32, k16-PERMUTED output. Each float4 covers 4 logical
// ks {k0..k0+3} (k0%4==0) -> two uint2 at slots slot0 and slot0+4.
// ============================================================================
__global__ void cvt_all(const float* __restrict__ x,
                        const float* __restrict__ wq,
                        const float* __restrict__ wk,
                        const float* __restrict__ wv,
                        const float* __restrict__ wo,
                        uint32_t* __restrict__ xt,
                        uint32_t* __restrict__ wqt,
                        uint32_t* __restrict__ wkt,
                        uint32_t* __restrict__ wvt,
                        uint32_t* __restrict__ wot)
{
    int i = blockIdx.x * blockDim.x + threadIdx.x;
    const float* in;
    uint32_t* out;
    if (i < 2097152)        { in = x;  out = xt; }
    else if (i < 3145728)   { in = wq; out = wqt; i -= 2097152; }
    else if (i < 3407872)   { in = wk; out = wkt; i -= 3145728; }
    else if (i < 3670016)   { in = wv; out = wvt; i -= 3407872; }
    else                    { in = wo; out = wot; i -= 3670016; }
    float4 v = ((const float4*)in)[i];
    const int w0 = i * 4;
    const int blockbase = w0 & ~15;
    const int k0 = w0 & 15;
    const int slot0 = ((k0 & 7) >> 1) * 4 + ((k0 >> 3) & 1) * 2;
    uint2 lo, hi;
    lo.x = f2tf32(v.x); lo.y = f2tf32(v.y);
    hi.x = f2tf32(v.z); hi.y = f2tf32(v.w);
    *(uint2*)&out[blockbase + slot0] = lo;
    *(uint2*)&out[blockbase + slot0 + 4] = hi;
}

// ============================================================================
// Prep: V (b,kv,t,d) fp32 -> V^T (b,kv,d,t) tf32, key dim k16-PERMUTED.
// ============================================================================
__global__ void vtrans(const float* __restrict__ vin, uint32_t* __restrict__ vt)
{
    __shared__ uint32_t ts[64 * 65];
    const int tid = threadIdx.x;
    const int jt = blockIdx.x;
    const int bkv = blockIdx.y;

    const float* in = vin + ((size_t)bkv * T_SEQ + jt * 64) * HD;
#pragma unroll
    for (int p = 0; p < 4; p++) {
        const int lin = p * 256 + tid;
        const int t = lin >> 4;
        const int dq = (lin & 15) * 4;
        float4 v = *(const float4*)&in[t * HD + dq];
        ts[(dq + 0) * 65 + t] = f2tf32(v.x);
        ts[(dq + 1) * 65 + t] = f2tf32(v.y);
        ts[(dq + 2) * 65 + t] = f2tf32(v.z);
        ts[(dq + 3) * 65 + t] = f2tf32(v.w);
    }
    __syncthreads();
    uint32_t* out = vt + (size_t)bkv * HD * T_SEQ + jt * 64;
#pragma unroll
    for (int p = 0; p < 4; p++) {
        const int lin = p * 256 + tid;
        const int d = lin >> 4;
        const int cq = (lin & 15) * 4;   // key offset within tile, %4==0
        const int blockbase = cq & ~15;
        const int k0 = cq & 15;
        const int slot0 = ((k0 & 7) >> 1) * 4 + ((k0 >> 3) & 1) * 2;
        uint2 lo, hi;
        lo.x = ts[d * 65 + cq + 0];
        lo.y = ts[d * 65 + cq + 1];
        hi.x = ts[d * 65 + cq + 2];
        hi.y = ts[d * 65 + cq + 3];
        *(uint2*)&out[(size_t)d * T_SEQ + blockbase + slot0] = lo;
        *(uint2*)&out[(size_t)d * T_SEQ + blockbase + slot0 + 4] = hi;
    }
}

// ============================================================================
// cp.async double-buffered tf32 GEMM, 128x128 tile, BK=32, 8 warps (2x4),
// warp tile 64x32. PERM16 operands -> LDS.128 fragment loads (half the LDS
// instructions of R7). Pitch 48 (==16 mod 32): conflict-free v4 reads.
// KIND 0: fused QKV. bx<16: Q+RoPE->g_q fp32; 16..19: K+RoPE->kout fp32 +
//         g_kc tf32 PERM; 20..23: V->vout fp32.
// KIND 1: O projection: A=g_ctx (tf32 PERM), C=out fp32.
// ============================================================================
#define SPAD 48
#define TILE_W (128 * SPAD)

template <int KIND>
__global__ __launch_bounds__(256, 2) void db_gemm(
    const uint32_t* __restrict__ xA,
    const float* __restrict__ bq, const float* __restrict__ bk,
    const float* __restrict__ bv,
    float* __restrict__ kout, float* __restrict__ vout,
    float* __restrict__ outC,
    const float* __restrict__ cosT, const float* __restrict__ sinT)
{
    extern __shared__ __align__(16) uint32_t sm[];
    const uint32_t sm_addr = smem_u32(sm);

    const int tid = threadIdx.x;
    const int wid = tid >> 5;
    const int lane = tid & 31;
    const int gr = lane >> 2;
    const int tig = lane & 3;
    const int wm = wid >> 2;   // 0..1
    const int wn = wid & 3;    // 0..3

    constexpr int K = DMODEL;
    const int m0 = blockIdx.y * 128;

    int mode, n0;
    const uint32_t* A;
    const uint32_t* W;
    const float* bias;
    if (KIND == 1) {
        mode = 0; n0 = blockIdx.x * 128; A = g_ctx; W = g_wo; bias = bq;
    } else {
        const int bx = blockIdx.x;
        A = xA;
        if (bx < 16)      { mode = 1; n0 = bx * 128;        W = g_wq; bias = bq; }
        else if (bx < 20) { mode = 2; n0 = (bx - 16) * 128; W = g_wk; bias = bk; }
        else              { mode = 3; n0 = (bx - 20) * 128; W = g_wv; bias = bv; }
    }

    const int rbase = tid >> 3;   // 0..31
    const int cg = tid & 7;       // 16B chunk within 32 words
    const uint32_t* Asrc[4];
    const uint32_t* Wsrc[4];
    uint32_t dsto[4];
#pragma unroll
    for (int i = 0; i < 4; i++) {
        Asrc[i] = A + (size_t)(m0 + i * 32 + rbase) * K + cg * 4;
        Wsrc[i] = W + (size_t)(n0 + i * 32 + rbase) * K + cg * 4;
        dsto[i] = (uint32_t)(((i * 32 + rbase) * SPAD + cg * 4) * 4);
    }

    float acc[4][4][4];
#pragma unroll
    for (int mi = 0; mi < 4; mi++)
#pragma unroll
        for (int ni = 0; ni < 4; ni++)
#pragma unroll
            for (int r = 0; r < 4; r++) acc[mi][ni][r] = 0.f;

    const int NST = K / 32;
#pragma unroll
    for (int i = 0; i < 4; i++) {
        CP_ASYNC16(sm_addr + dsto[i], Asrc[i]);
        CP_ASYNC16(sm_addr + TILE_W * 4 + dsto[i], Wsrc[i]);
    }
    CP_COMMIT();

    for (int s = 0; s < NST; s++) {
        CP_WAIT0();
        __syncthreads();
        if (s + 1 < NST) {
            const uint32_t boff = (uint32_t)((s + 1) & 1) * (2 * TILE_W * 4);
            const int ko = (s + 1) * 32;
#pragma unroll
            for (int i = 0; i < 4; i++) {
                CP_ASYNC16(sm_addr + boff + dsto[i], Asrc[i] + ko);
                CP_ASYNC16(sm_addr + boff + TILE_W * 4 + dsto[i], Wsrc[i] + ko);
            }
            CP_COMMIT();
        }

        const uint32_t* Abase = sm + (s & 1) * 2 * TILE_W + (wm * 64) * SPAD;
        const uint32_t* Bbase = sm + (s & 1) * 2 * TILE_W + TILE_W + (wn * 32) * SPAD;
#pragma unroll
        for (int kp = 0; kp < 2; kp++) {              // 2 kk-pairs per stage
            const int kc = kp * 16 + tig * 4;
            uint4 bf[4];
#pragma unroll
            for (int ni = 0; ni < 4; ni++)
                bf[ni] = *(const uint4*)&Bbase[(ni * 8 + gr) * SPAD + kc];
#pragma unroll
            for (int mi = 0; mi < 4; mi++) {
                uint4 aL = *(const uint4*)&Abase[(mi * 16 + gr) * SPAD + kc];
                uint4 aH = *(const uint4*)&Abase[(mi * 16 + gr + 8) * SPAD + kc];
#pragma unroll
                for (int ni = 0; ni < 4; ni++) {
                    mma_tf32(acc[mi][ni], aL.x, aH.x, aL.y, aH.y, bf[ni].x, bf[ni].y);
                    mma_tf32(acc[mi][ni], aL.z, aH.z, aL.w, aH.w, bf[ni].z, bf[ni].w);
                }
            }
        }
    }

    // ---------------- Register epilogue ----------------
#pragma unroll
    for (int mi = 0; mi < 4; mi++) {
#pragma unroll
        for (int half = 0; half < 2; half++) {
            const int m = m0 + wm * 64 + mi * 16 + gr + half * 8;
            const int bb = m >> 11;
            const int t = m & (T_SEQ - 1);
#pragma unroll
            for (int ni = 0; ni < 4; ni++) {
                const int n = n0 + wn * 32 + ni * 8 + tig * 2;
                float v0 = acc[mi][ni][half * 2 + 0] + bias[n];
                float v1 = acc[mi][ni][half * 2 + 1] + bias[n + 1];
                if (mode == 1 || mode == 2) {
                    const int hh = (n & 63) >> 1;
                    const float c = cosT[t * (HD / 2) + hh];
                    const float ss = sinT[t * (HD / 2) + hh];
                    const float e = v0 * c - v1 * ss;
                    const float o = v0 * ss + v1 * c;
                    v0 = e;
                    v1 = o;
                }
                if (mode == 0) {
                    *(float2*)&outC[(size_t)m * DMODEL + n] = make_float2(v0, v1);
                } else if (mode == 1) {
                    *(float2*)&g_q[(((size_t)(bb * NH + (n >> 6))) * T_SEQ + t) * HD + (n & 63)] =
                        make_float2(v0, v1);
                } else {
                    const size_t idx =
                        (((size_t)(bb * NKV + (n >> 6))) * T_SEQ + t) * HD + (n & 63);
                    if (mode == 2) {
                        *(float2*)&kout[idx] = make_float2(v0, v1);
                        // PERM16 tf32 K: d pair (even) -> consecutive slots
                        const int d = n & 63;
                        const int k0 = d & 15;
                        const int slot0 = ((k0 & 7) >> 1) * 4 + ((k0 >> 3) & 1) * 2;
                        const size_t base =
                            (((size_t)(bb * NKV + (n >> 6))) * T_SEQ + t) * HD +
                            (d & ~15) + slot0;
                        uint2 kq;
                        kq.x = f2tf32(v0);
                        kq.y = f2tf32(v1);
                        *(uint2*)&g_kc[base] = kq;
                    } else {
                        *(float2*)&vout[idx] = make_float2(v0, v1);
                    }
                }
            }
        }
    }
}

// ============================================================================
// Flash attention, tf32 mma.sync. 256 thr = 8 warps, warp tile 16x64 (R7).
// K/V tiles PERM16 in global -> LDS.128 fragment loads. Pitch 80.
// Heavy-first q-tile scheduling. cp.async double-buffered K/V.
// ============================================================================
#define ATP 80
#define KVW (64 * ATP)   // 5120 words

__global__ __launch_bounds__(256, 2) void attn_mma()
{
    extern __shared__ __align__(16) uint32_t sm[];
    const uint32_t sm_addr = smem_u32(sm);

    const int tid = threadIdx.x;
    const int wid = tid >> 5;
    const int lane = tid & 31;
    const int gr = lane >> 2;
    const int tig = lane & 3;

    const int qt = (gridDim.x - 1) - blockIdx.x;  // heavy-first
    const int bh = blockIdx.y;
    const int b = bh >> 5;
    const int h = bh & 31;
    const int bkv = (b * NKV) + (h >> 2);

    // Q fragments (registers, natural layout): qa[ks] covers d = 8ks+2tig, +1
    const float* Qg = g_q + (((size_t)(b * NH + h)) * T_SEQ + qt * 128 + wid * 16) * HD;
    uint32_t qa[8][4];
#pragma unroll
    for (int ks = 0; ks < 8; ks++) {
        const int d0 = 8 * ks + 2 * tig;
        qa[ks][0] = f2tf32(Qg[gr * HD + d0] * 0.125f);
        qa[ks][1] = f2tf32(Qg[(gr + 8) * HD + d0] * 0.125f);
        qa[ks][2] = f2tf32(Qg[gr * HD + d0 + 1] * 0.125f);
        qa[ks][3] = f2tf32(Qg[(gr + 8) * HD + d0 + 1] * 0.125f);
    }

    const uint32_t* Kbase = g_kc + (size_t)bkv * T_SEQ * HD;
    const uint32_t* Vbase = g_vt + (size_t)bkv * HD * T_SEQ;

    float ctx[8][4];
#pragma unroll
    for (int ni = 0; ni < 8; ni++)
#pragma unroll
        for (int r = 0; r < 4; r++) ctx[ni][r] = 0.f;
    float mrun0 = -INFINITY, mrun1 = -INFINITY;
    float lrun0 = 0.f, lrun1 = 0.f;

    const int lrow = tid >> 2;
    const int lcol = (tid & 3) * 16;
    const int row0 = qt * 128 + wid * 16 + gr;
    const int row1 = row0 + 8;
    const int njt = 2 * qt + 2;

#pragma unroll
    for (int c = 0; c < 4; c++) {
        const int col = lcol + 4 * c;
        CP_ASYNC16(sm_addr + (lrow * ATP + col) * 4, Kbase + (size_t)lrow * HD + col);
        CP_ASYNC16(sm_addr + (2 * KVW + lrow * ATP + col) * 4,
                   Vbase + (size_t)lrow * T_SEQ + col);
    }
    CP_COMMIT();

    for (int jt = 0; jt < njt; jt++) {
        CP_WAIT0();
        __syncthreads();
        if (jt + 1 < njt) {
            const uint32_t boff = (uint32_t)((jt + 1) & 1) * KVW * 4;
            const int kt = (jt + 1) * 64;
#pragma unroll
            for (int c = 0; c < 4; c++) {
                const int col = lcol + 4 * c;
                CP_ASYNC16(sm_addr + boff + (lrow * ATP + col) * 4,
                           Kbase + (size_t)(kt + lrow) * HD + col);
                CP_ASYNC16(sm_addr + 2 * KVW * 4 + boff + (lrow * ATP + col) * 4,
                           Vbase + (size_t)lrow * T_SEQ + kt + col);
            }
            CP_COMMIT();
        }

        if (jt == 2 * qt + 1 && wid < 4) continue;  // fully masked

        const uint32_t* Ks = sm + (jt & 1) * KVW;
        const uint32_t* Vt = sm + 2 * KVW + (jt & 1) * KVW;

        // ---- S = Q K^T : LDS.128 gives kk-pair (2kp, 2kp+1) per read ----
        float s[8][4];
#pragma unroll
        for (int ni = 0; ni < 8; ni++)
#pragma unroll
            for (int r = 0; r < 4; r++) s[ni][r] = 0.f;
#pragma unroll
        for (int kp = 0; kp < 4; kp++) {
            const int kc = kp * 16 + tig * 4;
#pragma unroll
            for (int ni = 0; ni < 8; ni++) {
                uint4 bv = *(const uint4*)&Ks[(ni * 8 + gr) * ATP + kc];
                mma_tf32(s[ni], qa[2 * kp][0], qa[2 * kp][1], qa[2 * kp][2],
                         qa[2 * kp][3], bv.x, bv.y);
                mma_tf32(s[ni], qa[2 * kp + 1][0], qa[2 * kp + 1][1],
                         qa[2 * kp + 1][2], qa[2 * kp + 1][3], bv.z, bv.w);
            }
        }

        // ---- causal mask ----
        if (jt >= 2 * qt) {
            const int colb = jt * 64 + 2 * tig;
#pragma unroll
            for (int ni = 0; ni < 8; ni++) {
                const int c0 = colb + 8 * ni;
                if (c0 > row0) s[ni][0] = -INFINITY;
                if (c0 + 1 > row0) s[ni][1] = -INFINITY;
                if (c0 > row1) s[ni][2] = -INFINITY;
                if (c0 + 1 > row1) s[ni][3] = -INFINITY;
            }
        }

        // ---- online softmax ----
        float m0 = -INFINITY, m1 = -INFINITY;
#pragma unroll
        for (int ni = 0; ni < 8; ni++) {
            m0 = fmaxf(m0, fmaxf(s[ni][0], s[ni][1]));
            m1 = fmaxf(m1, fmaxf(s[ni][2], s[ni][3]));
        }
        m0 = fmaxf(m0, __shfl_xor_sync(0xffffffffu, m0, 1, 4));
        m0 = fmaxf(m0, __shfl_xor_sync(0xffffffffu, m0, 2, 4));
        m1 = fmaxf(m1, __shfl_xor_sync(0xffffffffu, m1, 1, 4));
        m1 = fmaxf(m1, __shfl_xor_sync(0xffffffffu, m1, 2, 4));
        const float mn0 = fmaxf(mrun0, m0);
        const float mn1 = fmaxf(mrun1, m1);
        const float al0 = __expf(mrun0 - mn0);
        const float al1 = __expf(mrun1 - mn1);
        float ls0 = 0.f, ls1 = 0.f;
        uint32_t pb[8][4];
#pragma unroll
        for (int ni = 0; ni < 8; ni++) {
            float p0 = __expf(s[ni][0] - mn0);
            float p1 = __expf(s[ni][1] - mn0);
            float p2 = __expf(s[ni][2] - mn1);
            float p3 = __expf(s[ni][3] - mn1);
            ls0 += p0 + p1;
            ls1 += p2 + p3;
            pb[ni][0] = f2tf32(p0);
            pb[ni][1] = f2tf32(p1);
            pb[ni][2] = f2tf32(p2);
            pb[ni][3] = f2tf32(p3);
            ctx[ni][0] *= al0;
            ctx[ni][1] *= al0;
            ctx[ni][2] *= al1;
            ctx[ni][3] *= al1;
        }
        ls0 += __shfl_xor_sync(0xffffffffu, ls0, 1, 4);
        ls0 += __shfl_xor_sync(0xffffffffu, ls0, 2, 4);
        ls1 += __shfl_xor_sync(0xffffffffu, ls1, 1, 4);
        ls1 += __shfl_xor_sync(0xffffffffu, ls1, 2, 4);
        mrun0 = mn0;
        mrun1 = mn1;
        lrun0 = lrun0 * al0 + ls0;
        lrun1 = lrun1 * al1 + ls1;

        // ---- ctx += P V : LDS.128 gives key-pair blocks (2kp, 2kp+1) ----
#pragma unroll
        for (int kp = 0; kp < 4; kp++) {
            const int kc = kp * 16 + tig * 4;
#pragma unroll
            for (int ni = 0; ni < 8; ni++) {
                uint4 bv = *(const uint4*)&Vt[(ni * 8 + gr) * ATP + kc];
                mma_tf32(ctx[ni], pb[2 * kp][0], pb[2 * kp][2], pb[2 * kp][1],
                         pb[2 * kp][3], bv.x, bv.y);
                mma_tf32(ctx[ni], pb[2 * kp + 1][0], pb[2 * kp + 1][2],
                         pb[2 * kp + 1][1], pb[2 * kp + 1][3], bv.z, bv.w);
            }
        }
    }

    // ---- finalize: g_ctx tf32 PERM16 (consumed by O-GEMM smem loads) ----
    const float inv0 = 1.0f / lrun0;
    const float inv1 = 1.0f / lrun1;
    uint32_t* o0 = g_ctx + (((size_t)(b * T_SEQ + row0)) * NH + h) * HD;
    uint32_t* o1 = g_ctx + (((size_t)(b * T_SEQ + row1)) * NH + h) * HD;
#pragma unroll
    for (int ni = 0; ni < 8; ni++) {
        const int d = ni * 8 + 2 * tig;
        const int word = ((d >> 4) << 4) + tig * 4 + (ni & 1) * 2;  // PERM slot
        uint2 w0, w1;
        w0.x = f2tf32(ctx[ni][0] * inv0);
        w0.y = f2tf32(ctx[ni][1] * inv0);
        w1.x = f2tf32(ctx[ni][2] * inv1);
        w1.y = f2tf32(ctx[ni][3] * inv1);
        *(uint2*)&o0[word] = w0;
        *(uint2*)&o1[word] = w1;
    }
}

// ---------------------------------------------------------------------------
extern "C" void kernel_launch(void* const* d_in, const int* in_sizes, int n_in,
                              void* d_out, int out_size)
{
    const float* x    = (const float*)d_in[0];
    const float* cosT = (const float*)d_in[1];
    const float* sinT = (const float*)d_in[2];
    const float* wq   = (const float*)d_in[3];
    const float* bq   = (const float*)d_in[4];
    const float* wk   = (const float*)d_in[5];
    const float* bk   = (const float*)d_in[6];
    const float* wv   = (const float*)d_in[7];
    const float* bv   = (const float*)d_in[8];
    const float* wo   = (const float*)d_in[9];
    const float* bo   = (const float*)d_in[10];

    float* out  = (float*)d_out;            // (B, T, D)
    float* kout = out + (size_t)8388608;    // (B, KV, T, HD)
    float* vout = out + (size_t)10485760;   // (B, KV, T, HD)

    const int GEMM_SMEM = 4 * TILE_W * 4;   // 98304 B
    const int ATTN_SMEM = 4 * KVW * 4;      // 81920 B
    static bool attr_set = false;
    if (!attr_set) {
        cudaFuncSetAttribute(db_gemm<0>, cudaFuncAttributeMaxDynamicSharedMemorySize, GEMM_SMEM);
        cudaFuncSetAttribute(db_gemm<1>, cudaFuncAttributeMaxDynamicSharedMemorySize, GEMM_SMEM);
        cudaFuncSetAttribute(attn_mma, cudaFuncAttributeMaxDynamicSharedMemorySize, ATTN_SMEM);
        attr_set = true;
    }

    uint32_t* p_xt;  cudaGetSymbolAddress((void**)&p_xt, g_xt);
    uint32_t* p_wq;  cudaGetSymbolAddress((void**)&p_wq, g_wq);
    uint32_t* p_wk;  cudaGetSymbolAddress((void**)&p_wk, g_wk);
    uint32_t* p_wv;  cudaGetSymbolAddress((void**)&p_wv, g_wv);
    uint32_t* p_wo;  cudaGetSymbolAddress((void**)&p_wo, g_wo);
    uint32_t* p_vt;  cudaGetSymbolAddress((void**)&p_vt, g_vt);

    // Prep: fp32 -> tf32 (PERM16), one launch
    cvt_all<<<18432, 256>>>(x, wq, wk, wv, wo, p_xt, p_wq, p_wk, p_wv, p_wo);

    // Fused QKV projections (+RoPE for Q,K; K also written as PERM tf32 g_kc)
    db_gemm<0><<<dim3(24, 32), 256, GEMM_SMEM>>>(
        p_xt, bq, bk, bv, kout, vout, nullptr, cosT, sinT);

    // V -> transposed PERM tf32
    vtrans<<<dim3(32, 16), 256>>>(vout, p_vt);

    // Attention -> g_ctx (PERM tf32)
    attn_mma<<<dim3(T_SEQ / 128, 2 * NH), 256, ATTN_SMEM>>>();

    // Output projection -> out
    db_gemm<1><<<dim3(16, 32), 256, GEMM_SMEM>>>(
        nullptr, bo, nullptr, nullptr, nullptr, nullptr, out, nullptr, nullptr);
}

// round 10
// speedup vs baseline: 1.1019x; 1.0148x over previous
#include <cuda_runtime.h>
#include <cstdint>
#include <math.h>

#define T_SEQ 2048
#define DMODEL 2048
#define NH 32
#define NKV 8
#define HD 64

// ---------------- Scratch (device globals; allocation-free) ----------------
// k16 permutation (global): within each 16-word k-block, logical k = b*8 +
// 2*tig + lo stored at slot tig*4 + b*2 + lo. Applied identically to both MMA
// operands' k dimension -> results bit-exact.
// smem additionally uses an XOR-16 block swizzle: phys_col = col ^ ((row&1)*16).
__device__ float    g_q  [(size_t)2 * NH * T_SEQ * HD];   // fp32 Q (b,h,t,d)
__device__ uint32_t g_ctx[(size_t)2 * T_SEQ * NH * HD];   // tf32 ctx PERM
__device__ uint32_t g_xt [(size_t)4096 * 2048];           // tf32 x PERM
__device__ uint32_t g_wq [(size_t)2048 * 2048];           // PERM
__device__ uint32_t g_wk [(size_t)512 * 2048];            // PERM
__device__ uint32_t g_wv [(size_t)512 * 2048];            // PERM
__device__ uint32_t g_wo [(size_t)2048 * 2048];           // PERM
__device__ uint32_t g_kc [(size_t)2 * NKV * T_SEQ * HD];  // tf32 K PERM(d)
__device__ uint32_t g_vt [(size_t)2 * NKV * HD * T_SEQ];  // tf32 V^T PERM(t)

__device__ __forceinline__ uint32_t f2tf32(float f) {
    uint32_t u;
    asm("cvt.rna.tf32.f32 %0, %1;" : "=r"(u) : "f"(f));
    return u;
}

__device__ __forceinline__ void mma_tf32(float* c, uint32_t a0, uint32_t a1,
                                         uint32_t a2, uint32_t a3,
                                         uint32_t b0, uint32_t b1) {
    asm volatile(
        "mma.sync.aligned.m16n8k8.row.col.f32.tf32.tf32.f32 "
        "{%0,%1,%2,%3}, {%4,%5,%6,%7}, {%8,%9}, {%0,%1,%2,%3};"
        : "+f"(c[0]), "+f"(c[1]), "+f"(c[2]), "+f"(c[3])
        : "r"(a0), "r"(a1), "r"(a2), "r"(a3), "r"(b0), "r"(b1));
}

__device__ __forceinline__ uint32_t smem_u32(const void* p) {
    uint32_t a;
    asm("{ .reg .u64 t; cvta.to.shared.u64 t, %1; cvt.u32.u64 %0, t; }"
        : "=r"(a) : "l"(p));
    return a;
}
#define CP_ASYNC16(dst, src) \
    asm volatile("cp.async.ca.shared.global [%0], [%1], 16;" :: "r"(dst), "l"(src))
#define CP_COMMIT() asm volatile("cp.async.commit_group;" ::: "memory")
#define CP_WAIT0()  asm volatile("cp.async.wait_group 0;" ::: "memory")

// ============================================================================
// Prep: all fp32 -> tf32, k16-PERMUTED output.
// ============================================================================
__global__ void cvt_all(const float* __restrict__ x,
                        const float* __restrict__ wq,
                        const float* __restrict__ wk,
                        const float* __restrict__ wv,
                        const float* __restrict__ wo,
                        uint32_t* __restrict__ xt,
                        uint32_t* __restrict__ wqt,
                        uint32_t* __restrict__ wkt,
                        uint32_t* __restrict__ wvt,
                        uint32_t* __restrict__ wot)
{
    int i = blockIdx.x * blockDim.x + threadIdx.x;
    const float* in;
    uint32_t* out;
    if (i < 2097152)        { in = x;  out = xt; }
    else if (i < 3145728)   { in = wq; out = wqt; i -= 2097152; }
    else if (i < 3407872)   { in = wk; out = wkt; i -= 3145728; }
    else if (i < 3670016)   { in = wv; out = wvt; i -= 3407872; }
    else                    { in = wo; out = wot; i -= 3670016; }
    float4 v = ((const float4*)in)[i];
    const int w0 = i * 4;
    const int blockbase = w0 & ~15;
    const int k0 = w0 & 15;
    const int slot0 = ((k0 & 7) >> 1) * 4 + ((k0 >> 3) & 1) * 2;
    uint2 lo, hi;
    lo.x = f2tf32(v.x); lo.y = f2tf32(v.y);
    hi.x = f2tf32(v.z); hi.y = f2tf32(v.w);
    *(uint2*)&out[blockbase + slot0] = lo;
    *(uint2*)&out[blockbase + slot0 + 4] = hi;
}

// ============================================================================
// Prep: V (b,kv,t,d) fp32 -> V^T (b,kv,d,t) tf32, key dim k16-PERMUTED.
// ============================================================================
__global__ void vtrans(const float* __restrict__ vin, uint32_t* __restrict__ vt)
{
    __shared__ uint32_t ts[64 * 65];
    const int tid = threadIdx.x;
    const int jt = blockIdx.x;
    const int bkv = blockIdx.y;

    const float* in = vin + ((size_t)bkv * T_SEQ + jt * 64) * HD;
#pragma unroll
    for (int p = 0; p < 4; p++) {
        const int lin = p * 256 + tid;
        const int t = lin >> 4;
        const int dq = (lin & 15) * 4;
        float4 v = *(const float4*)&in[t * HD + dq];
        ts[(dq + 0) * 65 + t] = f2tf32(v.x);
        ts[(dq + 1) * 65 + t] = f2tf32(v.y);
        ts[(dq + 2) * 65 + t] = f2tf32(v.z);
        ts[(dq + 3) * 65 + t] = f2tf32(v.w);
    }
    __syncthreads();
    uint32_t* out = vt + (size_t)bkv * HD * T_SEQ + jt * 64;
#pragma unroll
    for (int p = 0; p < 4; p++) {
        const int lin = p * 256 + tid;
        const int d = lin >> 4;
        const int cq = (lin & 15) * 4;
        const int blockbase = cq & ~15;
        const int k0 = cq & 15;
        const int slot0 = ((k0 & 7) >> 1) * 4 + ((k0 >> 3) & 1) * 2;
        uint2 lo, hi;
        lo.x = ts[d * 65 + cq + 0];
        lo.y = ts[d * 65 + cq + 1];
        hi.x = ts[d * 65 + cq + 2];
        hi.y = ts[d * 65 + cq + 3];
        *(uint2*)&out[(size_t)d * T_SEQ + blockbase + slot0] = lo;
        *(uint2*)&out[(size_t)d * T_SEQ + blockbase + slot0 + 4] = hi;
    }
}

// ============================================================================
// cp.async double-buffered tf32 GEMM, 128x128 tile, BK=32, 8 warps (2x4),
// warp tile 64x32. PERM16 + XOR16 smem swizzle; pitch = exact 32 words.
// Conflict-free LDS.128 fragment loads (bank group = (kp^gr&1)*4 + tig).
// KIND 0: fused QKV. bx<16: Q+RoPE->g_q fp32; 16..19: K+RoPE->kout fp32 +
//         g_kc tf32 PERM; 20..23: V->vout fp32.
// KIND 1: O projection: A=g_ctx (tf32 PERM), C=out fp32.
// ============================================================================
#define GP 32
#define TILE_W (128 * GP)   // 4096 words per operand tile

template <int KIND>
__global__ __launch_bounds__(256, 2) void db_gemm(
    const uint32_t* __restrict__ xA,
    const float* __restrict__ bq, const float* __restrict__ bk,
    const float* __restrict__ bv,
    float* __restrict__ kout, float* __restrict__ vout,
    float* __restrict__ outC,
    const float* __restrict__ cosT, const float* __restrict__ sinT)
{
    extern __shared__ __align__(16) uint32_t sm[];
    const uint32_t sm_addr = smem_u32(sm);

    const int tid = threadIdx.x;
    const int wid = tid >> 5;
    const int lane = tid & 31;
    const int gr = lane >> 2;
    const int tig = lane & 3;
    const int wm = wid >> 2;   // 0..1
    const int wn = wid & 3;    // 0..3
    const int rpar16 = (gr & 1) << 4;   // XOR16 swizzle for this thread's rows

    constexpr int K = DMODEL;
    const int m0 = blockIdx.y * 128;

    int mode, n0;
    const uint32_t* A;
    const uint32_t* W;
    const float* bias;
    if (KIND == 1) {
        mode = 0; n0 = blockIdx.x * 128; A = g_ctx; W = g_wo; bias = bq;
    } else {
        const int bx = blockIdx.x;
        A = xA;
        if (bx < 16)      { mode = 1; n0 = bx * 128;        W = g_wq; bias = bq; }
        else if (bx < 20) { mode = 2; n0 = (bx - 16) * 128; W = g_wk; bias = bk; }
        else              { mode = 3; n0 = (bx - 20) * 128; W = g_wv; bias = bv; }
    }

    const int rbase = tid >> 3;   // 0..31
    const int cg = tid & 7;       // 16B chunk
    const int scol = (cg * 4) ^ ((rbase & 1) << 4);   // swizzled store col
    const uint32_t* Asrc[4];
    const uint32_t* Wsrc[4];
    uint32_t dsto[4];
#pragma unroll
    for (int i = 0; i < 4; i++) {
        Asrc[i] = A + (size_t)(m0 + i * 32 + rbase) * K + cg * 4;
        Wsrc[i] = W + (size_t)(n0 + i * 32 + rbase) * K + cg * 4;
        dsto[i] = (uint32_t)(((i * 32 + rbase) * GP + scol) * 4);
    }

    float acc[4][4][4];
#pragma unroll
    for (int mi = 0; mi < 4; mi++)
#pragma unroll
        for (int ni = 0; ni < 4; ni++)
#pragma unroll
            for (int r = 0; r < 4; r++) acc[mi][ni][r] = 0.f;

    const int NST = K / 32;
#pragma unroll
    for (int i = 0; i < 4; i++) {
        CP_ASYNC16(sm_addr + dsto[i], Asrc[i]);
        CP_ASYNC16(sm_addr + TILE_W * 4 + dsto[i], Wsrc[i]);
    }
    CP_COMMIT();

    for (int s = 0; s < NST; s++) {
        CP_WAIT0();
        __syncthreads();
        if (s + 1 < NST) {
            const uint32_t boff = (uint32_t)((s + 1) & 1) * (2 * TILE_W * 4);
            const int ko = (s + 1) * 32;
#pragma unroll
            for (int i = 0; i < 4; i++) {
                CP_ASYNC16(sm_addr + boff + dsto[i], Asrc[i] + ko);
                CP_ASYNC16(sm_addr + boff + TILE_W * 4 + dsto[i], Wsrc[i] + ko);
            }
            CP_COMMIT();
        }

        const uint32_t* Abase = sm + (s & 1) * 2 * TILE_W + (wm * 64) * GP;
        const uint32_t* Bbase = sm + (s & 1) * 2 * TILE_W + TILE_W + (wn * 32) * GP;
#pragma unroll
        for (int kp = 0; kp < 2; kp++) {
            const int kc = (kp * 16 + tig * 4) ^ rpar16;   // swizzled load col
            uint4 bf[4];
#pragma unroll
            for (int ni = 0; ni < 4; ni++)
                bf[ni] = *(const uint4*)&Bbase[(ni * 8 + gr) * GP + kc];
#pragma unroll
            for (int mi = 0; mi < 4; mi++) {
                uint4 aL = *(const uint4*)&Abase[(mi * 16 + gr) * GP + kc];
                uint4 aH = *(const uint4*)&Abase[(mi * 16 + gr + 8) * GP + kc];
#pragma unroll
                for (int ni = 0; ni < 4; ni++) {
                    mma_tf32(acc[mi][ni], aL.x, aH.x, aL.y, aH.y, bf[ni].x, bf[ni].y);
                    mma_tf32(acc[mi][ni], aL.z, aH.z, aL.w, aH.w, bf[ni].z, bf[ni].w);
                }
            }
        }
    }

    // ---------------- Register epilogue ----------------
#pragma unroll
    for (int mi = 0; mi < 4; mi++) {
#pragma unroll
        for (int half = 0; half < 2; half++) {
            const int m = m0 + wm * 64 + mi * 16 + gr + half * 8;
            const int bb = m >> 11;
            const int t = m & (T_SEQ - 1);
#pragma unroll
            for (int ni = 0; ni < 4; ni++) {
                const int n = n0 + wn * 32 + ni * 8 + tig * 2;
                float v0 = acc[mi][ni][half * 2 + 0] + bias[n];
                float v1 = acc[mi][ni][half * 2 + 1] + bias[n + 1];
                if (mode == 1 || mode == 2) {
                    const int hh = (n & 63) >> 1;
                    const float c = cosT[t * (HD / 2) + hh];
                    const float ss = sinT[t * (HD / 2) + hh];
                    const float e = v0 * c - v1 * ss;
                    const float o = v0 * ss + v1 * c;
                    v0 = e;
                    v1 = o;
                }
                if (mode == 0) {
                    *(float2*)&outC[(size_t)m * DMODEL + n] = make_float2(v0, v1);
                } else if (mode == 1) {
                    *(float2*)&g_q[(((size_t)(bb * NH + (n >> 6))) * T_SEQ + t) * HD + (n & 63)] =
                        make_float2(v0, v1);
                } else {
                    const size_t idx =
                        (((size_t)(bb * NKV + (n >> 6))) * T_SEQ + t) * HD + (n & 63);
                    if (mode == 2) {
                        *(float2*)&kout[idx] = make_float2(v0, v1);
                        const int d = n & 63;
                        const int k0 = d & 15;
                        const int slot0 = ((k0 & 7) >> 1) * 4 + ((k0 >> 3) & 1) * 2;
                        const size_t base =
                            (((size_t)(bb * NKV + (n >> 6))) * T_SEQ + t) * HD +
                            (d & ~15) + slot0;
                        uint2 kq;
                        kq.x = f2tf32(v0);
                        kq.y = f2tf32(v1);
                        *(uint2*)&g_kc[base] = kq;
                    } else {
                        *(float2*)&vout[idx] = make_float2(v0, v1);
                    }
                }
            }
        }
    }
}

// ============================================================================
// Flash attention, tf32 mma.sync, 8 warps, warp tile 16x64.
// PERM16 global K/V + XOR16 smem swizzle, pitch = exact 64 words.
// Conflict-free LDS.128; cp.async double-buffered; heavy-first schedule.
// smem: 4 x 4096 words = 64 KB.
// ============================================================================
#define ATP 64
#define KVW (64 * ATP)   // 4096 words

__global__ __launch_bounds__(256, 2) void attn_mma()
{
    extern __shared__ __align__(16) uint32_t sm[];
    const uint32_t sm_addr = smem_u32(sm);

    const int tid = threadIdx.x;
    const int wid = tid >> 5;
    const int lane = tid & 31;
    const int gr = lane >> 2;
    const int tig = lane & 3;
    const int rpar16 = (gr & 1) << 4;

    const int qt = (gridDim.x - 1) - blockIdx.x;  // heavy-first
    const int bh = blockIdx.y;
    const int b = bh >> 5;
    const int h = bh & 31;
    const int bkv = (b * NKV) + (h >> 2);

    // Q fragments (registers): qa[ks] covers logical d = 8ks+2tig, +1
    const float* Qg = g_q + (((size_t)(b * NH + h)) * T_SEQ + qt * 128 + wid * 16) * HD;
    uint32_t qa[8][4];
#pragma unroll
    for (int ks = 0; ks < 8; ks++) {
        const int d0 = 8 * ks + 2 * tig;
        qa[ks][0] = f2tf32(Qg[gr * HD + d0] * 0.125f);
        qa[ks][1] = f2tf32(Qg[(gr + 8) * HD + d0] * 0.125f);
        qa[ks][2] = f2tf32(Qg[gr * HD + d0 + 1] * 0.125f);
        qa[ks][3] = f2tf32(Qg[(gr + 8) * HD + d0 + 1] * 0.125f);
    }

    const uint32_t* Kbase = g_kc + (size_t)bkv * T_SEQ * HD;
    const uint32_t* Vbase = g_vt + (size_t)bkv * HD * T_SEQ;

    float ctx[8][4];
#pragma unroll
    for (int ni = 0; ni < 8; ni++)
#pragma unroll
        for (int r = 0; r < 4; r++) ctx[ni][r] = 0.f;
    float mrun0 = -INFINITY, mrun1 = -INFINITY;
    float lrun0 = 0.f, lrun1 = 0.f;

    // loader: row = tid>>2 (0..63), 4 chunks at cols (tid&3)*4 + 16c (swizzled)
    const int lrow = tid >> 2;
    const int lc4 = (tid & 3) * 4;
    const int lpar16 = (lrow & 1) << 4;
    const int row0 = qt * 128 + wid * 16 + gr;
    const int row1 = row0 + 8;
    const int njt = 2 * qt + 2;

#pragma unroll
    for (int c = 0; c < 4; c++) {
        const int col = lc4 + c * 16;               // logical (global) col
        const int pcol = col ^ lpar16;              // swizzled smem col
        CP_ASYNC16(sm_addr + (lrow * ATP + pcol) * 4, Kbase + (size_t)lrow * HD + col);
        CP_ASYNC16(sm_addr + (2 * KVW + lrow * ATP + pcol) * 4,
                   Vbase + (size_t)lrow * T_SEQ + col);
    }
    CP_COMMIT();

    for (int jt = 0; jt < njt; jt++) {
        CP_WAIT0();
        __syncthreads();
        if (jt + 1 < njt) {
            const uint32_t boff = (uint32_t)((jt + 1) & 1) * KVW * 4;
            const int kt = (jt + 1) * 64;
#pragma unroll
            for (int c = 0; c < 4; c++) {
                const int col = lc4 + c * 16;
                const int pcol = col ^ lpar16;
                CP_ASYNC16(sm_addr + boff + (lrow * ATP + pcol) * 4,
                           Kbase + (size_t)(kt + lrow) * HD + col);
                CP_ASYNC16(sm_addr + 2 * KVW * 4 + boff + (lrow * ATP + pcol) * 4,
                           Vbase + (size_t)lrow * T_SEQ + kt + col);
            }
            CP_COMMIT();
        }

        if (jt == 2 * qt + 1 && wid < 4) continue;  // fully masked

        const uint32_t* Ks = sm + (jt & 1) * KVW;
        const uint32_t* Vt = sm + 2 * KVW + (jt & 1) * KVW;

        // ---- S = Q K^T ----
        float s[8][4];
#pragma unroll
        for (int ni = 0; ni < 8; ni++)
#pragma unroll
            for (int r = 0; r < 4; r++) s[ni][r] = 0.f;
#pragma unroll
        for (int kp = 0; kp < 4; kp++) {
            const int kc = (kp * 16 + tig * 4) ^ rpar16;
#pragma unroll
            for (int ni = 0; ni < 8; ni++) {
                uint4 bv = *(const uint4*)&Ks[(ni * 8 + gr) * ATP + kc];
                mma_tf32(s[ni], qa[2 * kp][0], qa[2 * kp][1], qa[2 * kp][2],
                         qa[2 * kp][3], bv.x, bv.y);
                mma_tf32(s[ni], qa[2 * kp + 1][0], qa[2 * kp + 1][1],
                         qa[2 * kp + 1][2], qa[2 * kp + 1][3], bv.z, bv.w);
            }
        }

        // ---- causal mask ----
        if (jt >= 2 * qt) {
            const int colb = jt * 64 + 2 * tig;
#pragma unroll
            for (int ni = 0; ni < 8; ni++) {
                const int c0 = colb + 8 * ni;
                if (c0 > row0) s[ni][0] = -INFINITY;
                if (c0 + 1 > row0) s[ni][1] = -INFINITY;
                if (c0 > row1) s[ni][2] = -INFINITY;
                if (c0 + 1 > row1) s[ni][3] = -INFINITY;
            }
        }

        // ---- online softmax ----
        float m0 = -INFINITY, m1 = -INFINITY;
#pragma unroll
        for (int ni = 0; ni < 8; ni++) {
            m0 = fmaxf(m0, fmaxf(s[ni][0], s[ni][1]));
            m1 = fmaxf(m1, fmaxf(s[ni][2], s[ni][3]));
        }
        m0 = fmaxf(m0, __shfl_xor_sync(0xffffffffu, m0, 1, 4));
        m0 = fmaxf(m0, __shfl_xor_sync(0xffffffffu, m0, 2, 4));
        m1 = fmaxf(m1, __shfl_xor_sync(0xffffffffu, m1, 1, 4));
        m1 = fmaxf(m1, __shfl_xor_sync(0xffffffffu, m1, 2, 4));
        const float mn0 = fmaxf(mrun0, m0);
        const float mn1 = fmaxf(mrun1, m1);
        const float al0 = __expf(mrun0 - mn0);
        const float al1 = __expf(mrun1 - mn1);
        float ls0 = 0.f, ls1 = 0.f;
        uint32_t pb[8][4];
#pragma unroll
        for (int ni = 0; ni < 8; ni++) {
            float p0 = __expf(s[ni][0] - mn0);
            float p1 = __expf(s[ni][1] - mn0);
            float p2 = __expf(s[ni][2] - mn1);
            float p3 = __expf(s[ni][3] - mn1);
            ls0 += p0 + p1;
            ls1 += p2 + p3;
            pb[ni][0] = f2tf32(p0);
            pb[ni][1] = f2tf32(p1);
            pb[ni][2] = f2tf32(p2);
            pb[ni][3] = f2tf32(p3);
            ctx[ni][0] *= al0;
            ctx[ni][1] *= al0;
            ctx[ni][2] *= al1;
            ctx[ni][3] *= al1;
        }
        ls0 += __shfl_xor_sync(0xffffffffu, ls0, 1, 4);
        ls0 += __shfl_xor_sync(0xffffffffu, ls0, 2, 4);
        ls1 += __shfl_xor_sync(0xffffffffu, ls1, 1, 4);
        ls1 += __shfl_xor_sync(0xffffffffu, ls1, 2, 4);
        mrun0 = mn0;
        mrun1 = mn1;
        lrun0 = lrun0 * al0 + ls0;
        lrun1 = lrun1 * al1 + ls1;

        // ---- ctx += P V ----
#pragma unroll
        for (int kp = 0; kp < 4; kp++) {
            const int kc = (kp * 16 + tig * 4) ^ rpar16;
#pragma unroll
            for (int ni = 0; ni < 8; ni++) {
                uint4 bv = *(const uint4*)&Vt[(ni * 8 + gr) * ATP + kc];
                mma_tf32(ctx[ni], pb[2 * kp][0], pb[2 * kp][2], pb[2 * kp][1],
                         pb[2 * kp][3], bv.x, bv.y);
                mma_tf32(ctx[ni], pb[2 * kp + 1][0], pb[2 * kp + 1][2],
                         pb[2 * kp + 1][1], pb[2 * kp + 1][3], bv.z, bv.w);
            }
        }
    }

    // ---- finalize: g_ctx tf32 PERM16 ----
    const float inv0 = 1.0f / lrun0;
    const float inv1 = 1.0f / lrun1;
    uint32_t* o0 = g_ctx + (((size_t)(b * T_SEQ + row0)) * NH + h) * HD;
    uint32_t* o1 = g_ctx + (((size_t)(b * T_SEQ + row1)) * NH + h) * HD;
#pragma unroll
    for (int ni = 0; ni < 8; ni++) {
        const int d = ni * 8 + 2 * tig;
        const int word = ((d >> 4) << 4) + tig * 4 + (ni & 1) * 2;  // PERM slot
        uint2 w0, w1;
        w0.x = f2tf32(ctx[ni][0] * inv0);
        w0.y = f2tf32(ctx[ni][1] * inv0);
        w1.x = f2tf32(ctx[ni][2] * inv1);
        w1.y = f2tf32(ctx[ni][3] * inv1);
        *(uint2*)&o0[word] = w0;
        *(uint2*)&o1[word] = w1;
    }
}

// ---------------------------------------------------------------------------
extern "C" void kernel_launch(void* const* d_in, const int* in_sizes, int n_in,
                              void* d_out, int out_size)
{
    const float* x    = (const float*)d_in[0];
    const float* cosT = (const float*)d_in[1];
    const float* sinT = (const float*)d_in[2];
    const float* wq   = (const float*)d_in[3];
    const float* bq   = (const float*)d_in[4];
    const float* wk   = (const float*)d_in[5];
    const float* bk   = (const float*)d_in[6];
    const float* wv   = (const float*)d_in[7];
    const float* bv   = (const float*)d_in[8];
    const float* wo   = (const float*)d_in[9];
    const float* bo   = (const float*)d_in[10];

    float* out  = (float*)d_out;            // (B, T, D)
    float* kout = out + (size_t)8388608;    // (B, KV, T, HD)
    float* vout = out + (size_t)10485760;   // (B, KV, T, HD)

    const int GEMM_SMEM = 4 * TILE_W * 4;   // 65536 B
    const int ATTN_SMEM = 4 * KVW * 4;      // 65536 B
    static bool attr_set = false;
    if (!attr_set) {
        cudaFuncSetAttribute(db_gemm<0>, cudaFuncAttributeMaxDynamicSharedMemorySize, GEMM_SMEM);
        cudaFuncSetAttribute(db_gemm<1>, cudaFuncAttributeMaxDynamicSharedMemorySize, GEMM_SMEM);
        cudaFuncSetAttribute(attn_mma, cudaFuncAttributeMaxDynamicSharedMemorySize, ATTN_SMEM);
        attr_set = true;
    }

    uint32_t* p_xt;  cudaGetSymbolAddress((void**)&p_xt, g_xt);
    uint32_t* p_wq;  cudaGetSymbolAddress((void**)&p_wq, g_wq);
    uint32_t* p_wk;  cudaGetSymbolAddress((void**)&p_wk, g_wk);
    uint32_t* p_wv;  cudaGetSymbolAddress((void**)&p_wv, g_wv);
    uint32_t* p_wo;  cudaGetSymbolAddress((void**)&p_wo, g_wo);
    uint32_t* p_vt;  cudaGetSymbolAddress((void**)&p_vt, g_vt);

    // Prep: fp32 -> tf32 (PERM16), one launch
    cvt_all<<<18432, 256>>>(x, wq, wk, wv, wo, p_xt, p_wq, p_wk, p_wv, p_wo);

    // Fused QKV projections (+RoPE for Q,K; K also written as PERM tf32 g_kc)
    db_gemm<0><<<dim3(24, 32), 256, GEMM_SMEM>>>(
        p_xt, bq, bk, bv, kout, vout, nullptr, cosT, sinT);

    // V -> transposed PERM tf32
    vtrans<<<dim3(32, 16), 256>>>(vout, p_vt);

    // Attention -> g_ctx (PERM tf32)
    attn_mma<<<dim3(T_SEQ / 128, 2 * NH), 256, ATTN_SMEM>>>();

    // Output projection -> out
    db_gemm<1><<<dim3(16, 32), 256, GEMM_SMEM>>>(
        nullptr, bo, nullptr, nullptr, nullptr, nullptr, out, nullptr, nullptr);
}

// round 11
// speedup vs baseline: 1.1488x; 1.0426x over previous
#include <cuda_runtime.h>
#include <cstdint>
#include <math.h>

#define T_SEQ 2048
#define DMODEL 2048
#define NH 32
#define NKV 8
#define HD 64

// ---------------- Scratch (device globals; allocation-free) ----------------
// g_kc / g_vt use the k16 permutation: within each 16-word k-block, logical
// k = b*8 + 2*tig + lo (b in {0,1}, tig 0..3, lo {0,1}) stored at slot
// tig*4 + b*2 + lo. Applied identically to both MMA operands -> bit-exact.
// All other tf32 globals are natural layout (consumed by uint64-pair loads).
__device__ float    g_q  [(size_t)2 * NH * T_SEQ * HD];   // fp32 Q (b,h,t,d)
__device__ uint32_t g_ctx[(size_t)2 * T_SEQ * NH * HD];   // tf32 ctx natural
__device__ uint32_t g_xt [(size_t)4096 * 2048];           // tf32 x natural
__device__ uint32_t g_wq [(size_t)2048 * 2048];
__device__ uint32_t g_wk [(size_t)512 * 2048];
__device__ uint32_t g_wv [(size_t)512 * 2048];
__device__ uint32_t g_wo [(size_t)2048 * 2048];
__device__ uint32_t g_kc [(size_t)2 * NKV * T_SEQ * HD];  // tf32 K PERM16(d)
__device__ uint32_t g_vt [(size_t)2 * NKV * HD * T_SEQ];  // tf32 V^T PERM16(t)

__device__ __forceinline__ uint32_t f2tf32(float f) {
    uint32_t u;
    asm("cvt.rna.tf32.f32 %0, %1;" : "=r"(u) : "f"(f));
    return u;
}

__device__ __forceinline__ void mma_tf32(float* c, uint32_t a0, uint32_t a1,
                                         uint32_t a2, uint32_t a3,
                                         uint32_t b0, uint32_t b1) {
    asm volatile(
        "mma.sync.aligned.m16n8k8.row.col.f32.tf32.tf32.f32 "
        "{%0,%1,%2,%3}, {%4,%5,%6,%7}, {%8,%9}, {%0,%1,%2,%3};"
        : "+f"(c[0]), "+f"(c[1]), "+f"(c[2]), "+f"(c[3])
        : "r"(a0), "r"(a1), "r"(a2), "r"(a3), "r"(b0), "r"(b1));
}

__device__ __forceinline__ uint32_t smem_u32(const void* p) {
    uint32_t a;
    asm("{ .reg .u64 t; cvta.to.shared.u64 t, %1; cvt.u32.u64 %0, t; }"
        : "=r"(a) : "l"(p));
    return a;
}
#define CP_ASYNC16(dst, src) \
    asm volatile("cp.async.ca.shared.global [%0], [%1], 16;" :: "r"(dst), "l"(src))
#define CP_COMMIT() asm volatile("cp.async.commit_group;" ::: "memory")
#define CP_WAIT0()  asm volatile("cp.async.wait_group 0;" ::: "memory")

// ============================================================================
// Prep: all fp32 -> tf32 (natural layout), one launch. (R7 version)
// ============================================================================
__global__ void cvt_all(const float* __restrict__ x,
                        const float* __restrict__ wq,
                        const float* __restrict__ wk,
                        const float* __restrict__ wv,
                        const float* __restrict__ wo,
                        uint32_t* __restrict__ xt,
                        uint32_t* __restrict__ wqt,
                        uint32_t* __restrict__ wkt,
                        uint32_t* __restrict__ wvt,
                        uint32_t* __restrict__ wot)
{
    int i = blockIdx.x * blockDim.x + threadIdx.x;
    const float* in;
    uint32_t* out;
    if (i < 2097152)        { in = x;  out = xt; }
    else if (i < 3145728)   { in = wq; out = wqt; i -= 2097152; }
    else if (i < 3407872)   { in = wk; out = wkt; i -= 3145728; }
    else if (i < 3670016)   { in = wv; out = wvt; i -= 3407872; }
    else                    { in = wo; out = wot; i -= 3670016; }
    float4 v = ((const float4*)in)[i];
    uint4 o;
    o.x = f2tf32(v.x); o.y = f2tf32(v.y); o.z = f2tf32(v.z); o.w = f2tf32(v.w);
    ((uint4*)out)[i] = o;
}

// ============================================================================
// Prep: V (b,kv,t,d) fp32 -> V^T (b,kv,d,t) tf32, key dim k16-PERMUTED. (R9)
// ============================================================================
__global__ void vtrans(const float* __restrict__ vin, uint32_t* __restrict__ vt)
{
    __shared__ uint32_t ts[64 * 65];
    const int tid = threadIdx.x;
    const int jt = blockIdx.x;
    const int bkv = blockIdx.y;

    const float* in = vin + ((size_t)bkv * T_SEQ + jt * 64) * HD;
#pragma unroll
    for (int p = 0; p < 4; p++) {
        const int lin = p * 256 + tid;
        const int t = lin >> 4;
        const int dq = (lin & 15) * 4;
        float4 v = *(const float4*)&in[t * HD + dq];
        ts[(dq + 0) * 65 + t] = f2tf32(v.x);
        ts[(dq + 1) * 65 + t] = f2tf32(v.y);
        ts[(dq + 2) * 65 + t] = f2tf32(v.z);
        ts[(dq + 3) * 65 + t] = f2tf32(v.w);
    }
    __syncthreads();
    uint32_t* out = vt + (size_t)bkv * HD * T_SEQ + jt * 64;
#pragma unroll
    for (int p = 0; p < 4; p++) {
        const int lin = p * 256 + tid;
        const int d = lin >> 4;
        const int cq = (lin & 15) * 4;
        const int blockbase = cq & ~15;
        const int k0 = cq & 15;
        const int slot0 = ((k0 & 7) >> 1) * 4 + ((k0 >> 3) & 1) * 2;
        uint2 lo, hi;
        lo.x = ts[d * 65 + cq + 0];
        lo.y = ts[d * 65 + cq + 1];
        hi.x = ts[d * 65 + cq + 2];
        hi.y = ts[d * 65 + cq + 3];
        *(uint2*)&out[(size_t)d * T_SEQ + blockbase + slot0] = lo;
        *(uint2*)&out[(size_t)d * T_SEQ + blockbase + slot0 + 4] = hi;
    }
}

// ============================================================================
// cp.async double-buffered tf32 GEMM — EXACT R7 config (fastest measured):
// 128x128 tile, BK=32, 8 warps (2x4), warp tile 64x32, SPAD 40,
// uint64-pair fragment loads on natural-layout operands.
// KIND 0: fused QKV. bx<16: Q+RoPE->g_q fp32; 16..19: K+RoPE->kout fp32 +
//         g_kc tf32 PERM16; 20..23: V->vout fp32.
// KIND 1: O projection: A=g_ctx (tf32 natural), C=out fp32.
// ============================================================================
#define SPAD 40
#define TILE_W (128 * SPAD)

template <int KIND>
__global__ __launch_bounds__(256, 2) void db_gemm(
    const uint32_t* __restrict__ xA,
    const float* __restrict__ bq, const float* __restrict__ bk,
    const float* __restrict__ bv,
    float* __restrict__ kout, float* __restrict__ vout,
    float* __restrict__ outC,
    const float* __restrict__ cosT, const float* __restrict__ sinT)
{
    extern __shared__ __align__(16) uint32_t sm[];
    const uint32_t sm_addr = smem_u32(sm);

    const int tid = threadIdx.x;
    const int wid = tid >> 5;
    const int lane = tid & 31;
    const int gr = lane >> 2;
    const int tig = lane & 3;
    const int wm = wid >> 2;
    const int wn = wid & 3;

    constexpr int K = DMODEL;
    const int m0 = blockIdx.y * 128;

    int mode, n0;
    const uint32_t* A;
    const uint32_t* W;
    const float* bias;
    if (KIND == 1) {
        mode = 0; n0 = blockIdx.x * 128; A = g_ctx; W = g_wo; bias = bq;
    } else {
        const int bx = blockIdx.x;
        A = xA;
        if (bx < 16)      { mode = 1; n0 = bx * 128;        W = g_wq; bias = bq; }
        else if (bx < 20) { mode = 2; n0 = (bx - 16) * 128; W = g_wk; bias = bk; }
        else              { mode = 3; n0 = (bx - 20) * 128; W = g_wv; bias = bv; }
    }

    const int rbase = tid >> 3;
    const int cg = tid & 7;
    const uint32_t* Asrc[4];
    const uint32_t* Wsrc[4];
    uint32_t dsto[4];
#pragma unroll
    for (int i = 0; i < 4; i++) {
        Asrc[i] = A + (size_t)(m0 + i * 32 + rbase) * K + cg * 4;
        Wsrc[i] = W + (size_t)(n0 + i * 32 + rbase) * K + cg * 4;
        dsto[i] = (uint32_t)(((i * 32 + rbase) * SPAD + cg * 4) * 4);
    }

    float acc[4][4][4];
#pragma unroll
    for (int mi = 0; mi < 4; mi++)
#pragma unroll
        for (int ni = 0; ni < 4; ni++)
#pragma unroll
            for (int r = 0; r < 4; r++) acc[mi][ni][r] = 0.f;

    const int NST = K / 32;
#pragma unroll
    for (int i = 0; i < 4; i++) {
        CP_ASYNC16(sm_addr + dsto[i], Asrc[i]);
        CP_ASYNC16(sm_addr + TILE_W * 4 + dsto[i], Wsrc[i]);
    }
    CP_COMMIT();

    for (int s = 0; s < NST; s++) {
        CP_WAIT0();
        __syncthreads();
        if (s + 1 < NST) {
            const uint32_t boff = (uint32_t)((s + 1) & 1) * (2 * TILE_W * 4);
            const int ko = (s + 1) * 32;
#pragma unroll
            for (int i = 0; i < 4; i++) {
                CP_ASYNC16(sm_addr + boff + dsto[i], Asrc[i] + ko);
                CP_ASYNC16(sm_addr + boff + TILE_W * 4 + dsto[i], Wsrc[i] + ko);
            }
            CP_COMMIT();
        }

        const uint32_t* Abase = sm + (s & 1) * 2 * TILE_W + (wm * 64) * SPAD;
        const uint32_t* Bbase = sm + (s & 1) * 2 * TILE_W + TILE_W + (wn * 32) * SPAD;
#pragma unroll
        for (int kk = 0; kk < 4; kk++) {
            const int kc = kk * 8 + 2 * tig;
            uint32_t bf[4][2];
#pragma unroll
            for (int ni = 0; ni < 4; ni++) {
                uint64_t bv = *(const uint64_t*)&Bbase[(ni * 8 + gr) * SPAD + kc];
                bf[ni][0] = (uint32_t)bv;
                bf[ni][1] = (uint32_t)(bv >> 32);
            }
#pragma unroll
            for (int mi = 0; mi < 4; mi++) {
                uint64_t a02 = *(const uint64_t*)&Abase[(mi * 16 + gr) * SPAD + kc];
                uint64_t a13 = *(const uint64_t*)&Abase[(mi * 16 + gr + 8) * SPAD + kc];
                uint32_t a0 = (uint32_t)a02, a2 = (uint32_t)(a02 >> 32);
                uint32_t a1 = (uint32_t)a13, a3 = (uint32_t)(a13 >> 32);
#pragma unroll
                for (int ni = 0; ni < 4; ni++)
                    mma_tf32(acc[mi][ni], a0, a1, a2, a3, bf[ni][0], bf[ni][1]);
            }
        }
    }

    // ---------------- Register epilogue ----------------
#pragma unroll
    for (int mi = 0; mi < 4; mi++) {
#pragma unroll
        for (int half = 0; half < 2; half++) {
            const int m = m0 + wm * 64 + mi * 16 + gr + half * 8;
            const int bb = m >> 11;
            const int t = m & (T_SEQ - 1);
#pragma unroll
            for (int ni = 0; ni < 4; ni++) {
                const int n = n0 + wn * 32 + ni * 8 + tig * 2;
                float v0 = acc[mi][ni][half * 2 + 0] + bias[n];
                float v1 = acc[mi][ni][half * 2 + 1] + bias[n + 1];
                if (mode == 1 || mode == 2) {
                    const int hh = (n & 63) >> 1;
                    const float c = cosT[t * (HD / 2) + hh];
                    const float ss = sinT[t * (HD / 2) + hh];
                    const float e = v0 * c - v1 * ss;
                    const float o = v0 * ss + v1 * c;
                    v0 = e;
                    v1 = o;
                }
                if (mode == 0) {
                    *(float2*)&outC[(size_t)m * DMODEL + n] = make_float2(v0, v1);
                } else if (mode == 1) {
                    *(float2*)&g_q[(((size_t)(bb * NH + (n >> 6))) * T_SEQ + t) * HD + (n & 63)] =
                        make_float2(v0, v1);
                } else {
                    const size_t idx =
                        (((size_t)(bb * NKV + (n >> 6))) * T_SEQ + t) * HD + (n & 63);
                    if (mode == 2) {
                        *(float2*)&kout[idx] = make_float2(v0, v1);
                        // PERM16 tf32 K for attention LDS.128 path
                        const int d = n & 63;
                        const int k0 = d & 15;
                        const int slot0 = ((k0 & 7) >> 1) * 4 + ((k0 >> 3) & 1) * 2;
                        const size_t base =
                            (((size_t)(bb * NKV + (n >> 6))) * T_SEQ + t) * HD +
                            (d & ~15) + slot0;
                        uint2 kq;
                        kq.x = f2tf32(v0);
                        kq.y = f2tf32(v1);
                        *(uint2*)&g_kc[base] = kq;
                    } else {
                        *(float2*)&vout[idx] = make_float2(v0, v1);
                    }
                }
            }
        }
    }
}

// ============================================================================
// Flash attention — EXACT R9 config (fastest measured: 317us):
// 8 warps, warp tile 16x64, PERM16 K/V globals, LDS.128 frags, pitch 80,
// cp.async double-buffered, heavy-first schedule.
// Finalize writes NATURAL tf32 g_ctx (consumed by R7-style O-GEMM).
// ============================================================================
#define ATP 80
#define KVW (64 * ATP)   // 5120 words

__global__ __launch_bounds__(256, 2) void attn_mma()
{
    extern __shared__ __align__(16) uint32_t sm[];
    const uint32_t sm_addr = smem_u32(sm);

    const int tid = threadIdx.x;
    const int wid = tid >> 5;
    const int lane = tid & 31;
    const int gr = lane >> 2;
    const int tig = lane & 3;

    const int qt = (gridDim.x - 1) - blockIdx.x;  // heavy-first
    const int bh = blockIdx.y;
    const int b = bh >> 5;
    const int h = bh & 31;
    const int bkv = (b * NKV) + (h >> 2);

    // Q fragments (registers, natural): qa[ks] covers d = 8ks+2tig, +1
    const float* Qg = g_q + (((size_t)(b * NH + h)) * T_SEQ + qt * 128 + wid * 16) * HD;
    uint32_t qa[8][4];
#pragma unroll
    for (int ks = 0; ks < 8; ks++) {
        const int d0 = 8 * ks + 2 * tig;
        qa[ks][0] = f2tf32(Qg[gr * HD + d0] * 0.125f);
        qa[ks][1] = f2tf32(Qg[(gr + 8) * HD + d0] * 0.125f);
        qa[ks][2] = f2tf32(Qg[gr * HD + d0 + 1] * 0.125f);
        qa[ks][3] = f2tf32(Qg[(gr + 8) * HD + d0 + 1] * 0.125f);
    }

    const uint32_t* Kbase = g_kc + (size_t)bkv * T_SEQ * HD;
    const uint32_t* Vbase = g_vt + (size_t)bkv * HD * T_SEQ;

    float ctx[8][4];
#pragma unroll
    for (int ni = 0; ni < 8; ni++)
#pragma unroll
        for (int r = 0; r < 4; r++) ctx[ni][r] = 0.f;
    float mrun0 = -INFINITY, mrun1 = -INFINITY;
    float lrun0 = 0.f, lrun1 = 0.f;

    const int lrow = tid >> 2;
    const int lcol = (tid & 3) * 16;
    const int row0 = qt * 128 + wid * 16 + gr;
    const int row1 = row0 + 8;
    const int njt = 2 * qt + 2;

#pragma unroll
    for (int c = 0; c < 4; c++) {
        const int col = lcol + 4 * c;
        CP_ASYNC16(sm_addr + (lrow * ATP + col) * 4, Kbase + (size_t)lrow * HD + col);
        CP_ASYNC16(sm_addr + (2 * KVW + lrow * ATP + col) * 4,
                   Vbase + (size_t)lrow * T_SEQ + col);
    }
    CP_COMMIT();

    for (int jt = 0; jt < njt; jt++) {
        CP_WAIT0();
        __syncthreads();
        if (jt + 1 < njt) {
            const uint32_t boff = (uint32_t)((jt + 1) & 1) * KVW * 4;
            const int kt = (jt + 1) * 64;
#pragma unroll
            for (int c = 0; c < 4; c++) {
                const int col = lcol + 4 * c;
                CP_ASYNC16(sm_addr + boff + (lrow * ATP + col) * 4,
                           Kbase + (size_t)(kt + lrow) * HD + col);
                CP_ASYNC16(sm_addr + 2 * KVW * 4 + boff + (lrow * ATP + col) * 4,
                           Vbase + (size_t)lrow * T_SEQ + kt + col);
            }
            CP_COMMIT();
        }

        if (jt == 2 * qt + 1 && wid < 4) continue;  // fully masked

        const uint32_t* Ks = sm + (jt & 1) * KVW;
        const uint32_t* Vt = sm + 2 * KVW + (jt & 1) * KVW;

        // ---- S = Q K^T ----
        float s[8][4];
#pragma unroll
        for (int ni = 0; ni < 8; ni++)
#pragma unroll
            for (int r = 0; r < 4; r++) s[ni][r] = 0.f;
#pragma unroll
        for (int kp = 0; kp < 4; kp++) {
            const int kc = kp * 16 + tig * 4;
#pragma unroll
            for (int ni = 0; ni < 8; ni++) {
                uint4 bv = *(const uint4*)&Ks[(ni * 8 + gr) * ATP + kc];
                mma_tf32(s[ni], qa[2 * kp][0], qa[2 * kp][1], qa[2 * kp][2],
                         qa[2 * kp][3], bv.x, bv.y);
                mma_tf32(s[ni], qa[2 * kp + 1][0], qa[2 * kp + 1][1],
                         qa[2 * kp + 1][2], qa[2 * kp + 1][3], bv.z, bv.w);
            }
        }

        // ---- causal mask ----
        if (jt >= 2 * qt) {
            const int colb = jt * 64 + 2 * tig;
#pragma unroll
            for (int ni = 0; ni < 8; ni++) {
                const int c0 = colb + 8 * ni;
                if (c0 > row0) s[ni][0] = -INFINITY;
                if (c0 + 1 > row0) s[ni][1] = -INFINITY;
                if (c0 > row1) s[ni][2] = -INFINITY;
                if (c0 + 1 > row1) s[ni][3] = -INFINITY;
            }
        }

        // ---- online softmax ----
        float m0 = -INFINITY, m1 = -INFINITY;
#pragma unroll
        for (int ni = 0; ni < 8; ni++) {
            m0 = fmaxf(m0, fmaxf(s[ni][0], s[ni][1]));
            m1 = fmaxf(m1, fmaxf(s[ni][2], s[ni][3]));
        }
        m0 = fmaxf(m0, __shfl_xor_sync(0xffffffffu, m0, 1, 4));
        m0 = fmaxf(m0, __shfl_xor_sync(0xffffffffu, m0, 2, 4));
        m1 = fmaxf(m1, __shfl_xor_sync(0xffffffffu, m1, 1, 4));
        m1 = fmaxf(m1, __shfl_xor_sync(0xffffffffu, m1, 2, 4));
        const float mn0 = fmaxf(mrun0, m0);
        const float mn1 = fmaxf(mrun1, m1);
        const float al0 = __expf(mrun0 - mn0);
        const float al1 = __expf(mrun1 - mn1);
        float ls0 = 0.f, ls1 = 0.f;
        uint32_t pb[8][4];
#pragma unroll
        for (int ni = 0; ni < 8; ni++) {
            float p0 = __expf(s[ni][0] - mn0);
            float p1 = __expf(s[ni][1] - mn0);
            float p2 = __expf(s[ni][2] - mn1);
            float p3 = __expf(s[ni][3] - mn1);
            ls0 += p0 + p1;
            ls1 += p2 + p3;
            pb[ni][0] = f2tf32(p0);
            pb[ni][1] = f2tf32(p1);
            pb[ni][2] = f2tf32(p2);
            pb[ni][3] = f2tf32(p3);
            ctx[ni][0] *= al0;
            ctx[ni][1] *= al0;
            ctx[ni][2] *= al1;
            ctx[ni][3] *= al1;
        }
        ls0 += __shfl_xor_sync(0xffffffffu, ls0, 1, 4);
        ls0 += __shfl_xor_sync(0xffffffffu, ls0, 2, 4);
        ls1 += __shfl_xor_sync(0xffffffffu, ls1, 1, 4);
        ls1 += __shfl_xor_sync(0xffffffffu, ls1, 2, 4);
        mrun0 = mn0;
        mrun1 = mn1;
        lrun0 = lrun0 * al0 + ls0;
        lrun1 = lrun1 * al1 + ls1;

        // ---- ctx += P V ----
#pragma unroll
        for (int kp = 0; kp < 4; kp++) {
            const int kc = kp * 16 + tig * 4;
#pragma unroll
            for (int ni = 0; ni < 8; ni++) {
                uint4 bv = *(const uint4*)&Vt[(ni * 8 + gr) * ATP + kc];
                mma_tf32(ctx[ni], pb[2 * kp][0], pb[2 * kp][2], pb[2 * kp][1],
                         pb[2 * kp][3], bv.x, bv.y);
                mma_tf32(ctx[ni], pb[2 * kp + 1][0], pb[2 * kp + 1][2],
                         pb[2 * kp + 1][1], pb[2 * kp + 1][3], bv.z, bv.w);
            }
        }
    }

    // ---- finalize: g_ctx tf32 NATURAL layout (for R7-style O-GEMM) ----
    const float inv0 = 1.0f / lrun0;
    const float inv1 = 1.0f / lrun1;
    uint32_t* o0 = g_ctx + (((size_t)(b * T_SEQ + row0)) * NH + h) * HD;
    uint32_t* o1 = g_ctx + (((size_t)(b * T_SEQ + row1)) * NH + h) * HD;
#pragma unroll
    for (int ni = 0; ni < 8; ni++) {
        const int d = ni * 8 + 2 * tig;
        uint2 w0, w1;
        w0.x = f2tf32(ctx[ni][0] * inv0);
        w0.y = f2tf32(ctx[ni][1] * inv0);
        w1.x = f2tf32(ctx[ni][2] * inv1);
        w1.y = f2tf32(ctx[ni][3] * inv1);
        *(uint2*)&o0[d] = w0;
        *(uint2*)&o1[d] = w1;
    }
}

// ---------------------------------------------------------------------------
extern "C" void kernel_launch(void* const* d_in, const int* in_sizes, int n_in,
                              void* d_out, int out_size)
{
    const float* x    = (const float*)d_in[0];
    const float* cosT = (const float*)d_in[1];
    const float* sinT = (const float*)d_in[2];
    const float* wq   = (const float*)d_in[3];
    const float* bq   = (const float*)d_in[4];
    const float* wk   = (const float*)d_in[5];
    const float* bk   = (const float*)d_in[6];
    const float* wv   = (const float*)d_in[7];
    const float* bv   = (const float*)d_in[8];
    const float* wo   = (const float*)d_in[9];
    const float* bo   = (const float*)d_in[10];

    float* out  = (float*)d_out;            // (B, T, D)
    float* kout = out + (size_t)8388608;    // (B, KV, T, HD)
    float* vout = out + (size_t)10485760;   // (B, KV, T, HD)

    const int GEMM_SMEM = 4 * TILE_W * 4;   // 81920 B
    const int ATTN_SMEM = 4 * KVW * 4;      // 81920 B
    static bool attr_set = false;
    if (!attr_set) {
        cudaFuncSetAttribute(db_gemm<0>, cudaFuncAttributeMaxDynamicSharedMemorySize, GEMM_SMEM);
        cudaFuncSetAttribute(db_gemm<1>, cudaFuncAttributeMaxDynamicSharedMemorySize, GEMM_SMEM);
        cudaFuncSetAttribute(attn_mma, cudaFuncAttributeMaxDynamicSharedMemorySize, ATTN_SMEM);
        attr_set = true;
    }

    uint32_t* p_xt;  cudaGetSymbolAddress((void**)&p_xt, g_xt);
    uint32_t* p_wq;  cudaGetSymbolAddress((void**)&p_wq, g_wq);
    uint32_t* p_wk;  cudaGetSymbolAddress((void**)&p_wk, g_wk);
    uint32_t* p_wv;  cudaGetSymbolAddress((void**)&p_wv, g_wv);
    uint32_t* p_wo;  cudaGetSymbolAddress((void**)&p_wo, g_wo);
    uint32_t* p_vt;  cudaGetSymbolAddress((void**)&p_vt, g_vt);

    // Prep: fp32 -> tf32 (natural), one launch
    cvt_all<<<18432, 256>>>(x, wq, wk, wv, wo, p_xt, p_wq, p_wk, p_wv, p_wo);

    // Fused QKV projections (+RoPE for Q,K; K also written as PERM16 tf32)
    db_gemm<0><<<dim3(24, 32), 256, GEMM_SMEM>>>(
        p_xt, bq, bk, bv, kout, vout, nullptr, cosT, sinT);

    // V -> transposed PERM16 tf32
    vtrans<<<dim3(32, 16), 256>>>(vout, p_vt);

    // Attention -> g_ctx (natural tf32)
    attn_mma<<<dim3(T_SEQ / 128, 2 * NH), 256, ATTN_SMEM>>>();

    // Output projection -> out
    db_gemm<1><<<dim3(16, 32), 256, GEMM_SMEM>>>(
        nullptr, bo, nullptr, nullptr, nullptr, nullptr, out, nullptr, nullptr);
}

// round 12
// speedup vs baseline: 1.1644x; 1.0135x over previous
#include <cuda_runtime.h>
#include <cstdint>
#include <math.h>

#define T_SEQ 2048
#define DMODEL 2048
#define NH 32
#define NKV 8
#define HD 64

// ---------------- Scratch (device globals; allocation-free) ----------------
// g_kc / g_vt use the k16 permutation: within each 16-word k-block, logical
// k = b*8 + 2*tig + lo (b in {0,1}, tig 0..3, lo {0,1}) stored at slot
// tig*4 + b*2 + lo. Applied identically to both MMA operands -> bit-exact.
// All other tf32 globals are natural layout (consumed by uint64-pair loads).
__device__ float    g_q  [(size_t)2 * NH * T_SEQ * HD];   // fp32 Q (b,h,t,d)
__device__ uint32_t g_ctx[(size_t)2 * T_SEQ * NH * HD];   // tf32 ctx natural
__device__ uint32_t g_xt [(size_t)4096 * 2048];           // tf32 x natural
__device__ uint32_t g_wq [(size_t)2048 * 2048];
__device__ uint32_t g_wk [(size_t)512 * 2048];
__device__ uint32_t g_wv [(size_t)512 * 2048];
__device__ uint32_t g_wo [(size_t)2048 * 2048];
__device__ uint32_t g_kc [(size_t)2 * NKV * T_SEQ * HD];  // tf32 K PERM16(d)
__device__ uint32_t g_vt [(size_t)2 * NKV * HD * T_SEQ];  // tf32 V^T PERM16(t)

__device__ __forceinline__ uint32_t f2tf32(float f) {
    uint32_t u;
    asm("cvt.rna.tf32.f32 %0, %1;" : "=r"(u) : "f"(f));
    return u;
}

__device__ __forceinline__ void mma_tf32(float* c, uint32_t a0, uint32_t a1,
                                         uint32_t a2, uint32_t a3,
                                         uint32_t b0, uint32_t b1) {
    asm volatile(
        "mma.sync.aligned.m16n8k8.row.col.f32.tf32.tf32.f32 "
        "{%0,%1,%2,%3}, {%4,%5,%6,%7}, {%8,%9}, {%0,%1,%2,%3};"
        : "+f"(c[0]), "+f"(c[1]), "+f"(c[2]), "+f"(c[3])
        : "r"(a0), "r"(a1), "r"(a2), "r"(a3), "r"(b0), "r"(b1));
}

__device__ __forceinline__ uint32_t smem_u32(const void* p) {
    uint32_t a;
    asm("{ .reg .u64 t; cvta.to.shared.u64 t, %1; cvt.u32.u64 %0, t; }"
        : "=r"(a) : "l"(p));
    return a;
}
// L2-only fills: tile data has no L1 reuse; keep the L1 port free for LDS.
#define CP_ASYNC16(dst, src) \
    asm volatile("cp.async.cg.shared.global [%0], [%1], 16;" :: "r"(dst), "l"(src))
#define CP_COMMIT() asm volatile("cp.async.commit_group;" ::: "memory")
#define CP_WAIT0()  asm volatile("cp.async.wait_group 0;" ::: "memory")

// ============================================================================
// Prep: all fp32 -> tf32 (natural layout), one launch.
// ============================================================================
__global__ void cvt_all(const float* __restrict__ x,
                        const float* __restrict__ wq,
                        const float* __restrict__ wk,
                        const float* __restrict__ wv,
                        const float* __restrict__ wo,
                        uint32_t* __restrict__ xt,
                        uint32_t* __restrict__ wqt,
                        uint32_t* __restrict__ wkt,
                        uint32_t* __restrict__ wvt,
                        uint32_t* __restrict__ wot)
{
    int i = blockIdx.x * blockDim.x + threadIdx.x;
    const float* in;
    uint32_t* out;
    if (i < 2097152)        { in = x;  out = xt; }
    else if (i < 3145728)   { in = wq; out = wqt; i -= 2097152; }
    else if (i < 3407872)   { in = wk; out = wkt; i -= 3145728; }
    else if (i < 3670016)   { in = wv; out = wvt; i -= 3407872; }
    else                    { in = wo; out = wot; i -= 3670016; }
    float4 v = ((const float4*)in)[i];
    uint4 o;
    o.x = f2tf32(v.x); o.y = f2tf32(v.y); o.z = f2tf32(v.z); o.w = f2tf32(v.w);
    ((uint4*)out)[i] = o;
}

// ============================================================================
// Prep: V (b,kv,t,d) fp32 -> V^T (b,kv,d,t) tf32, key dim k16-PERMUTED.
// ============================================================================
__global__ void vtrans(const float* __restrict__ vin, uint32_t* __restrict__ vt)
{
    __shared__ uint32_t ts[64 * 65];
    const int tid = threadIdx.x;
    const int jt = blockIdx.x;
    const int bkv = blockIdx.y;

    const float* in = vin + ((size_t)bkv * T_SEQ + jt * 64) * HD;
#pragma unroll
    for (int p = 0; p < 4; p++) {
        const int lin = p * 256 + tid;
        const int t = lin >> 4;
        const int dq = (lin & 15) * 4;
        float4 v = *(const float4*)&in[t * HD + dq];
        ts[(dq + 0) * 65 + t] = f2tf32(v.x);
        ts[(dq + 1) * 65 + t] = f2tf32(v.y);
        ts[(dq + 2) * 65 + t] = f2tf32(v.z);
        ts[(dq + 3) * 65 + t] = f2tf32(v.w);
    }
    __syncthreads();
    uint32_t* out = vt + (size_t)bkv * HD * T_SEQ + jt * 64;
#pragma unroll
    for (int p = 0; p < 4; p++) {
        const int lin = p * 256 + tid;
        const int d = lin >> 4;
        const int cq = (lin & 15) * 4;
        const int blockbase = cq & ~15;
        const int k0 = cq & 15;
        const int slot0 = ((k0 & 7) >> 1) * 4 + ((k0 >> 3) & 1) * 2;
        uint2 lo, hi;
        lo.x = ts[d * 65 + cq + 0];
        lo.y = ts[d * 65 + cq + 1];
        hi.x = ts[d * 65 + cq + 2];
        hi.y = ts[d * 65 + cq + 3];
        *(uint2*)&out[(size_t)d * T_SEQ + blockbase + slot0] = lo;
        *(uint2*)&out[(size_t)d * T_SEQ + blockbase + slot0 + 4] = hi;
    }
}

// ============================================================================
// cp.async double-buffered tf32 GEMM — R7/R11 config (fastest measured):
// 128x128 tile, BK=32, 8 warps (2x4), warp tile 64x32, SPAD 40,
// uint64-pair fragment loads on natural-layout operands.
// KIND 0: fused QKV. bx<16: Q+RoPE->g_q fp32; 16..19: K+RoPE->kout fp32 +
//         g_kc tf32 PERM16; 20..23: V->vout fp32.
// KIND 1: O projection: A=g_ctx (tf32 natural), C=out fp32.
// ============================================================================
#define SPAD 40
#define TILE_W (128 * SPAD)

template <int KIND>
__global__ __launch_bounds__(256, 2) void db_gemm(
    const uint32_t* __restrict__ xA,
    const float* __restrict__ bq, const float* __restrict__ bk,
    const float* __restrict__ bv,
    float* __restrict__ kout, float* __restrict__ vout,
    float* __restrict__ outC,
    const float* __restrict__ cosT, const float* __restrict__ sinT)
{
    extern __shared__ __align__(16) uint32_t sm[];
    const uint32_t sm_addr = smem_u32(sm);

    const int tid = threadIdx.x;
    const int wid = tid >> 5;
    const int lane = tid & 31;
    const int gr = lane >> 2;
    const int tig = lane & 3;
    const int wm = wid >> 2;
    const int wn = wid & 3;

    constexpr int K = DMODEL;
    const int m0 = blockIdx.y * 128;

    int mode, n0;
    const uint32_t* A;
    const uint32_t* W;
    const float* bias;
    if (KIND == 1) {
        mode = 0; n0 = blockIdx.x * 128; A = g_ctx; W = g_wo; bias = bq;
    } else {
        const int bx = blockIdx.x;
        A = xA;
        if (bx < 16)      { mode = 1; n0 = bx * 128;        W = g_wq; bias = bq; }
        else if (bx < 20) { mode = 2; n0 = (bx - 16) * 128; W = g_wk; bias = bk; }
        else              { mode = 3; n0 = (bx - 20) * 128; W = g_wv; bias = bv; }
    }

    const int rbase = tid >> 3;
    const int cg = tid & 7;
    const uint32_t* Asrc[4];
    const uint32_t* Wsrc[4];
    uint32_t dsto[4];
#pragma unroll
    for (int i = 0; i < 4; i++) {
        Asrc[i] = A + (size_t)(m0 + i * 32 + rbase) * K + cg * 4;
        Wsrc[i] = W + (size_t)(n0 + i * 32 + rbase) * K + cg * 4;
        dsto[i] = (uint32_t)(((i * 32 + rbase) * SPAD + cg * 4) * 4);
    }

    float acc[4][4][4];
#pragma unroll
    for (int mi = 0; mi < 4; mi++)
#pragma unroll
        for (int ni = 0; ni < 4; ni++)
#pragma unroll
            for (int r = 0; r < 4; r++) acc[mi][ni][r] = 0.f;

    const int NST = K / 32;
#pragma unroll
    for (int i = 0; i < 4; i++) {
        CP_ASYNC16(sm_addr + dsto[i], Asrc[i]);
        CP_ASYNC16(sm_addr + TILE_W * 4 + dsto[i], Wsrc[i]);
    }
    CP_COMMIT();

    for (int s = 0; s < NST; s++) {
        CP_WAIT0();
        __syncthreads();
        if (s + 1 < NST) {
            const uint32_t boff = (uint32_t)((s + 1) & 1) * (2 * TILE_W * 4);
            const int ko = (s + 1) * 32;
#pragma unroll
            for (int i = 0; i < 4; i++) {
                CP_ASYNC16(sm_addr + boff + dsto[i], Asrc[i] + ko);
                CP_ASYNC16(sm_addr + boff + TILE_W * 4 + dsto[i], Wsrc[i] + ko);
            }
            CP_COMMIT();
        }

        const uint32_t* Abase = sm + (s & 1) * 2 * TILE_W + (wm * 64) * SPAD;
        const uint32_t* Bbase = sm + (s & 1) * 2 * TILE_W + TILE_W + (wn * 32) * SPAD;
#pragma unroll
        for (int kk = 0; kk < 4; kk++) {
            const int kc = kk * 8 + 2 * tig;
            uint32_t bf[4][2];
#pragma unroll
            for (int ni = 0; ni < 4; ni++) {
                uint64_t bv = *(const uint64_t*)&Bbase[(ni * 8 + gr) * SPAD + kc];
                bf[ni][0] = (uint32_t)bv;
                bf[ni][1] = (uint32_t)(bv >> 32);
            }
#pragma unroll
            for (int mi = 0; mi < 4; mi++) {
                uint64_t a02 = *(const uint64_t*)&Abase[(mi * 16 + gr) * SPAD + kc];
                uint64_t a13 = *(const uint64_t*)&Abase[(mi * 16 + gr + 8) * SPAD + kc];
                uint32_t a0 = (uint32_t)a02, a2 = (uint32_t)(a02 >> 32);
                uint32_t a1 = (uint32_t)a13, a3 = (uint32_t)(a13 >> 32);
#pragma unroll
                for (int ni = 0; ni < 4; ni++)
                    mma_tf32(acc[mi][ni], a0, a1, a2, a3, bf[ni][0], bf[ni][1]);
            }
        }
    }

    // ---------------- Register epilogue ----------------
#pragma unroll
    for (int mi = 0; mi < 4; mi++) {
#pragma unroll
        for (int half = 0; half < 2; half++) {
            const int m = m0 + wm * 64 + mi * 16 + gr + half * 8;
            const int bb = m >> 11;
            const int t = m & (T_SEQ - 1);
#pragma unroll
            for (int ni = 0; ni < 4; ni++) {
                const int n = n0 + wn * 32 + ni * 8 + tig * 2;
                float v0 = acc[mi][ni][half * 2 + 0] + bias[n];
                float v1 = acc[mi][ni][half * 2 + 1] + bias[n + 1];
                if (mode == 1 || mode == 2) {
                    const int hh = (n & 63) >> 1;
                    const float c = cosT[t * (HD / 2) + hh];
                    const float ss = sinT[t * (HD / 2) + hh];
                    const float e = v0 * c - v1 * ss;
                    const float o = v0 * ss + v1 * c;
                    v0 = e;
                    v1 = o;
                }
                if (mode == 0) {
                    *(float2*)&outC[(size_t)m * DMODEL + n] = make_float2(v0, v1);
                } else if (mode == 1) {
                    *(float2*)&g_q[(((size_t)(bb * NH + (n >> 6))) * T_SEQ + t) * HD + (n & 63)] =
                        make_float2(v0, v1);
                } else {
                    const size_t idx =
                        (((size_t)(bb * NKV + (n >> 6))) * T_SEQ + t) * HD + (n & 63);
                    if (mode == 2) {
                        *(float2*)&kout[idx] = make_float2(v0, v1);
                        // PERM16 tf32 K for attention LDS.128 path
                        const int d = n & 63;
                        const int k0 = d & 15;
                        const int slot0 = ((k0 & 7) >> 1) * 4 + ((k0 >> 3) & 1) * 2;
                        const size_t base =
                            (((size_t)(bb * NKV + (n >> 6))) * T_SEQ + t) * HD +
                            (d & ~15) + slot0;
                        uint2 kq;
                        kq.x = f2tf32(v0);
                        kq.y = f2tf32(v1);
                        *(uint2*)&g_kc[base] = kq;
                    } else {
                        *(float2*)&vout[idx] = make_float2(v0, v1);
                    }
                }
            }
        }
    }
}

// ============================================================================
// Flash attention — R9/R11 config (fastest measured):
// 8 warps, warp tile 16x64, PERM16 K/V globals, LDS.128 frags, pitch 80,
// cp.async.cg double-buffered, heavy-first schedule.
// ============================================================================
#define ATP 80
#define KVW (64 * ATP)   // 5120 words

__global__ __launch_bounds__(256, 2) void attn_mma()
{
    extern __shared__ __align__(16) uint32_t sm[];
    const uint32_t sm_addr = smem_u32(sm);

    const int tid = threadIdx.x;
    const int wid = tid >> 5;
    const int lane = tid & 31;
    const int gr = lane >> 2;
    const int tig = lane & 3;

    const int qt = (gridDim.x - 1) - blockIdx.x;  // heavy-first
    const int bh = blockIdx.y;
    const int b = bh >> 5;
    const int h = bh & 31;
    const int bkv = (b * NKV) + (h >> 2);

    // Q fragments (registers, natural): qa[ks] covers d = 8ks+2tig, +1
    const float* Qg = g_q + (((size_t)(b * NH + h)) * T_SEQ + qt * 128 + wid * 16) * HD;
    uint32_t qa[8][4];
#pragma unroll
    for (int ks = 0; ks < 8; ks++) {
        const int d0 = 8 * ks + 2 * tig;
        qa[ks][0] = f2tf32(Qg[gr * HD + d0] * 0.125f);
        qa[ks][1] = f2tf32(Qg[(gr + 8) * HD + d0] * 0.125f);
        qa[ks][2] = f2tf32(Qg[gr * HD + d0 + 1] * 0.125f);
        qa[ks][3] = f2tf32(Qg[(gr + 8) * HD + d0 + 1] * 0.125f);
    }

    const uint32_t* Kbase = g_kc + (size_t)bkv * T_SEQ * HD;
    const uint32_t* Vbase = g_vt + (size_t)bkv * HD * T_SEQ;

    float ctx[8][4];
#pragma unroll
    for (int ni = 0; ni < 8; ni++)
#pragma unroll
        for (int r = 0; r < 4; r++) ctx[ni][r] = 0.f;
    float mrun0 = -INFINITY, mrun1 = -INFINITY;
    float lrun0 = 0.f, lrun1 = 0.f;

    const int lrow = tid >> 2;
    const int lcol = (tid & 3) * 16;
    const int row0 = qt * 128 + wid * 16 + gr;
    const int row1 = row0 + 8;
    const int njt = 2 * qt + 2;

#pragma unroll
    for (int c = 0; c < 4; c++) {
        const int col = lcol + 4 * c;
        CP_ASYNC16(sm_addr + (lrow * ATP + col) * 4, Kbase + (size_t)lrow * HD + col);
        CP_ASYNC16(sm_addr + (2 * KVW + lrow * ATP + col) * 4,
                   Vbase + (size_t)lrow * T_SEQ + col);
    }
    CP_COMMIT();

    for (int jt = 0; jt < njt; jt++) {
        CP_WAIT0();
        __syncthreads();
        if (jt + 1 < njt) {
            const uint32_t boff = (uint32_t)((jt + 1) & 1) * KVW * 4;
            const int kt = (jt + 1) * 64;
#pragma unroll
            for (int c = 0; c < 4; c++) {
                const int col = lcol + 4 * c;
                CP_ASYNC16(sm_addr + boff + (lrow * ATP + col) * 4,
                           Kbase + (size_t)(kt + lrow) * HD + col);
                CP_ASYNC16(sm_addr + 2 * KVW * 4 + boff + (lrow * ATP + col) * 4,
                           Vbase + (size_t)lrow * T_SEQ + kt + col);
            }
            CP_COMMIT();
        }

        if (jt == 2 * qt + 1 && wid < 4) continue;  // fully masked

        const uint32_t* Ks = sm + (jt & 1) * KVW;
        const uint32_t* Vt = sm + 2 * KVW + (jt & 1) * KVW;

        // ---- S = Q K^T ----
        float s[8][4];
#pragma unroll
        for (int ni = 0; ni < 8; ni++)
#pragma unroll
            for (int r = 0; r < 4; r++) s[ni][r] = 0.f;
#pragma unroll
        for (int kp = 0; kp < 4; kp++) {
            const int kc = kp * 16 + tig * 4;
#pragma unroll
            for (int ni = 0; ni < 8; ni++) {
                uint4 bv = *(const uint4*)&Ks[(ni * 8 + gr) * ATP + kc];
                mma_tf32(s[ni], qa[2 * kp][0], qa[2 * kp][1], qa[2 * kp][2],
                         qa[2 * kp][3], bv.x, bv.y);
                mma_tf32(s[ni], qa[2 * kp + 1][0], qa[2 * kp + 1][1],
                         qa[2 * kp + 1][2], qa[2 * kp + 1][3], bv.z, bv.w);
            }
        }

        // ---- causal mask ----
        if (jt >= 2 * qt) {
            const int colb = jt * 64 + 2 * tig;
#pragma unroll
            for (int ni = 0; ni < 8; ni++) {
                const int c0 = colb + 8 * ni;
                if (c0 > row0) s[ni][0] = -INFINITY;
                if (c0 + 1 > row0) s[ni][1] = -INFINITY;
                if (c0 > row1) s[ni][2] = -INFINITY;
                if (c0 + 1 > row1) s[ni][3] = -INFINITY;
            }
        }

        // ---- online softmax ----
        float m0 = -INFINITY, m1 = -INFINITY;
#pragma unroll
        for (int ni = 0; ni < 8; ni++) {
            m0 = fmaxf(m0, fmaxf(s[ni][0], s[ni][1]));
            m1 = fmaxf(m1, fmaxf(s[ni][2], s[ni][3]));
        }
        m0 = fmaxf(m0, __shfl_xor_sync(0xffffffffu, m0, 1, 4));
        m0 = fmaxf(m0, __shfl_xor_sync(0xffffffffu, m0, 2, 4));
        m1 = fmaxf(m1, __shfl_xor_sync(0xffffffffu, m1, 1, 4));
        m1 = fmaxf(m1, __shfl_xor_sync(0xffffffffu, m1, 2, 4));
        const float mn0 = fmaxf(mrun0, m0);
        const float mn1 = fmaxf(mrun1, m1);
        const float al0 = __expf(mrun0 - mn0);
        const float al1 = __expf(mrun1 - mn1);
        float ls0 = 0.f, ls1 = 0.f;
        uint32_t pb[8][4];
#pragma unroll
        for (int ni = 0; ni < 8; ni++) {
            float p0 = __expf(s[ni][0] - mn0);
            float p1 = __expf(s[ni][1] - mn0);
            float p2 = __expf(s[ni][2] - mn1);
            float p3 = __expf(s[ni][3] - mn1);
            ls0 += p0 + p1;
            ls1 += p2 + p3;
            pb[ni][0] = f2tf32(p0);
            pb[ni][1] = f2tf32(p1);
            pb[ni][2] = f2tf32(p2);
            pb[ni][3] = f2tf32(p3);
            ctx[ni][0] *= al0;
            ctx[ni][1] *= al0;
            ctx[ni][2] *= al1;
            ctx[ni][3] *= al1;
        }
        ls0 += __shfl_xor_sync(0xffffffffu, ls0, 1, 4);
        ls0 += __shfl_xor_sync(0xffffffffu, ls0, 2, 4);
        ls1 += __shfl_xor_sync(0xffffffffu, ls1, 1, 4);
        ls1 += __shfl_xor_sync(0xffffffffu, ls1, 2, 4);
        mrun0 = mn0;
        mrun1 = mn1;
        lrun0 = lrun0 * al0 + ls0;
        lrun1 = lrun1 * al1 + ls1;

        // ---- ctx += P V ----
#pragma unroll
        for (int kp = 0; kp < 4; kp++) {
            const int kc = kp * 16 + tig * 4;
#pragma unroll
            for (int ni = 0; ni < 8; ni++) {
                uint4 bv = *(const uint4*)&Vt[(ni * 8 + gr) * ATP + kc];
                mma_tf32(ctx[ni], pb[2 * kp][0], pb[2 * kp][2], pb[2 * kp][1],
                         pb[2 * kp][3], bv.x, bv.y);
                mma_tf32(ctx[ni], pb[2 * kp + 1][0], pb[2 * kp + 1][2],
                         pb[2 * kp + 1][1], pb[2 * kp + 1][3], bv.z, bv.w);
            }
        }
    }

    // ---- finalize: g_ctx tf32 NATURAL layout (for O-GEMM) ----
    const float inv0 = 1.0f / lrun0;
    const float inv1 = 1.0f / lrun1;
    uint32_t* o0 = g_ctx + (((size_t)(b * T_SEQ + row0)) * NH + h) * HD;
    uint32_t* o1 = g_ctx + (((size_t)(b * T_SEQ + row1)) * NH + h) * HD;
#pragma unroll
    for (int ni = 0; ni < 8; ni++) {
        const int d = ni * 8 + 2 * tig;
        uint2 w0, w1;
        w0.x = f2tf32(ctx[ni][0] * inv0);
        w0.y = f2tf32(ctx[ni][1] * inv0);
        w1.x = f2tf32(ctx[ni][2] * inv1);
        w1.y = f2tf32(ctx[ni][3] * inv1);
        *(uint2*)&o0[d] = w0;
        *(uint2*)&o1[d] = w1;
    }
}

// ---------------------------------------------------------------------------
extern "C" void kernel_launch(void* const* d_in, const int* in_sizes, int n_in,
                              void* d_out, int out_size)
{
    const float* x    = (const float*)d_in[0];
    const float* cosT = (const float*)d_in[1];
    const float* sinT = (const float*)d_in[2];
    const float* wq   = (const float*)d_in[3];
    const float* bq   = (const float*)d_in[4];
    const float* wk   = (const float*)d_in[5];
    const float* bk   = (const float*)d_in[6];
    const float* wv   = (const float*)d_in[7];
    const float* bv   = (const float*)d_in[8];
    const float* wo   = (const float*)d_in[9];
    const float* bo   = (const float*)d_in[10];

    float* out  = (float*)d_out;            // (B, T, D)
    float* kout = out + (size_t)8388608;    // (B, KV, T, HD)
    float* vout = out + (size_t)10485760;   // (B, KV, T, HD)

    const int GEMM_SMEM = 4 * TILE_W * 4;   // 81920 B
    const int ATTN_SMEM = 4 * KVW * 4;      // 81920 B
    static bool attr_set = false;
    if (!attr_set) {
        cudaFuncSetAttribute(db_gemm<0>, cudaFuncAttributeMaxDynamicSharedMemorySize, GEMM_SMEM);
        cudaFuncSetAttribute(db_gemm<1>, cudaFuncAttributeMaxDynamicSharedMemorySize, GEMM_SMEM);
        cudaFuncSetAttribute(attn_mma, cudaFuncAttributeMaxDynamicSharedMemorySize, ATTN_SMEM);
        attr_set = true;
    }

    uint32_t* p_xt;  cudaGetSymbolAddress((void**)&p_xt, g_xt);
    uint32_t* p_wq;  cudaGetSymbolAddress((void**)&p_wq, g_wq);
    uint32_t* p_wk;  cudaGetSymbolAddress((void**)&p_wk, g_wk);
    uint32_t* p_wv;  cudaGetSymbolAddress((void**)&p_wv, g_wv);
    uint32_t* p_wo;  cudaGetSymbolAddress((void**)&p_wo, g_wo);
    uint32_t* p_vt;  cudaGetSymbolAddress((void**)&p_vt, g_vt);

    // Prep: fp32 -> tf32 (natural), one launch
    cvt_all<<<18432, 256>>>(x, wq, wk, wv, wo, p_xt, p_wq, p_wk, p_wv, p_wo);

    // Fused QKV projections (+RoPE for Q,K; K also written as PERM16 tf32)
    db_gemm<0><<<dim3(24, 32), 256, GEMM_SMEM>>>(
        p_xt, bq, bk, bv, kout, vout, nullptr, cosT, sinT);

    // V -> transposed PERM16 tf32
    vtrans<<<dim3(32, 16), 256>>>(vout, p_vt);

    // Attention -> g_ctx (natural tf32)
    attn_mma<<<dim3(T_SEQ / 128, 2 * NH), 256, ATTN_SMEM>>>();

    // Output projection -> out
    db_gemm<1><<<dim3(16, 32), 256, GEMM_SMEM>>>(
        nullptr, bo, nullptr, nullptr, nullptr, nullptr, out, nullptr, nullptr);
}

// round 13
// speedup vs baseline: 1.1817x; 1.0149x over previous
#include <cuda_runtime.h>
#include <cstdint>
#include <math.h>

#define T_SEQ 2048
#define DMODEL 2048
#define NH 32
#define NKV 8
#define HD 64

// ---------------- Scratch (device globals; allocation-free) ----------------
// g_kc / g_vt use the k16 permutation: within each 16-word k-block, logical
// k = b*8 + 2*tig + lo (b in {0,1}, tig 0..3, lo {0,1}) stored at slot
// tig*4 + b*2 + lo. Applied identically to both MMA operands -> bit-exact.
// All other tf32 globals are natural layout (consumed by uint64-pair loads).
__device__ float    g_q  [(size_t)2 * NH * T_SEQ * HD];   // fp32 Q (b,h,t,d)
__device__ uint32_t g_ctx[(size_t)2 * T_SEQ * NH * HD];   // tf32 ctx natural
__device__ uint32_t g_xt [(size_t)4096 * 2048];           // tf32 x natural
__device__ uint32_t g_wq [(size_t)2048 * 2048];
__device__ uint32_t g_wk [(size_t)512 * 2048];
__device__ uint32_t g_wv [(size_t)512 * 2048];
__device__ uint32_t g_wo [(size_t)2048 * 2048];
__device__ uint32_t g_kc [(size_t)2 * NKV * T_SEQ * HD];  // tf32 K PERM16(d)
__device__ uint32_t g_vt [(size_t)2 * NKV * HD * T_SEQ];  // tf32 V^T PERM16(t)

__device__ __forceinline__ uint32_t f2tf32(float f) {
    uint32_t u;
    asm("cvt.rna.tf32.f32 %0, %1;" : "=r"(u) : "f"(f));
    return u;
}

__device__ __forceinline__ void mma_tf32(float* c, uint32_t a0, uint32_t a1,
                                         uint32_t a2, uint32_t a3,
                                         uint32_t b0, uint32_t b1) {
    asm volatile(
        "mma.sync.aligned.m16n8k8.row.col.f32.tf32.tf32.f32 "
        "{%0,%1,%2,%3}, {%4,%5,%6,%7}, {%8,%9}, {%0,%1,%2,%3};"
        : "+f"(c[0]), "+f"(c[1]), "+f"(c[2]), "+f"(c[3])
        : "r"(a0), "r"(a1), "r"(a2), "r"(a3), "r"(b0), "r"(b1));
}

__device__ __forceinline__ uint32_t smem_u32(const void* p) {
    uint32_t a;
    asm("{ .reg .u64 t; cvta.to.shared.u64 t, %1; cvt.u32.u64 %0, t; }"
        : "=r"(a) : "l"(p));
    return a;
}
// GEMM fills: L2-only (.cg) — weights/activations have no L1 reuse (measured win R12).
#define CP_ASYNC16_CG(dst, src) \
    asm volatile("cp.async.cg.shared.global [%0], [%1], 16;" :: "r"(dst), "l"(src))
// Attention fills: L1-allocating (.ca) — K/V reused across CTAs on an SM (measured R11/R12).
#define CP_ASYNC16_CA(dst, src) \
    asm volatile("cp.async.ca.shared.global [%0], [%1], 16;" :: "r"(dst), "l"(src))
#define CP_COMMIT() asm volatile("cp.async.commit_group;" ::: "memory")
#define CP_WAIT0()  asm volatile("cp.async.wait_group 0;" ::: "memory")

// ============================================================================
// Prep: all fp32 -> tf32 (natural layout), one launch.
// ============================================================================
__global__ void cvt_all(const float* __restrict__ x,
                        const float* __restrict__ wq,
                        const float* __restrict__ wk,
                        const float* __restrict__ wv,
                        const float* __restrict__ wo,
                        uint32_t* __restrict__ xt,
                        uint32_t* __restrict__ wqt,
                        uint32_t* __restrict__ wkt,
                        uint32_t* __restrict__ wvt,
                        uint32_t* __restrict__ wot)
{
    int i = blockIdx.x * blockDim.x + threadIdx.x;
    const float* in;
    uint32_t* out;
    if (i < 2097152)        { in = x;  out = xt; }
    else if (i < 3145728)   { in = wq; out = wqt; i -= 2097152; }
    else if (i < 3407872)   { in = wk; out = wkt; i -= 3145728; }
    else if (i < 3670016)   { in = wv; out = wvt; i -= 3407872; }
    else                    { in = wo; out = wot; i -= 3670016; }
    float4 v = ((const float4*)in)[i];
    uint4 o;
    o.x = f2tf32(v.x); o.y = f2tf32(v.y); o.z = f2tf32(v.z); o.w = f2tf32(v.w);
    ((uint4*)out)[i] = o;
}

// ============================================================================
// Prep: V (b,kv,t,d) fp32 -> V^T (b,kv,d,t) tf32, key dim k16-PERMUTED.
// ============================================================================
__global__ void vtrans(const float* __restrict__ vin, uint32_t* __restrict__ vt)
{
    __shared__ uint32_t ts[64 * 65];
    const int tid = threadIdx.x;
    const int jt = blockIdx.x;
    const int bkv = blockIdx.y;

    const float* in = vin + ((size_t)bkv * T_SEQ + jt * 64) * HD;
#pragma unroll
    for (int p = 0; p < 4; p++) {
        const int lin = p * 256 + tid;
        const int t = lin >> 4;
        const int dq = (lin & 15) * 4;
        float4 v = *(const float4*)&in[t * HD + dq];
        ts[(dq + 0) * 65 + t] = f2tf32(v.x);
        ts[(dq + 1) * 65 + t] = f2tf32(v.y);
        ts[(dq + 2) * 65 + t] = f2tf32(v.z);
        ts[(dq + 3) * 65 + t] = f2tf32(v.w);
    }
    __syncthreads();
    uint32_t* out = vt + (size_t)bkv * HD * T_SEQ + jt * 64;
#pragma unroll
    for (int p = 0; p < 4; p++) {
        const int lin = p * 256 + tid;
        const int d = lin >> 4;
        const int cq = (lin & 15) * 4;
        const int blockbase = cq & ~15;
        const int k0 = cq & 15;
        const int slot0 = ((k0 & 7) >> 1) * 4 + ((k0 >> 3) & 1) * 2;
        uint2 lo, hi;
        lo.x = ts[d * 65 + cq + 0];
        lo.y = ts[d * 65 + cq + 1];
        hi.x = ts[d * 65 + cq + 2];
        hi.y = ts[d * 65 + cq + 3];
        *(uint2*)&out[(size_t)d * T_SEQ + blockbase + slot0] = lo;
        *(uint2*)&out[(size_t)d * T_SEQ + blockbase + slot0 + 4] = hi;
    }
}

// ============================================================================
// cp.async.cg double-buffered tf32 GEMM — R7/R11/R12 config:
// 128x128 tile, BK=32, 8 warps (2x4), warp tile 64x32, SPAD 40,
// uint64-pair fragment loads on natural-layout operands.
// KIND 0: fused QKV. bx<16: Q+RoPE->g_q fp32; 16..19: K+RoPE->kout fp32 +
//         g_kc tf32 PERM16; 20..23: V->vout fp32.
// KIND 1: O projection: A=g_ctx (tf32 natural), C=out fp32.
// ============================================================================
#define SPAD 40
#define TILE_W (128 * SPAD)

template <int KIND>
__global__ __launch_bounds__(256, 2) void db_gemm(
    const uint32_t* __restrict__ xA,
    const float* __restrict__ bq, const float* __restrict__ bk,
    const float* __restrict__ bv,
    float* __restrict__ kout, float* __restrict__ vout,
    float* __restrict__ outC,
    const float* __restrict__ cosT, const float* __restrict__ sinT)
{
    extern __shared__ __align__(16) uint32_t sm[];
    const uint32_t sm_addr = smem_u32(sm);

    const int tid = threadIdx.x;
    const int wid = tid >> 5;
    const int lane = tid & 31;
    const int gr = lane >> 2;
    const int tig = lane & 3;
    const int wm = wid >> 2;
    const int wn = wid & 3;

    constexpr int K = DMODEL;
    const int m0 = blockIdx.y * 128;

    int mode, n0;
    const uint32_t* A;
    const uint32_t* W;
    const float* bias;
    if (KIND == 1) {
        mode = 0; n0 = blockIdx.x * 128; A = g_ctx; W = g_wo; bias = bq;
    } else {
        const int bx = blockIdx.x;
        A = xA;
        if (bx < 16)      { mode = 1; n0 = bx * 128;        W = g_wq; bias = bq; }
        else if (bx < 20) { mode = 2; n0 = (bx - 16) * 128; W = g_wk; bias = bk; }
        else              { mode = 3; n0 = (bx - 20) * 128; W = g_wv; bias = bv; }
    }

    const int rbase = tid >> 3;
    const int cg = tid & 7;
    const uint32_t* Asrc[4];
    const uint32_t* Wsrc[4];
    uint32_t dsto[4];
#pragma unroll
    for (int i = 0; i < 4; i++) {
        Asrc[i] = A + (size_t)(m0 + i * 32 + rbase) * K + cg * 4;
        Wsrc[i] = W + (size_t)(n0 + i * 32 + rbase) * K + cg * 4;
        dsto[i] = (uint32_t)(((i * 32 + rbase) * SPAD + cg * 4) * 4);
    }

    float acc[4][4][4];
#pragma unroll
    for (int mi = 0; mi < 4; mi++)
#pragma unroll
        for (int ni = 0; ni < 4; ni++)
#pragma unroll
            for (int r = 0; r < 4; r++) acc[mi][ni][r] = 0.f;

    const int NST = K / 32;
#pragma unroll
    for (int i = 0; i < 4; i++) {
        CP_ASYNC16_CG(sm_addr + dsto[i], Asrc[i]);
        CP_ASYNC16_CG(sm_addr + TILE_W * 4 + dsto[i], Wsrc[i]);
    }
    CP_COMMIT();

    for (int s = 0; s < NST; s++) {
        CP_WAIT0();
        __syncthreads();
        if (s + 1 < NST) {
            const uint32_t boff = (uint32_t)((s + 1) & 1) * (2 * TILE_W * 4);
            const int ko = (s + 1) * 32;
#pragma unroll
            for (int i = 0; i < 4; i++) {
                CP_ASYNC16_CG(sm_addr + boff + dsto[i], Asrc[i] + ko);
                CP_ASYNC16_CG(sm_addr + boff + TILE_W * 4 + dsto[i], Wsrc[i] + ko);
            }
            CP_COMMIT();
        }

        const uint32_t* Abase = sm + (s & 1) * 2 * TILE_W + (wm * 64) * SPAD;
        const uint32_t* Bbase = sm + (s & 1) * 2 * TILE_W + TILE_W + (wn * 32) * SPAD;
#pragma unroll
        for (int kk = 0; kk < 4; kk++) {
            const int kc = kk * 8 + 2 * tig;
            uint32_t bf[4][2];
#pragma unroll
            for (int ni = 0; ni < 4; ni++) {
                uint64_t bv = *(const uint64_t*)&Bbase[(ni * 8 + gr) * SPAD + kc];
                bf[ni][0] = (uint32_t)bv;
                bf[ni][1] = (uint32_t)(bv >> 32);
            }
#pragma unroll
            for (int mi = 0; mi < 4; mi++) {
                uint64_t a02 = *(const uint64_t*)&Abase[(mi * 16 + gr) * SPAD + kc];
                uint64_t a13 = *(const uint64_t*)&Abase[(mi * 16 + gr + 8) * SPAD + kc];
                uint32_t a0 = (uint32_t)a02, a2 = (uint32_t)(a02 >> 32);
                uint32_t a1 = (uint32_t)a13, a3 = (uint32_t)(a13 >> 32);
#pragma unroll
                for (int ni = 0; ni < 4; ni++)
                    mma_tf32(acc[mi][ni], a0, a1, a2, a3, bf[ni][0], bf[ni][1]);
            }
        }
    }

    // ---------------- Register epilogue ----------------
#pragma unroll
    for (int mi = 0; mi < 4; mi++) {
#pragma unroll
        for (int half = 0; half < 2; half++) {
            const int m = m0 + wm * 64 + mi * 16 + gr + half * 8;
            const int bb = m >> 11;
            const int t = m & (T_SEQ - 1);
#pragma unroll
            for (int ni = 0; ni < 4; ni++) {
                const int n = n0 + wn * 32 + ni * 8 + tig * 2;
                float v0 = acc[mi][ni][half * 2 + 0] + bias[n];
                float v1 = acc[mi][ni][half * 2 + 1] + bias[n + 1];
                if (mode == 1 || mode == 2) {
                    const int hh = (n & 63) >> 1;
                    const float c = cosT[t * (HD / 2) + hh];
                    const float ss = sinT[t * (HD / 2) + hh];
                    const float e = v0 * c - v1 * ss;
                    const float o = v0 * ss + v1 * c;
                    v0 = e;
                    v1 = o;
                }
                if (mode == 0) {
                    *(float2*)&outC[(size_t)m * DMODEL + n] = make_float2(v0, v1);
                } else if (mode == 1) {
                    *(float2*)&g_q[(((size_t)(bb * NH + (n >> 6))) * T_SEQ + t) * HD + (n & 63)] =
                        make_float2(v0, v1);
                } else {
                    const size_t idx =
                        (((size_t)(bb * NKV + (n >> 6))) * T_SEQ + t) * HD + (n & 63);
                    if (mode == 2) {
                        *(float2*)&kout[idx] = make_float2(v0, v1);
                        // PERM16 tf32 K for attention LDS.128 path
                        const int d = n & 63;
                        const int k0 = d & 15;
                        const int slot0 = ((k0 & 7) >> 1) * 4 + ((k0 >> 3) & 1) * 2;
                        const size_t base =
                            (((size_t)(bb * NKV + (n >> 6))) * T_SEQ + t) * HD +
                            (d & ~15) + slot0;
                        uint2 kq;
                        kq.x = f2tf32(v0);
                        kq.y = f2tf32(v1);
                        *(uint2*)&g_kc[base] = kq;
                    } else {
                        *(float2*)&vout[idx] = make_float2(v0, v1);
                    }
                }
            }
        }
    }
}

// ============================================================================
// Flash attention — R9/R11 config with .ca fills (fastest measured: 317us):
// 8 warps, warp tile 16x64, PERM16 K/V globals, LDS.128 frags, pitch 80,
// cp.async.ca double-buffered, heavy-first schedule.
// ============================================================================
#define ATP 80
#define KVW (64 * ATP)   // 5120 words

__global__ __launch_bounds__(256, 2) void attn_mma()
{
    extern __shared__ __align__(16) uint32_t sm[];
    const uint32_t sm_addr = smem_u32(sm);

    const int tid = threadIdx.x;
    const int wid = tid >> 5;
    const int lane = tid & 31;
    const int gr = lane >> 2;
    const int tig = lane & 3;

    const int qt = (gridDim.x - 1) - blockIdx.x;  // heavy-first
    const int bh = blockIdx.y;
    const int b = bh >> 5;
    const int h = bh & 31;
    const int bkv = (b * NKV) + (h >> 2);

    // Q fragments (registers, natural): qa[ks] covers d = 8ks+2tig, +1
    const float* Qg = g_q + (((size_t)(b * NH + h)) * T_SEQ + qt * 128 + wid * 16) * HD;
    uint32_t qa[8][4];
#pragma unroll
    for (int ks = 0; ks < 8; ks++) {
        const int d0 = 8 * ks + 2 * tig;
        qa[ks][0] = f2tf32(Qg[gr * HD + d0] * 0.125f);
        qa[ks][1] = f2tf32(Qg[(gr + 8) * HD + d0] * 0.125f);
        qa[ks][2] = f2tf32(Qg[gr * HD + d0 + 1] * 0.125f);
        qa[ks][3] = f2tf32(Qg[(gr + 8) * HD + d0 + 1] * 0.125f);
    }

    const uint32_t* Kbase = g_kc + (size_t)bkv * T_SEQ * HD;
    const uint32_t* Vbase = g_vt + (size_t)bkv * HD * T_SEQ;

    float ctx[8][4];
#pragma unroll
    for (int ni = 0; ni < 8; ni++)
#pragma unroll
        for (int r = 0; r < 4; r++) ctx[ni][r] = 0.f;
    float mrun0 = -INFINITY, mrun1 = -INFINITY;
    float lrun0 = 0.f, lrun1 = 0.f;

    const int lrow = tid >> 2;
    const int lcol = (tid & 3) * 16;
    const int row0 = qt * 128 + wid * 16 + gr;
    const int row1 = row0 + 8;
    const int njt = 2 * qt + 2;

#pragma unroll
    for (int c = 0; c < 4; c++) {
        const int col = lcol + 4 * c;
        CP_ASYNC16_CA(sm_addr + (lrow * ATP + col) * 4, Kbase + (size_t)lrow * HD + col);
        CP_ASYNC16_CA(sm_addr + (2 * KVW + lrow * ATP + col) * 4,
                      Vbase + (size_t)lrow * T_SEQ + col);
    }
    CP_COMMIT();

    for (int jt = 0; jt < njt; jt++) {
        CP_WAIT0();
        __syncthreads();
        if (jt + 1 < njt) {
            const uint32_t boff = (uint32_t)((jt + 1) & 1) * KVW * 4;
            const int kt = (jt + 1) * 64;
#pragma unroll
            for (int c = 0; c < 4; c++) {
                const int col = lcol + 4 * c;
                CP_ASYNC16_CA(sm_addr + boff + (lrow * ATP + col) * 4,
                              Kbase + (size_t)(kt + lrow) * HD + col);
                CP_ASYNC16_CA(sm_addr + 2 * KVW * 4 + boff + (lrow * ATP + col) * 4,
                              Vbase + (size_t)lrow * T_SEQ + kt + col);
            }
            CP_COMMIT();
        }

        if (jt == 2 * qt + 1 && wid < 4) continue;  // fully masked

        const uint32_t* Ks = sm + (jt & 1) * KVW;
        const uint32_t* Vt = sm + 2 * KVW + (jt & 1) * KVW;

        // ---- S = Q K^T ----
        float s[8][4];
#pragma unroll
        for (int ni = 0; ni < 8; ni++)
#pragma unroll
            for (int r = 0; r < 4; r++) s[ni][r] = 0.f;
#pragma unroll
        for (int kp = 0; kp < 4; kp++) {
            const int kc = kp * 16 + tig * 4;
#pragma unroll
            for (int ni = 0; ni < 8; ni++) {
                uint4 bv = *(const uint4*)&Ks[(ni * 8 + gr) * ATP + kc];
                mma_tf32(s[ni], qa[2 * kp][0], qa[2 * kp][1], qa[2 * kp][2],
                         qa[2 * kp][3], bv.x, bv.y);
                mma_tf32(s[ni], qa[2 * kp + 1][0], qa[2 * kp + 1][1],
                         qa[2 * kp + 1][2], qa[2 * kp + 1][3], bv.z, bv.w);
            }
        }

        // ---- causal mask ----
        if (jt >= 2 * qt) {
            const int colb = jt * 64 + 2 * tig;
#pragma unroll
            for (int ni = 0; ni < 8; ni++) {
                const int c0 = colb + 8 * ni;
                if (c0 > row0) s[ni][0] = -INFINITY;
                if (c0 + 1 > row0) s[ni][1] = -INFINITY;
                if (c0 > row1) s[ni][2] = -INFINITY;
                if (c0 + 1 > row1) s[ni][3] = -INFINITY;
            }
        }

        // ---- online softmax ----
        float m0 = -INFINITY, m1 = -INFINITY;
#pragma unroll
        for (int ni = 0; ni < 8; ni++) {
            m0 = fmaxf(m0, fmaxf(s[ni][0], s[ni][1]));
            m1 = fmaxf(m1, fmaxf(s[ni][2], s[ni][3]));
        }
        m0 = fmaxf(m0, __shfl_xor_sync(0xffffffffu, m0, 1, 4));
        m0 = fmaxf(m0, __shfl_xor_sync(0xffffffffu, m0, 2, 4));
        m1 = fmaxf(m1, __shfl_xor_sync(0xffffffffu, m1, 1, 4));
        m1 = fmaxf(m1, __shfl_xor_sync(0xffffffffu, m1, 2, 4));
        const float mn0 = fmaxf(mrun0, m0);
        const float mn1 = fmaxf(mrun1, m1);
        const float al0 = __expf(mrun0 - mn0);
        const float al1 = __expf(mrun1 - mn1);
        float ls0 = 0.f, ls1 = 0.f;
        uint32_t pb[8][4];
#pragma unroll
        for (int ni = 0; ni < 8; ni++) {
            float p0 = __expf(s[ni][0] - mn0);
            float p1 = __expf(s[ni][1] - mn0);
            float p2 = __expf(s[ni][2] - mn1);
            float p3 = __expf(s[ni][3] - mn1);
            ls0 += p0 + p1;
            ls1 += p2 + p3;
            pb[ni][0] = f2tf32(p0);
            pb[ni][1] = f2tf32(p1);
            pb[ni][2] = f2tf32(p2);
            pb[ni][3] = f2tf32(p3);
            ctx[ni][0] *= al0;
            ctx[ni][1] *= al0;
            ctx[ni][2] *= al1;
            ctx[ni][3] *= al1;
        }
        ls0 += __shfl_xor_sync(0xffffffffu, ls0, 1, 4);
        ls0 += __shfl_xor_sync(0xffffffffu, ls0, 2, 4);
        ls1 += __shfl_xor_sync(0xffffffffu, ls1, 1, 4);
        ls1 += __shfl_xor_sync(0xffffffffu, ls1, 2, 4);
        mrun0 = mn0;
        mrun1 = mn1;
        lrun0 = lrun0 * al0 + ls0;
        lrun1 = lrun1 * al1 + ls1;

        // ---- ctx += P V ----
#pragma unroll
        for (int kp = 0; kp < 4; kp++) {
            const int kc = kp * 16 + tig * 4;
#pragma unroll
            for (int ni = 0; ni < 8; ni++) {
                uint4 bv = *(const uint4*)&Vt[(ni * 8 + gr) * ATP + kc];
                mma_tf32(ctx[ni], pb[2 * kp][0], pb[2 * kp][2], pb[2 * kp][1],
                         pb[2 * kp][3], bv.x, bv.y);
                mma_tf32(ctx[ni], pb[2 * kp + 1][0], pb[2 * kp + 1][2],
                         pb[2 * kp + 1][1], pb[2 * kp + 1][3], bv.z, bv.w);
            }
        }
    }

    // ---- finalize: g_ctx tf32 NATURAL layout (for O-GEMM) ----
    const float inv0 = 1.0f / lrun0;
    const float inv1 = 1.0f / lrun1;
    uint32_t* o0 = g_ctx + (((size_t)(b * T_SEQ + row0)) * NH + h) * HD;
    uint32_t* o1 = g_ctx + (((size_t)(b * T_SEQ + row1)) * NH + h) * HD;
#pragma unroll
    for (int ni = 0; ni < 8; ni++) {
        const int d = ni * 8 + 2 * tig;
        uint2 w0, w1;
        w0.x = f2tf32(ctx[ni][0] * inv0);
        w0.y = f2tf32(ctx[ni][1] * inv0);
        w1.x = f2tf32(ctx[ni][2] * inv1);
        w1.y = f2tf32(ctx[ni][3] * inv1);
        *(uint2*)&o0[d] = w0;
        *(uint2*)&o1[d] = w1;
    }
}

// ---------------------------------------------------------------------------
extern "C" void kernel_launch(void* const* d_in, const int* in_sizes, int n_in,
                              void* d_out, int out_size)
{
    const float* x    = (const float*)d_in[0];
    const float* cosT = (const float*)d_in[1];
    const float* sinT = (const float*)d_in[2];
    const float* wq   = (const float*)d_in[3];
    const float* bq   = (const float*)d_in[4];
    const float* wk   = (const float*)d_in[5];
    const float* bk   = (const float*)d_in[6];
    const float* wv   = (const float*)d_in[7];
    const float* bv   = (const float*)d_in[8];
    const float* wo   = (const float*)d_in[9];
    const float* bo   = (const float*)d_in[10];

    float* out  = (float*)d_out;            // (B, T, D)
    float* kout = out + (size_t)8388608;    // (B, KV, T, HD)
    float* vout = out + (size_t)10485760;   // (B, KV, T, HD)

    const int GEMM_SMEM = 4 * TILE_W * 4;   // 81920 B
    const int ATTN_SMEM = 4 * KVW * 4;      // 81920 B
    static bool attr_set = false;
    if (!attr_set) {
        cudaFuncSetAttribute(db_gemm<0>, cudaFuncAttributeMaxDynamicSharedMemorySize, GEMM_SMEM);
        cudaFuncSetAttribute(db_gemm<1>, cudaFuncAttributeMaxDynamicSharedMemorySize, GEMM_SMEM);
        cudaFuncSetAttribute(attn_mma, cudaFuncAttributeMaxDynamicSharedMemorySize, ATTN_SMEM);
        attr_set = true;
    }

    uint32_t* p_xt;  cudaGetSymbolAddress((void**)&p_xt, g_xt);
    uint32_t* p_wq;  cudaGetSymbolAddress((void**)&p_wq, g_wq);
    uint32_t* p_wk;  cudaGetSymbolAddress((void**)&p_wk, g_wk);
    uint32_t* p_wv;  cudaGetSymbolAddress((void**)&p_wv, g_wv);
    uint32_t* p_wo;  cudaGetSymbolAddress((void**)&p_wo, g_wo);
    uint32_t* p_vt;  cudaGetSymbolAddress((void**)&p_vt, g_vt);

    // Prep: fp32 -> tf32 (natural), one launch
    cvt_all<<<18432, 256>>>(x, wq, wk, wv, wo, p_xt, p_wq, p_wk, p_wv, p_wo);

    // Fused QKV projections (+RoPE for Q,K; K also written as PERM16 tf32)
    db_gemm<0><<<dim3(24, 32), 256, GEMM_SMEM>>>(
        p_xt, bq, bk, bv, kout, vout, nullptr, cosT, sinT);

    // V -> transposed PERM16 tf32
    vtrans<<<dim3(32, 16), 256>>>(vout, p_vt);

    // Attention -> g_ctx (natural tf32)
    attn_mma<<<dim3(T_SEQ / 128, 2 * NH), 256, ATTN_SMEM>>>();

    // Output projection -> out
    db_gemm<1><<<dim3(16, 32), 256, GEMM_SMEM>>>(
        nullptr, bo, nullptr, nullptr, nullptr, nullptr, out, nullptr, nullptr);
}

// round 14
// speedup vs baseline: 2.3368x; 1.9775x over previous
#include <cuda_runtime.h>
#include <cuda_fp16.h>
#include <cstdint>
#include <math.h>

#define T_SEQ 2048
#define DMODEL 2048
#define NH 32
#define NKV 8
#define HD 64

// ---------------- Scratch (device globals; allocation-free) ----------------
// All fp16 operand globals use the k16 permutation: within each 16-half
// k-block, logical k = b*8 + 2*tig + lo (b in {0,1}, tig 0..3, lo {0,1})
// stored at slot tig*4 + b*2 + lo. Applied identically to both MMA operands'
// k dimension -> dot products preserved. One LDS.64 = one fp16 B-fragment.
__device__ float  g_q  [(size_t)2 * NH * T_SEQ * HD];   // fp32 Q (b,h,t,d)
__device__ __half g_ctx[(size_t)2 * T_SEQ * NH * HD];   // fp16 ctx PERM16
__device__ __half g_xt [(size_t)4096 * 2048];           // fp16 x PERM16
__device__ __half g_wq [(size_t)2048 * 2048];           // PERM16
__device__ __half g_wk [(size_t)512 * 2048];            // PERM16
__device__ __half g_wv [(size_t)512 * 2048];            // PERM16
__device__ __half g_wo [(size_t)2048 * 2048];           // PERM16
__device__ __half g_kc [(size_t)2 * NKV * T_SEQ * HD];  // fp16 K PERM16(d)
__device__ __half g_vt [(size_t)2 * NKV * HD * T_SEQ];  // fp16 V^T PERM16(t)

__device__ __forceinline__ uint32_t pack_h2(float a, float b) {
    __half2 h = __floats2half2_rn(a, b);
    return *(uint32_t*)&h;
}

__device__ __forceinline__ void mma_f16(float* c, uint32_t a0, uint32_t a1,
                                        uint32_t a2, uint32_t a3,
                                        uint32_t b0, uint32_t b1) {
    asm volatile(
        "mma.sync.aligned.m16n8k16.row.col.f32.f16.f16.f32 "
        "{%0,%1,%2,%3}, {%4,%5,%6,%7}, {%8,%9}, {%0,%1,%2,%3};"
        : "+f"(c[0]), "+f"(c[1]), "+f"(c[2]), "+f"(c[3])
        : "r"(a0), "r"(a1), "r"(a2), "r"(a3), "r"(b0), "r"(b1));
}

__device__ __forceinline__ uint32_t smem_u32(const void* p) {
    uint32_t a;
    asm("{ .reg .u64 t; cvta.to.shared.u64 t, %1; cvt.u32.u64 %0, t; }"
        : "=r"(a) : "l"(p));
    return a;
}
#define CP_ASYNC16_CG(dst, src) \
    asm volatile("cp.async.cg.shared.global [%0], [%1], 16;" :: "r"(dst), "l"(src))
#define CP_ASYNC16_CA(dst, src) \
    asm volatile("cp.async.ca.shared.global [%0], [%1], 16;" :: "r"(dst), "l"(src))
#define CP_COMMIT() asm volatile("cp.async.commit_group;" ::: "memory")
#define CP_WAIT0()  asm volatile("cp.async.wait_group 0;" ::: "memory")

// ============================================================================
// Prep: all fp32 -> fp16 PERM16, one launch. Each float4 (4 logical ks,
// k0%4==0) -> two half2 at slots 8u+2b and 8u+4+2b (u=(k0>>2)&1, b=k0>>3).
// ============================================================================
__global__ void cvt_all(const float* __restrict__ x,
                        const float* __restrict__ wq,
                        const float* __restrict__ wk,
                        const float* __restrict__ wv,
                        const float* __restrict__ wo,
                        __half* __restrict__ xt,
                        __half* __restrict__ wqt,
                        __half* __restrict__ wkt,
                        __half* __restrict__ wvt,
                        __half* __restrict__ wot)
{
    int i = blockIdx.x * blockDim.x + threadIdx.x;
    const float* in;
    __half* out;
    if (i < 2097152)        { in = x;  out = xt; }
    else if (i < 3145728)   { in = wq; out = wqt; i -= 2097152; }
    else if (i < 3407872)   { in = wk; out = wkt; i -= 3145728; }
    else if (i < 3670016)   { in = wv; out = wvt; i -= 3407872; }
    else                    { in = wo; out = wot; i -= 3670016; }
    float4 v = ((const float4*)in)[i];
    const int w0 = i * 4;
    const int blockbase = w0 & ~15;
    const int k0 = w0 & 15;
    const int u = (k0 >> 2) & 1;
    const int b = (k0 >> 3) & 1;
    const int s0 = 8 * u + 2 * b;
    *(__half2*)&out[blockbase + s0]     = __floats2half2_rn(v.x, v.y);
    *(__half2*)&out[blockbase + s0 + 4] = __floats2half2_rn(v.z, v.w);
}

// ============================================================================
// Prep: V (b,kv,t,d) fp32 -> V^T (b,kv,d,t) fp16, key dim PERM16.
// ============================================================================
__global__ void vtrans(const float* __restrict__ vin, __half* __restrict__ vt)
{
    __shared__ float ts[64 * 65];
    const int tid = threadIdx.x;
    const int jt = blockIdx.x;
    const int bkv = blockIdx.y;

    const float* in = vin + ((size_t)bkv * T_SEQ + jt * 64) * HD;
#pragma unroll
    for (int p = 0; p < 4; p++) {
        const int lin = p * 256 + tid;
        const int t = lin >> 4;
        const int dq = (lin & 15) * 4;
        float4 v = *(const float4*)&in[t * HD + dq];
        ts[(dq + 0) * 65 + t] = v.x;
        ts[(dq + 1) * 65 + t] = v.y;
        ts[(dq + 2) * 65 + t] = v.z;
        ts[(dq + 3) * 65 + t] = v.w;
    }
    __syncthreads();
    __half* out = vt + (size_t)bkv * HD * T_SEQ + jt * 64;
#pragma unroll
    for (int p = 0; p < 4; p++) {
        const int lin = p * 256 + tid;
        const int d = lin >> 4;
        const int cq = (lin & 15) * 4;
        const int blockbase = cq & ~15;
        const int k0 = cq & 15;
        const int u = (k0 >> 2) & 1;
        const int b = (k0 >> 3) & 1;
        const int s0 = 8 * u + 2 * b;
        *(__half2*)&out[(size_t)d * T_SEQ + blockbase + s0] =
            __floats2half2_rn(ts[d * 65 + cq + 0], ts[d * 65 + cq + 1]);
        *(__half2*)&out[(size_t)d * T_SEQ + blockbase + s0 + 4] =
            __floats2half2_rn(ts[d * 65 + cq + 2], ts[d * 65 + cq + 3]);
    }
}

// ============================================================================
// cp.async.cg double-buffered fp16 GEMM: 128x128 tile, BK=64 halves, 8 warps
// (2x4), warp tile 64x32, m16n8k16. PERM16 operands -> LDS.64 B-fragments.
// Pitch 80 halves (160B): 4gr+tig distinct mod 16 -> conflict-free LDS.64.
// KIND 0: fused QKV. bx<16: Q+RoPE->g_q fp32; 16..19: K+RoPE->kout fp32 +
//         g_kc fp16 PERM16; 20..23: V->vout fp32.
// KIND 1: O projection: A=g_ctx (fp16 PERM16), C=out fp32.
// ============================================================================
#define GP 80
#define TILE_H (128 * GP)   // 10240 halves per operand buffer

template <int KIND>
__global__ __launch_bounds__(256, 2) void db_gemm(
    const __half* __restrict__ xA,
    const float* __restrict__ bq, const float* __restrict__ bk,
    const float* __restrict__ bv,
    float* __restrict__ kout, float* __restrict__ vout,
    float* __restrict__ outC,
    const float* __restrict__ cosT, const float* __restrict__ sinT)
{
    extern __shared__ __align__(16) __half smh[];
    const uint32_t sm_addr = smem_u32(smh);

    const int tid = threadIdx.x;
    const int wid = tid >> 5;
    const int lane = tid & 31;
    const int gr = lane >> 2;
    const int tig = lane & 3;
    const int wm = wid >> 2;
    const int wn = wid & 3;

    constexpr int K = DMODEL;
    const int m0 = blockIdx.y * 128;

    int mode, n0;
    const __half* A;
    const __half* W;
    const float* bias;
    if (KIND == 1) {
        mode = 0; n0 = blockIdx.x * 128; A = g_ctx; W = g_wo; bias = bq;
    } else {
        const int bx = blockIdx.x;
        A = xA;
        if (bx < 16)      { mode = 1; n0 = bx * 128;        W = g_wq; bias = bq; }
        else if (bx < 20) { mode = 2; n0 = (bx - 16) * 128; W = g_wk; bias = bk; }
        else              { mode = 3; n0 = (bx - 20) * 128; W = g_wv; bias = bv; }
    }

    // fills: 4 chunks per op per thread; row_i = i*32 + (tid>>3), chunk col tid&7
    const int rbase = tid >> 3;
    const int ch = tid & 7;
    const __half* Asrc = A + (size_t)(m0 + rbase) * K + ch * 8;
    const __half* Wsrc = W + (size_t)(n0 + rbase) * K + ch * 8;
    const uint32_t dstb = (uint32_t)(rbase * GP + ch * 8) * 2;

    float acc[4][4][4];
#pragma unroll
    for (int mi = 0; mi < 4; mi++)
#pragma unroll
        for (int ni = 0; ni < 4; ni++)
#pragma unroll
            for (int r = 0; r < 4; r++) acc[mi][ni][r] = 0.f;

    const int NST = K / 64;   // 32 stages
#pragma unroll
    for (int i = 0; i < 4; i++) {
        CP_ASYNC16_CG(sm_addr + i * 32 * GP * 2 + dstb, Asrc + (size_t)i * 32 * K);
        CP_ASYNC16_CG(sm_addr + TILE_H * 2 + i * 32 * GP * 2 + dstb,
                      Wsrc + (size_t)i * 32 * K);
    }
    CP_COMMIT();

    for (int s = 0; s < NST; s++) {
        CP_WAIT0();
        __syncthreads();
        if (s + 1 < NST) {
            const uint32_t boff = (uint32_t)((s + 1) & 1) * (2 * TILE_H * 2);
            const int ko = (s + 1) * 64;
#pragma unroll
            for (int i = 0; i < 4; i++) {
                CP_ASYNC16_CG(sm_addr + boff + i * 32 * GP * 2 + dstb,
                              Asrc + (size_t)i * 32 * K + ko);
                CP_ASYNC16_CG(sm_addr + boff + TILE_H * 2 + i * 32 * GP * 2 + dstb,
                              Wsrc + (size_t)i * 32 * K + ko);
            }
            CP_COMMIT();
        }

        const __half* Abase = smh + (s & 1) * 2 * TILE_H + (wm * 64) * GP;
        const __half* Bbase = smh + (s & 1) * 2 * TILE_H + TILE_H + (wn * 32) * GP;
#pragma unroll
        for (int blk = 0; blk < 4; blk++) {
            const int kc = blk * 16 + tig * 4;
            uint32_t bf[4][2];
#pragma unroll
            for (int ni = 0; ni < 4; ni++) {
                uint64_t bv = *(const uint64_t*)&Bbase[(ni * 8 + gr) * GP + kc];
                bf[ni][0] = (uint32_t)bv;
                bf[ni][1] = (uint32_t)(bv >> 32);
            }
#pragma unroll
            for (int mi = 0; mi < 4; mi++) {
                uint64_t aL = *(const uint64_t*)&Abase[(mi * 16 + gr) * GP + kc];
                uint64_t aH = *(const uint64_t*)&Abase[(mi * 16 + gr + 8) * GP + kc];
                const uint32_t a0 = (uint32_t)aL, a2 = (uint32_t)(aL >> 32);
                const uint32_t a1 = (uint32_t)aH, a3 = (uint32_t)(aH >> 32);
#pragma unroll
                for (int ni = 0; ni < 4; ni++)
                    mma_f16(acc[mi][ni], a0, a1, a2, a3, bf[ni][0], bf[ni][1]);
            }
        }
    }

    // ---------------- Register epilogue ----------------
#pragma unroll
    for (int mi = 0; mi < 4; mi++) {
#pragma unroll
        for (int half = 0; half < 2; half++) {
            const int m = m0 + wm * 64 + mi * 16 + gr + half * 8;
            const int bb = m >> 11;
            const int t = m & (T_SEQ - 1);
#pragma unroll
            for (int ni = 0; ni < 4; ni++) {
                const int n = n0 + wn * 32 + ni * 8 + tig * 2;
                float v0 = acc[mi][ni][half * 2 + 0] + bias[n];
                float v1 = acc[mi][ni][half * 2 + 1] + bias[n + 1];
                if (mode == 1 || mode == 2) {
                    const int hh = (n & 63) >> 1;
                    const float c = cosT[t * (HD / 2) + hh];
                    const float ss = sinT[t * (HD / 2) + hh];
                    const float e = v0 * c - v1 * ss;
                    const float o = v0 * ss + v1 * c;
                    v0 = e;
                    v1 = o;
                }
                if (mode == 0) {
                    *(float2*)&outC[(size_t)m * DMODEL + n] = make_float2(v0, v1);
                } else if (mode == 1) {
                    *(float2*)&g_q[(((size_t)(bb * NH + (n >> 6))) * T_SEQ + t) * HD + (n & 63)] =
                        make_float2(v0, v1);
                } else {
                    const size_t idx =
                        (((size_t)(bb * NKV + (n >> 6))) * T_SEQ + t) * HD + (n & 63);
                    if (mode == 2) {
                        *(float2*)&kout[idx] = make_float2(v0, v1);
                        // fp16 PERM16 K for attention: slot = ((d&7)>>1)*4 + ((d>>3)&1)*2
                        const int d = n & 63;
                        const int slot = ((d & 7) >> 1) * 4 + ((d >> 3) & 1) * 2;
                        const size_t base =
                            (((size_t)(bb * NKV + (n >> 6))) * T_SEQ + t) * HD +
                            (d & ~15) + slot;
                        *(__half2*)&g_kc[base] = __floats2half2_rn(v0, v1);
                    } else {
                        *(float2*)&vout[idx] = make_float2(v0, v1);
                    }
                }
            }
        }
    }
}

// ============================================================================
// Flash attention, fp16 m16n8k16. 8 warps, warp tile 16x64.
// PERM16 fp16 K/V globals -> LDS.64 B-fragments, pitch 80 halves (160B).
// cp.async.ca double-buffered, heavy-first schedule. P->A remap = 16 packs.
// ============================================================================
#define ATP 80
#define KVH (64 * ATP)   // 5120 halves per tile buffer

__global__ __launch_bounds__(256, 2) void attn_mma()
{
    extern __shared__ __align__(16) __half smh[];
    const uint32_t sm_addr = smem_u32(smh);

    const int tid = threadIdx.x;
    const int wid = tid >> 5;
    const int lane = tid & 31;
    const int gr = lane >> 2;
    const int tig = lane & 3;

    const int qt = (gridDim.x - 1) - blockIdx.x;  // heavy-first
    const int bh = blockIdx.y;
    const int b = bh >> 5;
    const int h = bh & 31;
    const int bkv = (b * NKV) + (h >> 2);

    // Q A-fragments (fp16, pre-scaled 1/8): block j covers d = 16j..16j+15.
    const float* Qg = g_q + (((size_t)(b * NH + h)) * T_SEQ + qt * 128 + wid * 16) * HD;
    uint32_t qa[4][4];
#pragma unroll
    for (int j = 0; j < 4; j++) {
        const int d0 = 16 * j + 2 * tig;
        qa[j][0] = pack_h2(Qg[gr * HD + d0] * 0.125f, Qg[gr * HD + d0 + 1] * 0.125f);
        qa[j][1] = pack_h2(Qg[(gr + 8) * HD + d0] * 0.125f, Qg[(gr + 8) * HD + d0 + 1] * 0.125f);
        qa[j][2] = pack_h2(Qg[gr * HD + d0 + 8] * 0.125f, Qg[gr * HD + d0 + 9] * 0.125f);
        qa[j][3] = pack_h2(Qg[(gr + 8) * HD + d0 + 8] * 0.125f, Qg[(gr + 8) * HD + d0 + 9] * 0.125f);
    }

    const __half* Kbase = g_kc + (size_t)bkv * T_SEQ * HD;
    const __half* Vbase = g_vt + (size_t)bkv * HD * T_SEQ;

    float ctx[8][4];
#pragma unroll
    for (int ni = 0; ni < 8; ni++)
#pragma unroll
        for (int r = 0; r < 4; r++) ctx[ni][r] = 0.f;
    float mrun0 = -INFINITY, mrun1 = -INFINITY;
    float lrun0 = 0.f, lrun1 = 0.f;

    // fills: 2 chunks per op per thread: row = (i*256+tid)>>3, ch = tid&7
    const int lrow0 = tid >> 3;          // rows 0..31 (i=0), 32..63 (i=1)
    const int lch = tid & 7;
    const int row0 = qt * 128 + wid * 16 + gr;
    const int row1 = row0 + 8;
    const int njt = 2 * qt + 2;

#pragma unroll
    for (int i = 0; i < 2; i++) {
        const int r = lrow0 + i * 32;
        CP_ASYNC16_CA(sm_addr + (r * ATP + lch * 8) * 2, Kbase + (size_t)r * HD + lch * 8);
        CP_ASYNC16_CA(sm_addr + (2 * KVH + r * ATP + lch * 8) * 2,
                      Vbase + (size_t)r * T_SEQ + lch * 8);
    }
    CP_COMMIT();

    for (int jt = 0; jt < njt; jt++) {
        CP_WAIT0();
        __syncthreads();
        if (jt + 1 < njt) {
            const uint32_t boff = (uint32_t)((jt + 1) & 1) * KVH * 2;
            const int kt = (jt + 1) * 64;
#pragma unroll
            for (int i = 0; i < 2; i++) {
                const int r = lrow0 + i * 32;
                CP_ASYNC16_CA(sm_addr + boff + (r * ATP + lch * 8) * 2,
                              Kbase + (size_t)(kt + r) * HD + lch * 8);
                CP_ASYNC16_CA(sm_addr + 2 * KVH * 2 + boff + (r * ATP + lch * 8) * 2,
                              Vbase + (size_t)r * T_SEQ + kt + lch * 8);
            }
            CP_COMMIT();
        }

        if (jt == 2 * qt + 1 && wid < 4) continue;  // fully masked

        const __half* Ks = smh + (jt & 1) * KVH;
        const __half* Vt = smh + 2 * KVH + (jt & 1) * KVH;

        // ---- S = Q K^T : 4 k16-steps x 8 ni ----
        float s[8][4];
#pragma unroll
        for (int ni = 0; ni < 8; ni++)
#pragma unroll
            for (int r = 0; r < 4; r++) s[ni][r] = 0.f;
#pragma unroll
        for (int j = 0; j < 4; j++) {
            const int kc = j * 16 + tig * 4;
#pragma unroll
            for (int ni = 0; ni < 8; ni++) {
                uint64_t bv = *(const uint64_t*)&Ks[(ni * 8 + gr) * ATP + kc];
                mma_f16(s[ni], qa[j][0], qa[j][1], qa[j][2], qa[j][3],
                        (uint32_t)bv, (uint32_t)(bv >> 32));
            }
        }

        // ---- causal mask ----
        if (jt >= 2 * qt) {
            const int colb = jt * 64 + 2 * tig;
#pragma unroll
            for (int ni = 0; ni < 8; ni++) {
                const int c0 = colb + 8 * ni;
                if (c0 > row0) s[ni][0] = -INFINITY;
                if (c0 + 1 > row0) s[ni][1] = -INFINITY;
                if (c0 > row1) s[ni][2] = -INFINITY;
                if (c0 + 1 > row1) s[ni][3] = -INFINITY;
            }
        }

        // ---- online softmax (fp32) ----
        float m0 = -INFINITY, m1 = -INFINITY;
#pragma unroll
        for (int ni = 0; ni < 8; ni++) {
            m0 = fmaxf(m0, fmaxf(s[ni][0], s[ni][1]));
            m1 = fmaxf(m1, fmaxf(s[ni][2], s[ni][3]));
        }
        m0 = fmaxf(m0, __shfl_xor_sync(0xffffffffu, m0, 1, 4));
        m0 = fmaxf(m0, __shfl_xor_sync(0xffffffffu, m0, 2, 4));
        m1 = fmaxf(m1, __shfl_xor_sync(0xffffffffu, m1, 1, 4));
        m1 = fmaxf(m1, __shfl_xor_sync(0xffffffffu, m1, 2, 4));
        const float mn0 = fmaxf(mrun0, m0);
        const float mn1 = fmaxf(mrun1, m1);
        const float al0 = __expf(mrun0 - mn0);
        const float al1 = __expf(mrun1 - mn1);
        float ls0 = 0.f, ls1 = 0.f;
#pragma unroll
        for (int ni = 0; ni < 8; ni++) {
            float p0 = __expf(s[ni][0] - mn0);
            float p1 = __expf(s[ni][1] - mn0);
            float p2 = __expf(s[ni][2] - mn1);
            float p3 = __expf(s[ni][3] - mn1);
            ls0 += p0 + p1;
            ls1 += p2 + p3;
            s[ni][0] = p0;
            s[ni][1] = p1;
            s[ni][2] = p2;
            s[ni][3] = p3;
            ctx[ni][0] *= al0;
            ctx[ni][1] *= al0;
            ctx[ni][2] *= al1;
            ctx[ni][3] *= al1;
        }
        ls0 += __shfl_xor_sync(0xffffffffu, ls0, 1, 4);
        ls0 += __shfl_xor_sync(0xffffffffu, ls0, 2, 4);
        ls1 += __shfl_xor_sync(0xffffffffu, ls1, 1, 4);
        ls1 += __shfl_xor_sync(0xffffffffu, ls1, 2, 4);
        mrun0 = mn0;
        mrun1 = mn1;
        lrun0 = lrun0 * al0 + ls0;
        lrun1 = lrun1 * al1 + ls1;

        // ---- ctx += P V : pack P C-frags pairwise into fp16 A-frags ----
#pragma unroll
        for (int j = 0; j < 4; j++) {
            const uint32_t a0 = pack_h2(s[2 * j][0], s[2 * j][1]);
            const uint32_t a1 = pack_h2(s[2 * j][2], s[2 * j][3]);
            const uint32_t a2 = pack_h2(s[2 * j + 1][0], s[2 * j + 1][1]);
            const uint32_t a3 = pack_h2(s[2 * j + 1][2], s[2 * j + 1][3]);
            const int kc = j * 16 + tig * 4;
#pragma unroll
            for (int ni = 0; ni < 8; ni++) {
                uint64_t bv = *(const uint64_t*)&Vt[(ni * 8 + gr) * ATP + kc];
                mma_f16(ctx[ni], a0, a1, a2, a3, (uint32_t)bv, (uint32_t)(bv >> 32));
            }
        }
    }

    // ---- finalize: g_ctx fp16 PERM16 (consumed by O-GEMM) ----
    const float inv0 = 1.0f / lrun0;
    const float inv1 = 1.0f / lrun1;
    __half* o0 = g_ctx + (((size_t)(b * T_SEQ + row0)) * NH + h) * HD;
    __half* o1 = g_ctx + (((size_t)(b * T_SEQ + row1)) * NH + h) * HD;
#pragma unroll
    for (int ni = 0; ni < 8; ni++) {
        const int d = ni * 8 + 2 * tig;
        const int word = (d & ~15) + tig * 4 + (ni & 1) * 2;  // PERM slot
        *(__half2*)&o0[word] = __floats2half2_rn(ctx[ni][0] * inv0, ctx[ni][1] * inv0);
        *(__half2*)&o1[word] = __floats2half2_rn(ctx[ni][2] * inv1, ctx[ni][3] * inv1);
    }
}

// ---------------------------------------------------------------------------
extern "C" void kernel_launch(void* const* d_in, const int* in_sizes, int n_in,
                              void* d_out, int out_size)
{
    const float* x    = (const float*)d_in[0];
    const float* cosT = (const float*)d_in[1];
    const float* sinT = (const float*)d_in[2];
    const float* wq   = (const float*)d_in[3];
    const float* bq   = (const float*)d_in[4];
    const float* wk   = (const float*)d_in[5];
    const float* bk   = (const float*)d_in[6];
    const float* wv   = (const float*)d_in[7];
    const float* bv   = (const float*)d_in[8];
    const float* wo   = (const float*)d_in[9];
    const float* bo   = (const float*)d_in[10];

    float* out  = (float*)d_out;            // (B, T, D)
    float* kout = out + (size_t)8388608;    // (B, KV, T, HD)
    float* vout = out + (size_t)10485760;   // (B, KV, T, HD)

    const int GEMM_SMEM = 4 * TILE_H * 2;   // 81920 B
    const int ATTN_SMEM = 4 * KVH * 2;      // 40960 B
    static bool attr_set = false;
    if (!attr_set) {
        cudaFuncSetAttribute(db_gemm<0>, cudaFuncAttributeMaxDynamicSharedMemorySize, GEMM_SMEM);
        cudaFuncSetAttribute(db_gemm<1>, cudaFuncAttributeMaxDynamicSharedMemorySize, GEMM_SMEM);
        cudaFuncSetAttribute(attn_mma, cudaFuncAttributeMaxDynamicSharedMemorySize, ATTN_SMEM);
        attr_set = true;
    }

    __half* p_xt;  cudaGetSymbolAddress((void**)&p_xt, g_xt);
    __half* p_wq;  cudaGetSymbolAddress((void**)&p_wq, g_wq);
    __half* p_wk;  cudaGetSymbolAddress((void**)&p_wk, g_wk);
    __half* p_wv;  cudaGetSymbolAddress((void**)&p_wv, g_wv);
    __half* p_wo;  cudaGetSymbolAddress((void**)&p_wo, g_wo);
    __half* p_vt;  cudaGetSymbolAddress((void**)&p_vt, g_vt);

    // Prep: fp32 -> fp16 PERM16, one launch
    cvt_all<<<18432, 256>>>(x, wq, wk, wv, wo, p_xt, p_wq, p_wk, p_wv, p_wo);

    // Fused QKV projections (+RoPE for Q,K; K also written as PERM16 fp16)
    db_gemm<0><<<dim3(24, 32), 256, GEMM_SMEM>>>(
        p_xt, bq, bk, bv, kout, vout, nullptr, cosT, sinT);

    // V -> transposed PERM16 fp16
    vtrans<<<dim3(32, 16), 256>>>(vout, p_vt);

    // Attention -> g_ctx (PERM16 fp16)
    attn_mma<<<dim3(T_SEQ / 128, 2 * NH), 256, ATTN_SMEM>>>();

    // Output projection -> out
    db_gemm<1><<<dim3(16, 32), 256, GEMM_SMEM>>>(
        nullptr, bo, nullptr, nullptr, nullptr, nullptr, out, nullptr, nullptr);
}

// round 15
// speedup vs baseline: 2.3786x; 1.0179x over previous
#include <cuda_runtime.h>
#include <cuda_fp16.h>
#include <cstdint>
#include <math.h>

#define T_SEQ 2048
#define DMODEL 2048
#define NH 32
#define NKV 8
#define HD 64

// Q pre-scale: 1/sqrt(64) * log2(e)  (softmax runs in exp2 domain)
#define QSCALE 0.1803368801111364f

// ---------------- Scratch (device globals; allocation-free) ----------------
// fp16 operand globals use the k16 permutation: within each 16-half k-block,
// logical k = b*8 + 2*tig + lo stored at slot tig*4 + b*2 + lo. Applied
// identically to both MMA operands' k dim -> dot products preserved.
// g_qh: fp16 Q, NATURAL layout, pre-scaled by QSCALE (A-operand via LDG).
__device__ __half g_qh [(size_t)2 * NH * T_SEQ * HD];   // fp16 Q*QSCALE (b,h,t,d)
__device__ __half g_ctx[(size_t)2 * T_SEQ * NH * HD];   // fp16 ctx PERM16
__device__ __half g_xt [(size_t)4096 * 2048];           // fp16 x PERM16
__device__ __half g_wq [(size_t)2048 * 2048];           // PERM16
__device__ __half g_wk [(size_t)512 * 2048];            // PERM16
__device__ __half g_wv [(size_t)512 * 2048];            // PERM16
__device__ __half g_wo [(size_t)2048 * 2048];           // PERM16
__device__ __half g_kc [(size_t)2 * NKV * T_SEQ * HD];  // fp16 K PERM16(d)
__device__ __half g_vt [(size_t)2 * NKV * HD * T_SEQ];  // fp16 V^T PERM16(t)

__device__ __forceinline__ uint32_t pack_h2(float a, float b) {
    __half2 h = __floats2half2_rn(a, b);
    return *(uint32_t*)&h;
}

__device__ __forceinline__ float fast_exp2(float x) {
    float y;
    asm("ex2.approx.f32 %0, %1;" : "=f"(y) : "f"(x));
    return y;
}

__device__ __forceinline__ void mma_f16(float* c, uint32_t a0, uint32_t a1,
                                        uint32_t a2, uint32_t a3,
                                        uint32_t b0, uint32_t b1) {
    asm volatile(
        "mma.sync.aligned.m16n8k16.row.col.f32.f16.f16.f32 "
        "{%0,%1,%2,%3}, {%4,%5,%6,%7}, {%8,%9}, {%0,%1,%2,%3};"
        : "+f"(c[0]), "+f"(c[1]), "+f"(c[2]), "+f"(c[3])
        : "r"(a0), "r"(a1), "r"(a2), "r"(a3), "r"(b0), "r"(b1));
}

__device__ __forceinline__ uint32_t smem_u32(const void* p) {
    uint32_t a;
    asm("{ .reg .u64 t; cvta.to.shared.u64 t, %1; cvt.u32.u64 %0, t; }"
        : "=r"(a) : "l"(p));
    return a;
}
#define CP_ASYNC16_CG(dst, src) \
    asm volatile("cp.async.cg.shared.global [%0], [%1], 16;" :: "r"(dst), "l"(src))
#define CP_ASYNC16_CA(dst, src) \
    asm volatile("cp.async.ca.shared.global [%0], [%1], 16;" :: "r"(dst), "l"(src))
#define CP_COMMIT() asm volatile("cp.async.commit_group;" ::: "memory")
#define CP_WAIT0()  asm volatile("cp.async.wait_group 0;" ::: "memory")

// ============================================================================
// Prep: all fp32 -> fp16 PERM16, one launch.
// ============================================================================
__global__ void cvt_all(const float* __restrict__ x,
                        const float* __restrict__ wq,
                        const float* __restrict__ wk,
                        const float* __restrict__ wv,
                        const float* __restrict__ wo,
                        __half* __restrict__ xt,
                        __half* __restrict__ wqt,
                        __half* __restrict__ wkt,
                        __half* __restrict__ wvt,
                        __half* __restrict__ wot)
{
    int i = blockIdx.x * blockDim.x + threadIdx.x;
    const float* in;
    __half* out;
    if (i < 2097152)        { in = x;  out = xt; }
    else if (i < 3145728)   { in = wq; out = wqt; i -= 2097152; }
    else if (i < 3407872)   { in = wk; out = wkt; i -= 3145728; }
    else if (i < 3670016)   { in = wv; out = wvt; i -= 3407872; }
    else                    { in = wo; out = wot; i -= 3670016; }
    float4 v = ((const float4*)in)[i];
    const int w0 = i * 4;
    const int blockbase = w0 & ~15;
    const int k0 = w0 & 15;
    const int u = (k0 >> 2) & 1;
    const int b = (k0 >> 3) & 1;
    const int s0 = 8 * u + 2 * b;
    *(__half2*)&out[blockbase + s0]     = __floats2half2_rn(v.x, v.y);
    *(__half2*)&out[blockbase + s0 + 4] = __floats2half2_rn(v.z, v.w);
}

// ============================================================================
// Prep: V (b,kv,t,d) fp32 -> V^T (b,kv,d,t) fp16, key dim PERM16.
// ============================================================================
__global__ void vtrans(const float* __restrict__ vin, __half* __restrict__ vt)
{
    __shared__ float ts[64 * 65];
    const int tid = threadIdx.x;
    const int jt = blockIdx.x;
    const int bkv = blockIdx.y;

    const float* in = vin + ((size_t)bkv * T_SEQ + jt * 64) * HD;
#pragma unroll
    for (int p = 0; p < 4; p++) {
        const int lin = p * 256 + tid;
        const int t = lin >> 4;
        const int dq = (lin & 15) * 4;
        float4 v = *(const float4*)&in[t * HD + dq];
        ts[(dq + 0) * 65 + t] = v.x;
        ts[(dq + 1) * 65 + t] = v.y;
        ts[(dq + 2) * 65 + t] = v.z;
        ts[(dq + 3) * 65 + t] = v.w;
    }
    __syncthreads();
    __half* out = vt + (size_t)bkv * HD * T_SEQ + jt * 64;
#pragma unroll
    for (int p = 0; p < 4; p++) {
        const int lin = p * 256 + tid;
        const int d = lin >> 4;
        const int cq = (lin & 15) * 4;
        const int blockbase = cq & ~15;
        const int k0 = cq & 15;
        const int u = (k0 >> 2) & 1;
        const int b = (k0 >> 3) & 1;
        const int s0 = 8 * u + 2 * b;
        *(__half2*)&out[(size_t)d * T_SEQ + blockbase + s0] =
            __floats2half2_rn(ts[d * 65 + cq + 0], ts[d * 65 + cq + 1]);
        *(__half2*)&out[(size_t)d * T_SEQ + blockbase + s0 + 4] =
            __floats2half2_rn(ts[d * 65 + cq + 2], ts[d * 65 + cq + 3]);
    }
}

// ============================================================================
// cp.async.cg double-buffered fp16 GEMM (R14 config): 128x128 tile, BK=64,
// 8 warps (2x4), warp tile 64x32, m16n8k16, PERM16 operands, pitch 80 halves.
// KIND 0: fused QKV. bx<16: Q+RoPE -> g_qh fp16*QSCALE (natural);
//         16..19: K+RoPE -> kout fp32 + g_kc fp16 PERM16; 20..23: V -> vout.
// KIND 1: O projection: A=g_ctx (fp16 PERM16), C=out fp32.
// ============================================================================
#define GP 80
#define TILE_H (128 * GP)

template <int KIND>
__global__ __launch_bounds__(256, 2) void db_gemm(
    const __half* __restrict__ xA,
    const float* __restrict__ bq, const float* __restrict__ bk,
    const float* __restrict__ bv,
    float* __restrict__ kout, float* __restrict__ vout,
    float* __restrict__ outC,
    const float* __restrict__ cosT, const float* __restrict__ sinT)
{
    extern __shared__ __align__(16) __half smh[];
    const uint32_t sm_addr = smem_u32(smh);

    const int tid = threadIdx.x;
    const int wid = tid >> 5;
    const int lane = tid & 31;
    const int gr = lane >> 2;
    const int tig = lane & 3;
    const int wm = wid >> 2;
    const int wn = wid & 3;

    constexpr int K = DMODEL;
    const int m0 = blockIdx.y * 128;

    int mode, n0;
    const __half* A;
    const __half* W;
    const float* bias;
    if (KIND == 1) {
        mode = 0; n0 = blockIdx.x * 128; A = g_ctx; W = g_wo; bias = bq;
    } else {
        const int bx = blockIdx.x;
        A = xA;
        if (bx < 16)      { mode = 1; n0 = bx * 128;        W = g_wq; bias = bq; }
        else if (bx < 20) { mode = 2; n0 = (bx - 16) * 128; W = g_wk; bias = bk; }
        else              { mode = 3; n0 = (bx - 20) * 128; W = g_wv; bias = bv; }
    }

    const int rbase = tid >> 3;
    const int ch = tid & 7;
    const __half* Asrc = A + (size_t)(m0 + rbase) * K + ch * 8;
    const __half* Wsrc = W + (size_t)(n0 + rbase) * K + ch * 8;
    const uint32_t dstb = (uint32_t)(rbase * GP + ch * 8) * 2;

    float acc[4][4][4];
#pragma unroll
    for (int mi = 0; mi < 4; mi++)
#pragma unroll
        for (int ni = 0; ni < 4; ni++)
#pragma unroll
            for (int r = 0; r < 4; r++) acc[mi][ni][r] = 0.f;

    const int NST = K / 64;
#pragma unroll
    for (int i = 0; i < 4; i++) {
        CP_ASYNC16_CG(sm_addr + i * 32 * GP * 2 + dstb, Asrc + (size_t)i * 32 * K);
        CP_ASYNC16_CG(sm_addr + TILE_H * 2 + i * 32 * GP * 2 + dstb,
                      Wsrc + (size_t)i * 32 * K);
    }
    CP_COMMIT();

    for (int s = 0; s < NST; s++) {
        CP_WAIT0();
        __syncthreads();
        if (s + 1 < NST) {
            const uint32_t boff = (uint32_t)((s + 1) & 1) * (2 * TILE_H * 2);
            const int ko = (s + 1) * 64;
#pragma unroll
            for (int i = 0; i < 4; i++) {
                CP_ASYNC16_CG(sm_addr + boff + i * 32 * GP * 2 + dstb,
                              Asrc + (size_t)i * 32 * K + ko);
                CP_ASYNC16_CG(sm_addr + boff + TILE_H * 2 + i * 32 * GP * 2 + dstb,
                              Wsrc + (size_t)i * 32 * K + ko);
            }
            CP_COMMIT();
        }

        const __half* Abase = smh + (s & 1) * 2 * TILE_H + (wm * 64) * GP;
        const __half* Bbase = smh + (s & 1) * 2 * TILE_H + TILE_H + (wn * 32) * GP;
#pragma unroll
        for (int blk = 0; blk < 4; blk++) {
            const int kc = blk * 16 + tig * 4;
            uint32_t bf[4][2];
#pragma unroll
            for (int ni = 0; ni < 4; ni++) {
                uint64_t bv = *(const uint64_t*)&Bbase[(ni * 8 + gr) * GP + kc];
                bf[ni][0] = (uint32_t)bv;
                bf[ni][1] = (uint32_t)(bv >> 32);
            }
#pragma unroll
            for (int mi = 0; mi < 4; mi++) {
                uint64_t aL = *(const uint64_t*)&Abase[(mi * 16 + gr) * GP + kc];
                uint64_t aH = *(const uint64_t*)&Abase[(mi * 16 + gr + 8) * GP + kc];
                const uint32_t a0 = (uint32_t)aL, a2 = (uint32_t)(aL >> 32);
                const uint32_t a1 = (uint32_t)aH, a3 = (uint32_t)(aH >> 32);
#pragma unroll
                for (int ni = 0; ni < 4; ni++)
                    mma_f16(acc[mi][ni], a0, a1, a2, a3, bf[ni][0], bf[ni][1]);
            }
        }
    }

    // ---------------- Register epilogue ----------------
#pragma unroll
    for (int mi = 0; mi < 4; mi++) {
#pragma unroll
        for (int half = 0; half < 2; half++) {
            const int m = m0 + wm * 64 + mi * 16 + gr + half * 8;
            const int bb = m >> 11;
            const int t = m & (T_SEQ - 1);
#pragma unroll
            for (int ni = 0; ni < 4; ni++) {
                const int n = n0 + wn * 32 + ni * 8 + tig * 2;
                float v0 = acc[mi][ni][half * 2 + 0] + bias[n];
                float v1 = acc[mi][ni][half * 2 + 1] + bias[n + 1];
                if (mode == 1 || mode == 2) {
                    const int hh = (n & 63) >> 1;
                    const float c = cosT[t * (HD / 2) + hh];
                    const float ss = sinT[t * (HD / 2) + hh];
                    const float e = v0 * c - v1 * ss;
                    const float o = v0 * ss + v1 * c;
                    v0 = e;
                    v1 = o;
                }
                if (mode == 0) {
                    *(float2*)&outC[(size_t)m * DMODEL + n] = make_float2(v0, v1);
                } else if (mode == 1) {
                    // fp16 Q, pre-scaled by QSCALE, natural layout
                    *(__half2*)&g_qh[(((size_t)(bb * NH + (n >> 6))) * T_SEQ + t) * HD + (n & 63)] =
                        __floats2half2_rn(v0 * QSCALE, v1 * QSCALE);
                } else {
                    const size_t idx =
                        (((size_t)(bb * NKV + (n >> 6))) * T_SEQ + t) * HD + (n & 63);
                    if (mode == 2) {
                        *(float2*)&kout[idx] = make_float2(v0, v1);
                        const int d = n & 63;
                        const int slot = ((d & 7) >> 1) * 4 + ((d >> 3) & 1) * 2;
                        const size_t base =
                            (((size_t)(bb * NKV + (n >> 6))) * T_SEQ + t) * HD +
                            (d & ~15) + slot;
                        *(__half2*)&g_kc[base] = __floats2half2_rn(v0, v1);
                    } else {
                        *(float2*)&vout[idx] = make_float2(v0, v1);
                    }
                }
            }
        }
    }
}

// ============================================================================
// Flash attention, fp16 m16n8k16 (R14 config) + exp2-domain softmax + fp16 Q.
// 8 warps, warp tile 16x64, PERM16 K/V -> LDS.64 B-frags, pitch 80 halves,
// cp.async.ca double-buffered, heavy-first schedule.
// ============================================================================
#define ATP 80
#define KVH (64 * ATP)

__global__ __launch_bounds__(256, 2) void attn_mma()
{
    extern __shared__ __align__(16) __half smh[];
    const uint32_t sm_addr = smem_u32(smh);

    const int tid = threadIdx.x;
    const int wid = tid >> 5;
    const int lane = tid & 31;
    const int gr = lane >> 2;
    const int tig = lane & 3;

    const int qt = (gridDim.x - 1) - blockIdx.x;  // heavy-first
    const int bh = blockIdx.y;
    const int b = bh >> 5;
    const int h = bh & 31;
    const int bkv = (b * NKV) + (h >> 2);

    // Q A-fragments: direct 4B loads of pre-scaled fp16 (natural layout).
    const __half* Qg = g_qh + (((size_t)(b * NH + h)) * T_SEQ + qt * 128 + wid * 16) * HD;
    uint32_t qa[4][4];
#pragma unroll
    for (int j = 0; j < 4; j++) {
        const int d0 = 16 * j + 2 * tig;
        qa[j][0] = *(const uint32_t*)&Qg[gr * HD + d0];
        qa[j][1] = *(const uint32_t*)&Qg[(gr + 8) * HD + d0];
        qa[j][2] = *(const uint32_t*)&Qg[gr * HD + d0 + 8];
        qa[j][3] = *(const uint32_t*)&Qg[(gr + 8) * HD + d0 + 8];
    }

    const __half* Kbase = g_kc + (size_t)bkv * T_SEQ * HD;
    const __half* Vbase = g_vt + (size_t)bkv * HD * T_SEQ;

    float ctx[8][4];
#pragma unroll
    for (int ni = 0; ni < 8; ni++)
#pragma unroll
        for (int r = 0; r < 4; r++) ctx[ni][r] = 0.f;
    float mrun0 = -INFINITY, mrun1 = -INFINITY;
    float lrun0 = 0.f, lrun1 = 0.f;

    const int lrow0 = tid >> 3;
    const int lch = tid & 7;
    const int row0 = qt * 128 + wid * 16 + gr;
    const int row1 = row0 + 8;
    const int njt = 2 * qt + 2;

#pragma unroll
    for (int i = 0; i < 2; i++) {
        const int r = lrow0 + i * 32;
        CP_ASYNC16_CA(sm_addr + (r * ATP + lch * 8) * 2, Kbase + (size_t)r * HD + lch * 8);
        CP_ASYNC16_CA(sm_addr + (2 * KVH + r * ATP + lch * 8) * 2,
                      Vbase + (size_t)r * T_SEQ + lch * 8);
    }
    CP_COMMIT();

    for (int jt = 0; jt < njt; jt++) {
        CP_WAIT0();
        __syncthreads();
        if (jt + 1 < njt) {
            const uint32_t boff = (uint32_t)((jt + 1) & 1) * KVH * 2;
            const int kt = (jt + 1) * 64;
#pragma unroll
            for (int i = 0; i < 2; i++) {
                const int r = lrow0 + i * 32;
                CP_ASYNC16_CA(sm_addr + boff + (r * ATP + lch * 8) * 2,
                              Kbase + (size_t)(kt + r) * HD + lch * 8);
                CP_ASYNC16_CA(sm_addr + 2 * KVH * 2 + boff + (r * ATP + lch * 8) * 2,
                              Vbase + (size_t)r * T_SEQ + kt + lch * 8);
            }
            CP_COMMIT();
        }

        if (jt == 2 * qt + 1 && wid < 4) continue;  // fully masked

        const __half* Ks = smh + (jt & 1) * KVH;
        const __half* Vt = smh + 2 * KVH + (jt & 1) * KVH;

        // ---- S (exp2 domain) = (Q*QSCALE) K^T ----
        float s[8][4];
#pragma unroll
        for (int ni = 0; ni < 8; ni++)
#pragma unroll
            for (int r = 0; r < 4; r++) s[ni][r] = 0.f;
#pragma unroll
        for (int j = 0; j < 4; j++) {
            const int kc = j * 16 + tig * 4;
#pragma unroll
            for (int ni = 0; ni < 8; ni++) {
                uint64_t bv = *(const uint64_t*)&Ks[(ni * 8 + gr) * ATP + kc];
                mma_f16(s[ni], qa[j][0], qa[j][1], qa[j][2], qa[j][3],
                        (uint32_t)bv, (uint32_t)(bv >> 32));
            }
        }

        // ---- causal mask ----
        if (jt >= 2 * qt) {
            const int colb = jt * 64 + 2 * tig;
#pragma unroll
            for (int ni = 0; ni < 8; ni++) {
                const int c0 = colb + 8 * ni;
                if (c0 > row0) s[ni][0] = -INFINITY;
                if (c0 + 1 > row0) s[ni][1] = -INFINITY;
                if (c0 > row1) s[ni][2] = -INFINITY;
                if (c0 + 1 > row1) s[ni][3] = -INFINITY;
            }
        }

        // ---- online softmax (exp2 domain) ----
        float m0 = -INFINITY, m1 = -INFINITY;
#pragma unroll
        for (int ni = 0; ni < 8; ni++) {
            m0 = fmaxf(m0, fmaxf(s[ni][0], s[ni][1]));
            m1 = fmaxf(m1, fmaxf(s[ni][2], s[ni][3]));
        }
        m0 = fmaxf(m0, __shfl_xor_sync(0xffffffffu, m0, 1, 4));
        m0 = fmaxf(m0, __shfl_xor_sync(0xffffffffu, m0, 2, 4));
        m1 = fmaxf(m1, __shfl_xor_sync(0xffffffffu, m1, 1, 4));
        m1 = fmaxf(m1, __shfl_xor_sync(0xffffffffu, m1, 2, 4));
        const float mn0 = fmaxf(mrun0, m0);
        const float mn1 = fmaxf(mrun1, m1);
        const float al0 = fast_exp2(mrun0 - mn0);
        const float al1 = fast_exp2(mrun1 - mn1);
        float ls0 = 0.f, ls1 = 0.f;
#pragma unroll
        for (int ni = 0; ni < 8; ni++) {
            float p0 = fast_exp2(s[ni][0] - mn0);
            float p1 = fast_exp2(s[ni][1] - mn0);
            float p2 = fast_exp2(s[ni][2] - mn1);
            float p3 = fast_exp2(s[ni][3] - mn1);
            ls0 += p0 + p1;
            ls1 += p2 + p3;
            s[ni][0] = p0;
            s[ni][1] = p1;
            s[ni][2] = p2;
            s[ni][3] = p3;
            ctx[ni][0] *= al0;
            ctx[ni][1] *= al0;
            ctx[ni][2] *= al1;
            ctx[ni][3] *= al1;
        }
        ls0 += __shfl_xor_sync(0xffffffffu, ls0, 1, 4);
        ls0 += __shfl_xor_sync(0xffffffffu, ls0, 2, 4);
        ls1 += __shfl_xor_sync(0xffffffffu, ls1, 1, 4);
        ls1 += __shfl_xor_sync(0xffffffffu, ls1, 2, 4);
        mrun0 = mn0;
        mrun1 = mn1;
        lrun0 = lrun0 * al0 + ls0;
        lrun1 = lrun1 * al1 + ls1;

        // ---- ctx += P V : pack P C-frags pairwise into fp16 A-frags ----
#pragma unroll
        for (int j = 0; j < 4; j++) {
            const uint32_t a0 = pack_h2(s[2 * j][0], s[2 * j][1]);
            const uint32_t a1 = pack_h2(s[2 * j][2], s[2 * j][3]);
            const uint32_t a2 = pack_h2(s[2 * j + 1][0], s[2 * j + 1][1]);
            const uint32_t a3 = pack_h2(s[2 * j + 1][2], s[2 * j + 1][3]);
            const int kc = j * 16 + tig * 4;
#pragma unroll
            for (int ni = 0; ni < 8; ni++) {
                uint64_t bv = *(const uint64_t*)&Vt[(ni * 8 + gr) * ATP + kc];
                mma_f16(ctx[ni], a0, a1, a2, a3, (uint32_t)bv, (uint32_t)(bv >> 32));
            }
        }
    }

    // ---- finalize: g_ctx fp16 PERM16 (consumed by O-GEMM) ----
    const float inv0 = 1.0f / lrun0;
    const float inv1 = 1.0f / lrun1;
    __half* o0 = g_ctx + (((size_t)(b * T_SEQ + row0)) * NH + h) * HD;
    __half* o1 = g_ctx + (((size_t)(b * T_SEQ + row1)) * NH + h) * HD;
#pragma unroll
    for (int ni = 0; ni < 8; ni++) {
        const int d = ni * 8 + 2 * tig;
        const int word = (d & ~15) + tig * 4 + (ni & 1) * 2;  // PERM slot
        *(__half2*)&o0[word] = __floats2half2_rn(ctx[ni][0] * inv0, ctx[ni][1] * inv0);
        *(__half2*)&o1[word] = __floats2half2_rn(ctx[ni][2] * inv1, ctx[ni][3] * inv1);
    }
}

// ---------------------------------------------------------------------------
extern "C" void kernel_launch(void* const* d_in, const int* in_sizes, int n_in,
                              void* d_out, int out_size)
{
    const float* x    = (const float*)d_in[0];
    const float* cosT = (const float*)d_in[1];
    const float* sinT = (const float*)d_in[2];
    const float* wq   = (const float*)d_in[3];
    const float* bq   = (const float*)d_in[4];
    const float* wk   = (const float*)d_in[5];
    const float* bk   = (const float*)d_in[6];
    const float* wv   = (const float*)d_in[7];
    const float* bv   = (const float*)d_in[8];
    const float* wo   = (const float*)d_in[9];
    const float* bo   = (const float*)d_in[10];

    float* out  = (float*)d_out;            // (B, T, D)
    float* kout = out + (size_t)8388608;    // (B, KV, T, HD)
    float* vout = out + (size_t)10485760;   // (B, KV, T, HD)

    const int GEMM_SMEM = 4 * TILE_H * 2;   // 81920 B
    const int ATTN_SMEM = 4 * KVH * 2;      // 40960 B
    static bool attr_set = false;
    if (!attr_set) {
        cudaFuncSetAttribute(db_gemm<0>, cudaFuncAttributeMaxDynamicSharedMemorySize, GEMM_SMEM);
        cudaFuncSetAttribute(db_gemm<1>, cudaFuncAttributeMaxDynamicSharedMemorySize, GEMM_SMEM);
        cudaFuncSetAttribute(attn_mma, cudaFuncAttributeMaxDynamicSharedMemorySize, ATTN_SMEM);
        attr_set = true;
    }

    __half* p_xt;  cudaGetSymbolAddress((void**)&p_xt, g_xt);
    __half* p_wq;  cudaGetSymbolAddress((void**)&p_wq, g_wq);
    __half* p_wk;  cudaGetSymbolAddress((void**)&p_wk, g_wk);
    __half* p_wv;  cudaGetSymbolAddress((void**)&p_wv, g_wv);
    __half* p_wo;  cudaGetSymbolAddress((void**)&p_wo, g_wo);
    __half* p_vt;  cudaGetSymbolAddress((void**)&p_vt, g_vt);

    // Prep: fp32 -> fp16 PERM16, one launch
    cvt_all<<<18432, 256>>>(x, wq, wk, wv, wo, p_xt, p_wq, p_wk, p_wv, p_wo);

    // Fused QKV projections (+RoPE; Q -> fp16*QSCALE, K -> fp32 + fp16 PERM16)
    db_gemm<0><<<dim3(24, 32), 256, GEMM_SMEM>>>(
        p_xt, bq, bk, bv, kout, vout, nullptr, cosT, sinT);

    // V -> transposed PERM16 fp16
    vtrans<<<dim3(32, 16), 256>>>(vout, p_vt);

    // Attention -> g_ctx (PERM16 fp16)
    attn_mma<<<dim3(T_SEQ / 128, 2 * NH), 256, ATTN_SMEM>>>();

    // Output projection -> out
    db_gemm<1><<<dim3(16, 32), 256, GEMM_SMEM>>>(
        nullptr, bo, nullptr, nullptr, nullptr, nullptr, out, nullptr, nullptr);
}